// round 1
// baseline (speedup 1.0000x reference)
#include <cuda_runtime.h>
#include <cstdint>

// ---------------------------------------------------------------------------
// TSAKT: embedding gather -> ReLU MLP -> 2 layers causal MHA -> output proj.
// NOTE: the reference's glo/ts score biases are constant along the key axis
// and added BEFORE masking with a fixed NEG => softmax-shift-invariant =>
// mathematically irrelevant. We implement plain causal attention.
// ---------------------------------------------------------------------------

#define Bsz 32
#define SEQ 512
#define EMB 512
#define NH  8
#define DHD 64
#define TOT (Bsz * SEQ)        // 16384 rows
#define ATTN_SCALE 0.125f      // 1/sqrt(64)

// ---- device scratch (allocation-free rule: __device__ globals) -------------
__device__ float g_inputs[(size_t)TOT * 1024];
__device__ float g_query [(size_t)TOT * EMB];
__device__ float g_x     [(size_t)TOT * EMB];
__device__ float g_Qb    [(size_t)TOT * EMB];
__device__ float g_Kb    [(size_t)TOT * EMB];
__device__ float g_Vb    [(size_t)TOT * EMB];
__device__ float g_attn  [(size_t)TOT * EMB];
__device__ float g_outb  [(size_t)TOT * EMB];

// ---------------------------------------------------------------------------
// Gather: build inputs [g,1024] = [half*lab, half*(1-lab)], query [g,512]
// half = concat(item_emb[item_inputs], skill_emb[skill_inputs])
// ---------------------------------------------------------------------------
__global__ __launch_bounds__(128) void gather_kernel(
    const int* __restrict__ item_inputs, const int* __restrict__ skill_inputs,
    const int* __restrict__ label_inputs,
    const int* __restrict__ item_ids, const int* __restrict__ skill_ids,
    const float* __restrict__ item_emb, const float* __restrict__ skill_emb,
    float* __restrict__ inputs, float* __restrict__ query)
{
    int g = blockIdx.x;
    int t = threadIdx.x;
    float lab = (float)label_inputs[g];
    float nlab = 1.0f - lab;

    if (t < 64) {
        const float4* ie = reinterpret_cast<const float4*>(item_emb + (size_t)item_inputs[g] * 256);
        float4 v = ie[t];
        float4 a = make_float4(v.x * lab, v.y * lab, v.z * lab, v.w * lab);
        float4 c = make_float4(v.x * nlab, v.y * nlab, v.z * nlab, v.w * nlab);
        *reinterpret_cast<float4*>(inputs + (size_t)g * 1024 + t * 4)        = a;
        *reinterpret_cast<float4*>(inputs + (size_t)g * 1024 + 512 + t * 4)  = c;
        const float4* qe = reinterpret_cast<const float4*>(item_emb + (size_t)item_ids[g] * 256);
        *reinterpret_cast<float4*>(query + (size_t)g * 512 + t * 4) = qe[t];
    } else {
        int u = t - 64;
        const float4* se = reinterpret_cast<const float4*>(skill_emb + (size_t)skill_inputs[g] * 256);
        float4 v = se[u];
        float4 a = make_float4(v.x * lab, v.y * lab, v.z * lab, v.w * lab);
        float4 c = make_float4(v.x * nlab, v.y * nlab, v.z * nlab, v.w * nlab);
        *reinterpret_cast<float4*>(inputs + (size_t)g * 1024 + 256 + u * 4)       = a;
        *reinterpret_cast<float4*>(inputs + (size_t)g * 1024 + 512 + 256 + u * 4) = c;
        const float4* qs = reinterpret_cast<const float4*>(skill_emb + (size_t)skill_ids[g] * 256);
        *reinterpret_cast<float4*>(query + (size_t)g * 512 + 256 + u * 4) = qs[u];
    }
}

// ---------------------------------------------------------------------------
// SGEMM: C[M,N] = act(A[M,K] @ B[K,N] + bias[N]); 128x128x16 tile, 8x8/thread
// ---------------------------------------------------------------------------
template<bool RELU>
__global__ __launch_bounds__(256) void sgemm_bias_kernel(
    const float* __restrict__ A, const float* __restrict__ B,
    const float* __restrict__ bias, float* __restrict__ C,
    int M, int N, int K)
{
    const int BM = 128, BN = 128, BK = 16;
    __shared__ float As[BK][BM + 4];   // transposed A tile
    __shared__ float Bs[BK][BN];

    int tid = threadIdx.x;
    int bm = blockIdx.y * BM, bn = blockIdx.x * BN;
    int tx = tid & 15, ty = tid >> 4;

    float acc[8][8];
#pragma unroll
    for (int i = 0; i < 8; i++)
#pragma unroll
        for (int j = 0; j < 8; j++) acc[i][j] = 0.f;

    for (int k0 = 0; k0 < K; k0 += BK) {
#pragma unroll
        for (int i = 0; i < 2; i++) {
            int v = tid + i * 256;
            int ar = v >> 2, ac = (v & 3) * 4;
            float4 av = *reinterpret_cast<const float4*>(A + (size_t)(bm + ar) * K + k0 + ac);
            As[ac + 0][ar] = av.x; As[ac + 1][ar] = av.y;
            As[ac + 2][ar] = av.z; As[ac + 3][ar] = av.w;
            int br = v >> 5, bc = (v & 31) * 4;
            *reinterpret_cast<float4*>(&Bs[br][bc]) =
                *reinterpret_cast<const float4*>(B + (size_t)(k0 + br) * N + bn + bc);
        }
        __syncthreads();
#pragma unroll
        for (int kk = 0; kk < BK; kk++) {
            float a[8], b[8];
            *reinterpret_cast<float4*>(a)     = *reinterpret_cast<float4*>(&As[kk][ty * 8]);
            *reinterpret_cast<float4*>(a + 4) = *reinterpret_cast<float4*>(&As[kk][ty * 8 + 4]);
            *reinterpret_cast<float4*>(b)     = *reinterpret_cast<float4*>(&Bs[kk][tx * 8]);
            *reinterpret_cast<float4*>(b + 4) = *reinterpret_cast<float4*>(&Bs[kk][tx * 8 + 4]);
#pragma unroll
            for (int i = 0; i < 8; i++)
#pragma unroll
                for (int j = 0; j < 8; j++) acc[i][j] += a[i] * b[j];
        }
        __syncthreads();
    }

#pragma unroll
    for (int i = 0; i < 8; i++) {
        int row = bm + ty * 8 + i;
#pragma unroll
        for (int j = 0; j < 8; j += 4) {
            float4 bv = *reinterpret_cast<const float4*>(bias + bn + tx * 8 + j);
            float4 o;
            o.x = acc[i][j + 0] + bv.x;
            o.y = acc[i][j + 1] + bv.y;
            o.z = acc[i][j + 2] + bv.z;
            o.w = acc[i][j + 3] + bv.w;
            if (RELU) {
                o.x = fmaxf(o.x, 0.f); o.y = fmaxf(o.y, 0.f);
                o.z = fmaxf(o.z, 0.f); o.w = fmaxf(o.w, 0.f);
            }
            *reinterpret_cast<float4*>(C + (size_t)row * N + bn + tx * 8 + j) = o;
        }
    }
}

// ---------------------------------------------------------------------------
// Flash attention (fp32, causal): per block one (b, h, 64-query tile).
// dynamic smem: Qs/Ks/Vs/Ps [64][68] + stats
// ---------------------------------------------------------------------------
#define LDPAD 68
__global__ __launch_bounds__(256) void flash_kernel(
    const float* __restrict__ Q, const float* __restrict__ Kp,
    const float* __restrict__ Vp, float* __restrict__ O)
{
    extern __shared__ float smem[];
    float* Qs = smem;                   // 64*68
    float* Ks = Qs + 64 * LDPAD;
    float* Vs = Ks + 64 * LDPAD;
    float* Ps = Vs + 64 * LDPAD;
    float* m_s = Ps + 64 * LDPAD;       // 64
    float* l_s = m_s + 64;              // 64
    float* a_s = l_s + 64;              // 64

    int tid = threadIdx.x;
    int qt = blockIdx.x, h = blockIdx.y, b = blockIdx.z;
    size_t qbase = ((size_t)b * SEQ + qt * 64) * EMB + h * DHD;

#pragma unroll
    for (int i = 0; i < 4; i++) {
        int v = tid + i * 256;
        int r = v >> 4, c = (v & 15) * 4;
        *reinterpret_cast<float4*>(&Qs[r * LDPAD + c]) =
            *reinterpret_cast<const float4*>(Q + qbase + (size_t)r * EMB + c);
    }
    if (tid < 64) { m_s[tid] = -1e30f; l_s[tid] = 0.f; }

    float acc[4][4];
#pragma unroll
    for (int i = 0; i < 4; i++)
#pragma unroll
        for (int j = 0; j < 4; j++) acc[i][j] = 0.f;

    int ty = tid >> 4, tx = tid & 15;
    int r0 = ty * 4;

    for (int kt = 0; kt <= qt; kt++) {
        size_t kbase = ((size_t)b * SEQ + kt * 64) * EMB + h * DHD;
        __syncthreads();   // protect Ks/Vs/Ps reuse from previous iter
#pragma unroll
        for (int i = 0; i < 4; i++) {
            int v = tid + i * 256;
            int r = v >> 4, c = (v & 15) * 4;
            *reinterpret_cast<float4*>(&Ks[r * LDPAD + c]) =
                *reinterpret_cast<const float4*>(Kp + kbase + (size_t)r * EMB + c);
            *reinterpret_cast<float4*>(&Vs[r * LDPAD + c]) =
                *reinterpret_cast<const float4*>(Vp + kbase + (size_t)r * EMB + c);
        }
        __syncthreads();

        // scores: s[i][j] = Q[r0+i] . K[tx*4+j]
        float s[4][4];
#pragma unroll
        for (int i = 0; i < 4; i++)
#pragma unroll
            for (int j = 0; j < 4; j++) s[i][j] = 0.f;
#pragma unroll
        for (int d = 0; d < DHD; d += 4) {
            float4 qv[4], kv[4];
#pragma unroll
            for (int i = 0; i < 4; i++) qv[i] = *reinterpret_cast<float4*>(&Qs[(r0 + i) * LDPAD + d]);
#pragma unroll
            for (int j = 0; j < 4; j++) kv[j] = *reinterpret_cast<float4*>(&Ks[(tx * 4 + j) * LDPAD + d]);
#pragma unroll
            for (int i = 0; i < 4; i++)
#pragma unroll
                for (int j = 0; j < 4; j++)
                    s[i][j] += qv[i].x * kv[j].x + qv[i].y * kv[j].y +
                               qv[i].z * kv[j].z + qv[i].w * kv[j].w;
        }
        bool diag = (kt == qt);
#pragma unroll
        for (int i = 0; i < 4; i++) {
            float sv[4];
#pragma unroll
            for (int j = 0; j < 4; j++) {
                float val = s[i][j] * ATTN_SCALE;
                if (diag && (tx * 4 + j) > (r0 + i)) val = -1e30f;
                sv[j] = val;
            }
            *reinterpret_cast<float4*>(&Ps[(r0 + i) * LDPAD + tx * 4]) =
                make_float4(sv[0], sv[1], sv[2], sv[3]);
        }
        __syncthreads();

        // online softmax, one thread per row
        if (tid < 64) {
            int row = tid;
            float mo = m_s[row];
            float tm = -1e30f;
#pragma unroll
            for (int c = 0; c < 64; c += 4) {
                float4 v = *reinterpret_cast<float4*>(&Ps[row * LDPAD + c]);
                tm = fmaxf(tm, fmaxf(fmaxf(v.x, v.y), fmaxf(v.z, v.w)));
            }
            float mn = fmaxf(mo, tm);
            float al = __expf(mo - mn);
            float rs = 0.f;
#pragma unroll
            for (int c = 0; c < 64; c += 4) {
                float4 v = *reinterpret_cast<float4*>(&Ps[row * LDPAD + c]);
                v.x = __expf(v.x - mn); v.y = __expf(v.y - mn);
                v.z = __expf(v.z - mn); v.w = __expf(v.w - mn);
                rs += v.x + v.y + v.z + v.w;
                *reinterpret_cast<float4*>(&Ps[row * LDPAD + c]) = v;
            }
            m_s[row] = mn;
            l_s[row] = l_s[row] * al + rs;
            a_s[row] = al;
        }
        __syncthreads();

        // rescale + P @ V
#pragma unroll
        for (int i = 0; i < 4; i++) {
            float al = a_s[r0 + i];
            acc[i][0] *= al; acc[i][1] *= al; acc[i][2] *= al; acc[i][3] *= al;
        }
        for (int k = 0; k < 64; k++) {
            float4 vv = *reinterpret_cast<float4*>(&Vs[k * LDPAD + tx * 4]);
#pragma unroll
            for (int i = 0; i < 4; i++) {
                float p = Ps[(r0 + i) * LDPAD + k];
                acc[i][0] += p * vv.x; acc[i][1] += p * vv.y;
                acc[i][2] += p * vv.z; acc[i][3] += p * vv.w;
            }
        }
    }

#pragma unroll
    for (int i = 0; i < 4; i++) {
        float inv = 1.f / l_s[r0 + i];
        float4 o = make_float4(acc[i][0] * inv, acc[i][1] * inv,
                               acc[i][2] * inv, acc[i][3] * inv);
        *reinterpret_cast<float4*>(O + qbase + (size_t)(r0 + i) * EMB + tx * 4) = o;
    }
}
#define FLASH_SMEM ((4 * 64 * LDPAD + 3 * 64) * sizeof(float))

// ---------------------------------------------------------------------------
// out += relu(res), vectorized
// ---------------------------------------------------------------------------
__global__ __launch_bounds__(512) void add_relu_kernel(
    float* __restrict__ out, const float* __restrict__ res)
{
    size_t i = (size_t)blockIdx.x * blockDim.x + threadIdx.x;   // float4 index
    float4 o = reinterpret_cast<float4*>(out)[i];
    float4 r = reinterpret_cast<const float4*>(res)[i];
    o.x += fmaxf(r.x, 0.f); o.y += fmaxf(r.y, 0.f);
    o.z += fmaxf(r.z, 0.f); o.w += fmaxf(r.w, 0.f);
    reinterpret_cast<float4*>(out)[i] = o;
}

// ---------------------------------------------------------------------------
// y[g] = dot(out[g,:], W_out) + b_out ; one warp per row
// ---------------------------------------------------------------------------
__global__ __launch_bounds__(256) void out_proj_kernel(
    const float* __restrict__ out, const float* __restrict__ Wout,
    const float* __restrict__ bout, float* __restrict__ y)
{
    int g = blockIdx.x * 8 + (threadIdx.x >> 5);
    int lane = threadIdx.x & 31;
    const float4* o4 = reinterpret_cast<const float4*>(out + (size_t)g * EMB);
    const float4* w4 = reinterpret_cast<const float4*>(Wout);
    float s = 0.f;
#pragma unroll
    for (int i = 0; i < 4; i++) {
        float4 a = o4[lane + 32 * i];
        float4 b = w4[lane + 32 * i];
        s += a.x * b.x + a.y * b.y + a.z * b.z + a.w * b.w;
    }
#pragma unroll
    for (int off = 16; off > 0; off >>= 1)
        s += __shfl_xor_sync(0xFFFFFFFFu, s, off);
    if (lane == 0) y[g] = s + bout[0];
}

// ---------------------------------------------------------------------------
extern "C" void kernel_launch(void* const* d_in, const int* in_sizes, int n_in,
                              void* d_out, int out_size)
{
    const int*   item_inputs  = (const int*)d_in[0];
    const int*   skill_inputs = (const int*)d_in[1];
    const int*   label_inputs = (const int*)d_in[2];
    const int*   item_ids     = (const int*)d_in[3];
    const int*   skill_ids    = (const int*)d_in[4];
    const float* item_emb     = (const float*)d_in[5];
    const float* skill_emb    = (const float*)d_in[6];
    const float* W_in         = (const float*)d_in[7];
    const float* b_in         = (const float*)d_in[8];
    const float* Wq           = (const float*)d_in[9];
    const float* bq           = (const float*)d_in[10];
    const float* Wk           = (const float*)d_in[11];
    const float* bk           = (const float*)d_in[12];
    const float* Wv           = (const float*)d_in[13];
    const float* bv           = (const float*)d_in[14];
    // d_in[15..21]: Wg/bg/Wtq/btq/Wtk/btk/core -- softmax-shift-invariant, unused
    const float* W_out        = (const float*)d_in[22];
    const float* b_out        = (const float*)d_in[23];
    float* y = (float*)d_out;

    float *inputs, *query, *x, *Qb, *Kb, *Vb, *attn, *outb;
    cudaGetSymbolAddress((void**)&inputs, g_inputs);
    cudaGetSymbolAddress((void**)&query,  g_query);
    cudaGetSymbolAddress((void**)&x,      g_x);
    cudaGetSymbolAddress((void**)&Qb,     g_Qb);
    cudaGetSymbolAddress((void**)&Kb,     g_Kb);
    cudaGetSymbolAddress((void**)&Vb,     g_Vb);
    cudaGetSymbolAddress((void**)&attn,   g_attn);
    cudaGetSymbolAddress((void**)&outb,   g_outb);

    cudaFuncSetAttribute(flash_kernel,
                         cudaFuncAttributeMaxDynamicSharedMemorySize,
                         (int)FLASH_SMEM);

    gather_kernel<<<TOT, 128>>>(item_inputs, skill_inputs, label_inputs,
                                item_ids, skill_ids, item_emb, skill_emb,
                                inputs, query);

    // x = relu(inputs @ W_in + b_in)
    sgemm_bias_kernel<true><<<dim3(4, 128), 256>>>(inputs, W_in, b_in, x,
                                                   TOT, EMB, 1024);

    for (int l = 0; l < 2; l++) {
        const float* src = (l == 0) ? x : outb;
        const size_t wo = (size_t)l * EMB * EMB;
        sgemm_bias_kernel<false><<<dim3(4, 128), 256>>>(query, Wq + wo, bq + l * EMB, Qb, TOT, EMB, EMB);
        sgemm_bias_kernel<false><<<dim3(4, 128), 256>>>(src,   Wk + wo, bk + l * EMB, Kb, TOT, EMB, EMB);
        sgemm_bias_kernel<false><<<dim3(4, 128), 256>>>(src,   Wv + wo, bv + l * EMB, Vb, TOT, EMB, EMB);
        flash_kernel<<<dim3(SEQ / 64, NH, Bsz), 256, FLASH_SMEM>>>(
            Qb, Kb, Vb, (l == 0) ? outb : attn);
        if (l == 1)
            add_relu_kernel<<<(TOT * EMB / 4) / 512, 512>>>(outb, attn);
    }

    out_proj_kernel<<<TOT / 8, 256>>>(outb, W_out, b_out, y);
}

// round 3
// speedup vs baseline: 1.4918x; 1.4918x over previous
#include <cuda_runtime.h>
#include <cuda_bf16.h>
#include <cstdint>

// ---------------------------------------------------------------------------
// TSAKT: gather -> ReLU MLP -> 2x causal MHA -> output proj.
// glo/ts score biases are constant along the key axis before masking =>
// softmax-shift-invariant => dropped.
// R3: GEMMs on mma.sync bf16 (3-product hi/lo split, fp32 accumulate).
//     tcgen05 unavailable: harness ptxas targets sm_103 (non-'a').
// ---------------------------------------------------------------------------

#define Bsz 32
#define SEQ 512
#define EMB 512
#define NH  8
#define DHD 64
#define TOT (Bsz * SEQ)
#define ATTN_SCALE 0.125f

// ---- device scratch ---------------------------------------------------------
__device__ float g_inputs[(size_t)TOT * 1024];
__device__ float g_query [(size_t)TOT * EMB];
__device__ float g_x     [(size_t)TOT * EMB];
__device__ float g_Qb    [(size_t)TOT * EMB];
__device__ float g_Kb    [(size_t)TOT * EMB];
__device__ float g_Vb    [(size_t)TOT * EMB];
__device__ float g_attn  [(size_t)TOT * EMB];
__device__ float g_outb  [(size_t)TOT * EMB];
__device__ float g_Bt    [512 * 1024 + 6 * 512 * 512];   // transposed weights

// ---------------------------------------------------------------------------
__device__ __forceinline__ uint32_t pack_bf16(float x, float y) {
    __nv_bfloat162 h = __floats2bfloat162_rn(x, y);
    return *reinterpret_cast<uint32_t*>(&h);
}
__device__ __forceinline__ void mma_bf16(float* c, const uint32_t* a, const uint32_t* b) {
    asm volatile(
        "mma.sync.aligned.m16n8k16.row.col.f32.bf16.bf16.f32 "
        "{%0,%1,%2,%3}, {%4,%5,%6,%7}, {%8,%9}, {%0,%1,%2,%3};"
        : "+f"(c[0]), "+f"(c[1]), "+f"(c[2]), "+f"(c[3])
        : "r"(a[0]), "r"(a[1]), "r"(a[2]), "r"(a[3]), "r"(b[0]), "r"(b[1]));
}

// ---------------------------------------------------------------------------
// Gather
// ---------------------------------------------------------------------------
__global__ __launch_bounds__(128) void gather_kernel(
    const int* __restrict__ item_inputs, const int* __restrict__ skill_inputs,
    const int* __restrict__ label_inputs,
    const int* __restrict__ item_ids, const int* __restrict__ skill_ids,
    const float* __restrict__ item_emb, const float* __restrict__ skill_emb,
    float* __restrict__ inputs, float* __restrict__ query)
{
    int g = blockIdx.x;
    int t = threadIdx.x;
    float lab = (float)label_inputs[g];
    float nlab = 1.0f - lab;
    if (t < 64) {
        const float4* ie = reinterpret_cast<const float4*>(item_emb + (size_t)item_inputs[g] * 256);
        float4 v = ie[t];
        float4 a = make_float4(v.x * lab, v.y * lab, v.z * lab, v.w * lab);
        float4 c = make_float4(v.x * nlab, v.y * nlab, v.z * nlab, v.w * nlab);
        *reinterpret_cast<float4*>(inputs + (size_t)g * 1024 + t * 4)       = a;
        *reinterpret_cast<float4*>(inputs + (size_t)g * 1024 + 512 + t * 4) = c;
        const float4* qe = reinterpret_cast<const float4*>(item_emb + (size_t)item_ids[g] * 256);
        *reinterpret_cast<float4*>(query + (size_t)g * 512 + t * 4) = qe[t];
    } else {
        int u = t - 64;
        const float4* se = reinterpret_cast<const float4*>(skill_emb + (size_t)skill_inputs[g] * 256);
        float4 v = se[u];
        float4 a = make_float4(v.x * lab, v.y * lab, v.z * lab, v.w * lab);
        float4 c = make_float4(v.x * nlab, v.y * nlab, v.z * nlab, v.w * nlab);
        *reinterpret_cast<float4*>(inputs + (size_t)g * 1024 + 256 + u * 4)       = a;
        *reinterpret_cast<float4*>(inputs + (size_t)g * 1024 + 512 + 256 + u * 4) = c;
        const float4* qs = reinterpret_cast<const float4*>(skill_emb + (size_t)skill_ids[g] * 256);
        *reinterpret_cast<float4*>(query + (size_t)g * 512 + 256 + u * 4) = qs[u];
    }
}

// ---------------------------------------------------------------------------
// Weight transpose: dst[n,k] = src[k,n]
// ---------------------------------------------------------------------------
__global__ __launch_bounds__(256) void transpose_kernel(
    const float* __restrict__ src, float* __restrict__ dst, int K, int N)
{
    __shared__ float t[32][33];
    int bx = blockIdx.x * 32, by = blockIdx.y * 32;
    int x = threadIdx.x & 31, y0 = threadIdx.x >> 5;
#pragma unroll
    for (int j = 0; j < 32; j += 8)
        t[y0 + j][x] = src[(size_t)(by + y0 + j) * N + bx + x];
    __syncthreads();
#pragma unroll
    for (int j = 0; j < 32; j += 8)
        dst[(size_t)(bx + y0 + j) * K + by + x] = t[x][y0 + j];
}

// ---------------------------------------------------------------------------
// bf16 mma.sync GEMM (3-product split): C[M,512] = act(A[M,K] @ Bt^T + bias)
// A: [M,K] f32 row-major. Bt: [512,K] f32 row-major (pre-transposed weight).
// Block 128x128, 8 warps (2M x 4N), warp tile 64x32, K-chunk 32.
// smem planes (bf16, row stride 40 halves = 80 B): Ahi, Alo, Bhi, Blo.
// ---------------------------------------------------------------------------
#define RSTR 40                          // halves per smem row (32 + 8 pad)
#define PLANE_B (128 * RSTR * 2)         // 10240 bytes per plane

template<bool RELU>
__global__ __launch_bounds__(256, 1)
void gemm_bf16_kernel(const float* __restrict__ A, const float* __restrict__ Bt,
                      const float* __restrict__ bias, float* __restrict__ C,
                      int K)
{
    __shared__ __align__(16) char smem[4 * PLANE_B];
    char* AHI = smem;
    char* ALO = smem + PLANE_B;
    char* BHI = smem + 2 * PLANE_B;
    char* BLO = smem + 3 * PLANE_B;

    int tid = threadIdx.x;
    int wid = tid >> 5, lane = tid & 31;
    int g = lane >> 2, t = lane & 3;
    int bm = blockIdx.y * 128, bn = blockIdx.x * 128;
    int wm = (wid & 1) * 64, wn = (wid >> 1) * 32;
    int NC = K >> 5;

    // loader coords: 1024 float4 per 128x32 tile, 4 per thread
    int lrow[4], lkc[4];
#pragma unroll
    for (int i = 0; i < 4; i++) {
        int f = tid + i * 256;
        lrow[i] = f >> 3;
        lkc[i] = (f & 7) * 4;
    }

    float acc[4][4][4];
#pragma unroll
    for (int i = 0; i < 4; i++)
#pragma unroll
        for (int j = 0; j < 4; j++)
#pragma unroll
            for (int r = 0; r < 4; r++) acc[i][j][r] = 0.f;

    float4 sa[4], sb[4];
    // prologue: load chunk 0
#pragma unroll
    for (int i = 0; i < 4; i++) {
        sa[i] = *reinterpret_cast<const float4*>(A  + (size_t)(bm + lrow[i]) * K + lkc[i]);
        sb[i] = *reinterpret_cast<const float4*>(Bt + (size_t)(bn + lrow[i]) * K + lkc[i]);
    }

    for (int chunk = 0; chunk < NC; chunk++) {
        // convert + store staged regs to smem
#pragma unroll
        for (int i = 0; i < 4; i++) {
            int off = lrow[i] * (RSTR * 2) + lkc[i] * 2;   // bytes
            float4 a = sa[i], b = sb[i];
            float ahx = __bfloat162float(__float2bfloat16_rn(a.x));
            float ahy = __bfloat162float(__float2bfloat16_rn(a.y));
            float ahz = __bfloat162float(__float2bfloat16_rn(a.z));
            float ahw = __bfloat162float(__float2bfloat16_rn(a.w));
            *reinterpret_cast<uint2*>(AHI + off) =
                make_uint2(pack_bf16(a.x, a.y), pack_bf16(a.z, a.w));
            *reinterpret_cast<uint2*>(ALO + off) =
                make_uint2(pack_bf16(a.x - ahx, a.y - ahy), pack_bf16(a.z - ahz, a.w - ahw));
            float bhx = __bfloat162float(__float2bfloat16_rn(b.x));
            float bhy = __bfloat162float(__float2bfloat16_rn(b.y));
            float bhz = __bfloat162float(__float2bfloat16_rn(b.z));
            float bhw = __bfloat162float(__float2bfloat16_rn(b.w));
            *reinterpret_cast<uint2*>(BHI + off) =
                make_uint2(pack_bf16(b.x, b.y), pack_bf16(b.z, b.w));
            *reinterpret_cast<uint2*>(BLO + off) =
                make_uint2(pack_bf16(b.x - bhx, b.y - bhy), pack_bf16(b.z - bhz, b.w - bhw));
        }
        __syncthreads();

        // prefetch next chunk into regs (overlaps with MMA below)
        if (chunk + 1 < NC) {
            int k0 = (chunk + 1) << 5;
#pragma unroll
            for (int i = 0; i < 4; i++) {
                sa[i] = *reinterpret_cast<const float4*>(A  + (size_t)(bm + lrow[i]) * K + k0 + lkc[i]);
                sb[i] = *reinterpret_cast<const float4*>(Bt + (size_t)(bn + lrow[i]) * K + k0 + lkc[i]);
            }
        }

        // compute: two k16 steps
#pragma unroll
        for (int s = 0; s < 2; s++) {
            int kb = (s * 16 + t * 2) * 2;   // byte offset along k
            uint32_t bh[4][2], bl[4][2];
#pragma unroll
            for (int j = 0; j < 4; j++) {
                int rb = (wn + j * 8 + g) * (RSTR * 2) + kb;
                bh[j][0] = *reinterpret_cast<uint32_t*>(BHI + rb);
                bh[j][1] = *reinterpret_cast<uint32_t*>(BHI + rb + 16);
                bl[j][0] = *reinterpret_cast<uint32_t*>(BLO + rb);
                bl[j][1] = *reinterpret_cast<uint32_t*>(BLO + rb + 16);
            }
#pragma unroll
            for (int i = 0; i < 4; i++) {
                int ra = (wm + i * 16 + g) * (RSTR * 2) + kb;
                uint32_t ah[4], al[4];
                ah[0] = *reinterpret_cast<uint32_t*>(AHI + ra);
                ah[1] = *reinterpret_cast<uint32_t*>(AHI + ra + 8 * RSTR * 2);
                ah[2] = *reinterpret_cast<uint32_t*>(AHI + ra + 16);
                ah[3] = *reinterpret_cast<uint32_t*>(AHI + ra + 8 * RSTR * 2 + 16);
                al[0] = *reinterpret_cast<uint32_t*>(ALO + ra);
                al[1] = *reinterpret_cast<uint32_t*>(ALO + ra + 8 * RSTR * 2);
                al[2] = *reinterpret_cast<uint32_t*>(ALO + ra + 16);
                al[3] = *reinterpret_cast<uint32_t*>(ALO + ra + 8 * RSTR * 2 + 16);
#pragma unroll
                for (int j = 0; j < 4; j++) {
                    mma_bf16(acc[i][j], ah, bh[j]);
                    mma_bf16(acc[i][j], al, bh[j]);
                    mma_bf16(acc[i][j], ah, bl[j]);
                }
            }
        }
        __syncthreads();
    }

    // epilogue
#pragma unroll
    for (int i = 0; i < 4; i++) {
        int row0 = bm + wm + i * 16 + g;
#pragma unroll
        for (int j = 0; j < 4; j++) {
            int col = bn + wn + j * 8 + t * 2;
            float2 bv = *reinterpret_cast<const float2*>(bias + col);
            float v0 = acc[i][j][0] + bv.x, v1 = acc[i][j][1] + bv.y;
            float v2 = acc[i][j][2] + bv.x, v3 = acc[i][j][3] + bv.y;
            if (RELU) {
                v0 = fmaxf(v0, 0.f); v1 = fmaxf(v1, 0.f);
                v2 = fmaxf(v2, 0.f); v3 = fmaxf(v3, 0.f);
            }
            *reinterpret_cast<float2*>(C + (size_t)row0 * 512 + col)       = make_float2(v0, v1);
            *reinterpret_cast<float2*>(C + (size_t)(row0 + 8) * 512 + col) = make_float2(v2, v3);
        }
    }
}

// ---------------------------------------------------------------------------
// Flash attention (fp32, causal)
// ---------------------------------------------------------------------------
#define LDPAD 68
__global__ __launch_bounds__(256) void flash_kernel(
    const float* __restrict__ Q, const float* __restrict__ Kp,
    const float* __restrict__ Vp, float* __restrict__ O)
{
    extern __shared__ float smem[];
    float* Qs = smem;
    float* Ks = Qs + 64 * LDPAD;
    float* Vs = Ks + 64 * LDPAD;
    float* Ps = Vs + 64 * LDPAD;
    float* m_s = Ps + 64 * LDPAD;
    float* l_s = m_s + 64;
    float* a_s = l_s + 64;

    int tid = threadIdx.x;
    int qt = blockIdx.x, h = blockIdx.y, b = blockIdx.z;
    size_t qbase = ((size_t)b * SEQ + qt * 64) * EMB + h * DHD;

#pragma unroll
    for (int i = 0; i < 4; i++) {
        int v = tid + i * 256;
        int r = v >> 4, c = (v & 15) * 4;
        *reinterpret_cast<float4*>(&Qs[r * LDPAD + c]) =
            *reinterpret_cast<const float4*>(Q + qbase + (size_t)r * EMB + c);
    }
    if (tid < 64) { m_s[tid] = -1e30f; l_s[tid] = 0.f; }

    float acc[4][4];
#pragma unroll
    for (int i = 0; i < 4; i++)
#pragma unroll
        for (int j = 0; j < 4; j++) acc[i][j] = 0.f;

    int ty = tid >> 4, tx = tid & 15;
    int r0 = ty * 4;

    for (int kt = 0; kt <= qt; kt++) {
        size_t kbase = ((size_t)b * SEQ + kt * 64) * EMB + h * DHD;
        __syncthreads();
#pragma unroll
        for (int i = 0; i < 4; i++) {
            int v = tid + i * 256;
            int r = v >> 4, c = (v & 15) * 4;
            *reinterpret_cast<float4*>(&Ks[r * LDPAD + c]) =
                *reinterpret_cast<const float4*>(Kp + kbase + (size_t)r * EMB + c);
            *reinterpret_cast<float4*>(&Vs[r * LDPAD + c]) =
                *reinterpret_cast<const float4*>(Vp + kbase + (size_t)r * EMB + c);
        }
        __syncthreads();

        float s[4][4];
#pragma unroll
        for (int i = 0; i < 4; i++)
#pragma unroll
            for (int j = 0; j < 4; j++) s[i][j] = 0.f;
#pragma unroll
        for (int d = 0; d < DHD; d += 4) {
            float4 qv[4], kv[4];
#pragma unroll
            for (int i = 0; i < 4; i++) qv[i] = *reinterpret_cast<float4*>(&Qs[(r0 + i) * LDPAD + d]);
#pragma unroll
            for (int j = 0; j < 4; j++) kv[j] = *reinterpret_cast<float4*>(&Ks[(tx * 4 + j) * LDPAD + d]);
#pragma unroll
            for (int i = 0; i < 4; i++)
#pragma unroll
                for (int j = 0; j < 4; j++)
                    s[i][j] += qv[i].x * kv[j].x + qv[i].y * kv[j].y +
                               qv[i].z * kv[j].z + qv[i].w * kv[j].w;
        }
        bool diag = (kt == qt);
#pragma unroll
        for (int i = 0; i < 4; i++) {
            float sv[4];
#pragma unroll
            for (int j = 0; j < 4; j++) {
                float val = s[i][j] * ATTN_SCALE;
                if (diag && (tx * 4 + j) > (r0 + i)) val = -1e30f;
                sv[j] = val;
            }
            *reinterpret_cast<float4*>(&Ps[(r0 + i) * LDPAD + tx * 4]) =
                make_float4(sv[0], sv[1], sv[2], sv[3]);
        }
        __syncthreads();

        if (tid < 64) {
            int row = tid;
            float mo = m_s[row];
            float tm = -1e30f;
#pragma unroll
            for (int c = 0; c < 64; c += 4) {
                float4 v = *reinterpret_cast<float4*>(&Ps[row * LDPAD + c]);
                tm = fmaxf(tm, fmaxf(fmaxf(v.x, v.y), fmaxf(v.z, v.w)));
            }
            float mn = fmaxf(mo, tm);
            float al = __expf(mo - mn);
            float rs = 0.f;
#pragma unroll
            for (int c = 0; c < 64; c += 4) {
                float4 v = *reinterpret_cast<float4*>(&Ps[row * LDPAD + c]);
                v.x = __expf(v.x - mn); v.y = __expf(v.y - mn);
                v.z = __expf(v.z - mn); v.w = __expf(v.w - mn);
                rs += v.x + v.y + v.z + v.w;
                *reinterpret_cast<float4*>(&Ps[row * LDPAD + c]) = v;
            }
            m_s[row] = mn;
            l_s[row] = l_s[row] * al + rs;
            a_s[row] = al;
        }
        __syncthreads();

#pragma unroll
        for (int i = 0; i < 4; i++) {
            float al = a_s[r0 + i];
            acc[i][0] *= al; acc[i][1] *= al; acc[i][2] *= al; acc[i][3] *= al;
        }
        for (int k = 0; k < 64; k++) {
            float4 vv = *reinterpret_cast<float4*>(&Vs[k * LDPAD + tx * 4]);
#pragma unroll
            for (int i = 0; i < 4; i++) {
                float p = Ps[(r0 + i) * LDPAD + k];
                acc[i][0] += p * vv.x; acc[i][1] += p * vv.y;
                acc[i][2] += p * vv.z; acc[i][3] += p * vv.w;
            }
        }
    }

#pragma unroll
    for (int i = 0; i < 4; i++) {
        float inv = 1.f / l_s[r0 + i];
        float4 o = make_float4(acc[i][0] * inv, acc[i][1] * inv,
                               acc[i][2] * inv, acc[i][3] * inv);
        *reinterpret_cast<float4*>(O + qbase + (size_t)(r0 + i) * EMB + tx * 4) = o;
    }
}
#define FLASH_SMEM ((4 * 64 * LDPAD + 3 * 64) * sizeof(float))

// ---------------------------------------------------------------------------
__global__ __launch_bounds__(512) void add_relu_kernel(
    float* __restrict__ out, const float* __restrict__ res)
{
    size_t i = (size_t)blockIdx.x * blockDim.x + threadIdx.x;
    float4 o = reinterpret_cast<float4*>(out)[i];
    float4 r = reinterpret_cast<const float4*>(res)[i];
    o.x += fmaxf(r.x, 0.f); o.y += fmaxf(r.y, 0.f);
    o.z += fmaxf(r.z, 0.f); o.w += fmaxf(r.w, 0.f);
    reinterpret_cast<float4*>(out)[i] = o;
}

__global__ __launch_bounds__(256) void out_proj_kernel(
    const float* __restrict__ out, const float* __restrict__ Wout,
    const float* __restrict__ bout, float* __restrict__ y)
{
    int g = blockIdx.x * 8 + (threadIdx.x >> 5);
    int lane = threadIdx.x & 31;
    const float4* o4 = reinterpret_cast<const float4*>(out + (size_t)g * EMB);
    const float4* w4 = reinterpret_cast<const float4*>(Wout);
    float s = 0.f;
#pragma unroll
    for (int i = 0; i < 4; i++) {
        float4 a = o4[lane + 32 * i];
        float4 b = w4[lane + 32 * i];
        s += a.x * b.x + a.y * b.y + a.z * b.z + a.w * b.w;
    }
#pragma unroll
    for (int off = 16; off > 0; off >>= 1)
        s += __shfl_xor_sync(0xFFFFFFFFu, s, off);
    if (lane == 0) y[g] = s + bout[0];
}

// ---------------------------------------------------------------------------
extern "C" void kernel_launch(void* const* d_in, const int* in_sizes, int n_in,
                              void* d_out, int out_size)
{
    const int*   item_inputs  = (const int*)d_in[0];
    const int*   skill_inputs = (const int*)d_in[1];
    const int*   label_inputs = (const int*)d_in[2];
    const int*   item_ids     = (const int*)d_in[3];
    const int*   skill_ids    = (const int*)d_in[4];
    const float* item_emb     = (const float*)d_in[5];
    const float* skill_emb    = (const float*)d_in[6];
    const float* W_in         = (const float*)d_in[7];
    const float* b_in         = (const float*)d_in[8];
    const float* Wq           = (const float*)d_in[9];
    const float* bq           = (const float*)d_in[10];
    const float* Wk           = (const float*)d_in[11];
    const float* bk           = (const float*)d_in[12];
    const float* Wv           = (const float*)d_in[13];
    const float* bv           = (const float*)d_in[14];
    const float* W_out        = (const float*)d_in[22];
    const float* b_out        = (const float*)d_in[23];
    float* y = (float*)d_out;

    float *inputs, *query, *x, *Qb, *Kb, *Vb, *attn, *outb, *bt;
    cudaGetSymbolAddress((void**)&inputs, g_inputs);
    cudaGetSymbolAddress((void**)&query,  g_query);
    cudaGetSymbolAddress((void**)&x,      g_x);
    cudaGetSymbolAddress((void**)&Qb,     g_Qb);
    cudaGetSymbolAddress((void**)&Kb,     g_Kb);
    cudaGetSymbolAddress((void**)&Vb,     g_Vb);
    cudaGetSymbolAddress((void**)&attn,   g_attn);
    cudaGetSymbolAddress((void**)&outb,   g_outb);
    cudaGetSymbolAddress((void**)&bt,     g_Bt);

    cudaFuncSetAttribute(flash_kernel, cudaFuncAttributeMaxDynamicSharedMemorySize,
                         (int)FLASH_SMEM);

    float* bt_win = bt;                               // [512,1024]
    float* bt_qkv[2][3];
    for (int l = 0; l < 2; l++)
        for (int m = 0; m < 3; m++)
            bt_qkv[l][m] = bt + 512 * 1024 + (size_t)(l * 3 + m) * 512 * 512;

    transpose_kernel<<<dim3(16, 32), 256>>>(W_in, bt_win, 1024, 512);
    for (int l = 0; l < 2; l++) {
        const size_t wo = (size_t)l * EMB * EMB;
        transpose_kernel<<<dim3(16, 16), 256>>>(Wq + wo, bt_qkv[l][0], 512, 512);
        transpose_kernel<<<dim3(16, 16), 256>>>(Wk + wo, bt_qkv[l][1], 512, 512);
        transpose_kernel<<<dim3(16, 16), 256>>>(Wv + wo, bt_qkv[l][2], 512, 512);
    }

    gather_kernel<<<TOT, 128>>>(item_inputs, skill_inputs, label_inputs,
                                item_ids, skill_ids, item_emb, skill_emb,
                                inputs, query);

    // x = relu(inputs @ W_in + b_in)
    gemm_bf16_kernel<true><<<dim3(4, 128), 256>>>(inputs, bt_win, b_in, x, 1024);

    for (int l = 0; l < 2; l++) {
        const float* src = (l == 0) ? x : outb;
        gemm_bf16_kernel<false><<<dim3(4, 128), 256>>>(query, bt_qkv[l][0], bq + l * EMB, Qb, 512);
        gemm_bf16_kernel<false><<<dim3(4, 128), 256>>>(src,   bt_qkv[l][1], bk + l * EMB, Kb, 512);
        gemm_bf16_kernel<false><<<dim3(4, 128), 256>>>(src,   bt_qkv[l][2], bv + l * EMB, Vb, 512);
        flash_kernel<<<dim3(SEQ / 64, NH, Bsz), 256, FLASH_SMEM>>>(
            Qb, Kb, Vb, (l == 0) ? outb : attn);
        if (l == 1)
            add_relu_kernel<<<(TOT * EMB / 4) / 512, 512>>>(outb, attn);
    }

    out_proj_kernel<<<TOT / 8, 256>>>(outb, W_out, b_out, y);
}

// round 4
// speedup vs baseline: 2.2057x; 1.4786x over previous
#include <cuda_runtime.h>
#include <cuda_bf16.h>
#include <cstdint>

// ---------------------------------------------------------------------------
// TSAKT: gather -> ReLU MLP -> 2x causal MHA -> output proj.
// glo/ts score biases are key-axis-constant before masking => softmax-shift-
// invariant => dropped.
// R4: tensor-core flash attention (bf16 mma 3-product hi/lo), weights
//     pre-converted to bf16 planes once, GEMM B-loader reads bf16 directly.
// ---------------------------------------------------------------------------

#define Bsz 32
#define SEQ 512
#define EMB 512
#define NH  8
#define DHD 64
#define TOT (Bsz * SEQ)
#define ATTN_SCALE 0.125f

// ---- device scratch ---------------------------------------------------------
__device__ float g_inputs[(size_t)TOT * 1024];
__device__ float g_query [(size_t)TOT * EMB];
__device__ float g_x     [(size_t)TOT * EMB];
__device__ float g_Qb    [(size_t)TOT * EMB];
__device__ float g_Kb    [(size_t)TOT * EMB];
__device__ float g_Vb    [(size_t)TOT * EMB];
__device__ float g_attn  [(size_t)TOT * EMB];
__device__ float g_outb  [(size_t)TOT * EMB];
// bf16 hi/lo weight planes: 2*(512*1024) + 12*(512*512) halves
__device__ __nv_bfloat16 g_W[2 * 512 * 1024 + 12 * 512 * 512];

// ---------------------------------------------------------------------------
__device__ __forceinline__ uint32_t pack_bf16(float x, float y) {
    __nv_bfloat162 h = __floats2bfloat162_rn(x, y);
    return *reinterpret_cast<uint32_t*>(&h);
}
__device__ __forceinline__ float bf16_hi_f(float x) {
    return __bfloat162float(__float2bfloat16_rn(x));
}
__device__ __forceinline__ void mma_bf16(float* c, const uint32_t* a, const uint32_t* b) {
    asm volatile(
        "mma.sync.aligned.m16n8k16.row.col.f32.bf16.bf16.f32 "
        "{%0,%1,%2,%3}, {%4,%5,%6,%7}, {%8,%9}, {%0,%1,%2,%3};"
        : "+f"(c[0]), "+f"(c[1]), "+f"(c[2]), "+f"(c[3])
        : "r"(a[0]), "r"(a[1]), "r"(a[2]), "r"(a[3]), "r"(b[0]), "r"(b[1]));
}
// store float4 as bf16 hi+lo planes (4 halves each, 8B stores)
__device__ __forceinline__ void cvt_store4(float4 v, __nv_bfloat16* hi, __nv_bfloat16* lo) {
    float hx = bf16_hi_f(v.x), hy = bf16_hi_f(v.y);
    float hz = bf16_hi_f(v.z), hw = bf16_hi_f(v.w);
    *reinterpret_cast<uint2*>(hi) = make_uint2(pack_bf16(v.x, v.y), pack_bf16(v.z, v.w));
    *reinterpret_cast<uint2*>(lo) = make_uint2(pack_bf16(v.x - hx, v.y - hy),
                                               pack_bf16(v.z - hz, v.w - hw));
}

// ---------------------------------------------------------------------------
// Gather
// ---------------------------------------------------------------------------
__global__ __launch_bounds__(128) void gather_kernel(
    const int* __restrict__ item_inputs, const int* __restrict__ skill_inputs,
    const int* __restrict__ label_inputs,
    const int* __restrict__ item_ids, const int* __restrict__ skill_ids,
    const float* __restrict__ item_emb, const float* __restrict__ skill_emb,
    float* __restrict__ inputs, float* __restrict__ query)
{
    int g = blockIdx.x;
    int t = threadIdx.x;
    float lab = (float)label_inputs[g];
    float nlab = 1.0f - lab;
    if (t < 64) {
        const float4* ie = reinterpret_cast<const float4*>(item_emb + (size_t)item_inputs[g] * 256);
        float4 v = ie[t];
        float4 a = make_float4(v.x * lab, v.y * lab, v.z * lab, v.w * lab);
        float4 c = make_float4(v.x * nlab, v.y * nlab, v.z * nlab, v.w * nlab);
        *reinterpret_cast<float4*>(inputs + (size_t)g * 1024 + t * 4)       = a;
        *reinterpret_cast<float4*>(inputs + (size_t)g * 1024 + 512 + t * 4) = c;
        const float4* qe = reinterpret_cast<const float4*>(item_emb + (size_t)item_ids[g] * 256);
        *reinterpret_cast<float4*>(query + (size_t)g * 512 + t * 4) = qe[t];
    } else {
        int u = t - 64;
        const float4* se = reinterpret_cast<const float4*>(skill_emb + (size_t)skill_inputs[g] * 256);
        float4 v = se[u];
        float4 a = make_float4(v.x * lab, v.y * lab, v.z * lab, v.w * lab);
        float4 c = make_float4(v.x * nlab, v.y * nlab, v.z * nlab, v.w * nlab);
        *reinterpret_cast<float4*>(inputs + (size_t)g * 1024 + 256 + u * 4)       = a;
        *reinterpret_cast<float4*>(inputs + (size_t)g * 1024 + 512 + 256 + u * 4) = c;
        const float4* qs = reinterpret_cast<const float4*>(skill_emb + (size_t)skill_ids[g] * 256);
        *reinterpret_cast<float4*>(query + (size_t)g * 512 + 256 + u * 4) = qs[u];
    }
}

// ---------------------------------------------------------------------------
// Weight transpose + bf16 hi/lo split: dhi/dlo[n][k] = split(src[k][n])
// ---------------------------------------------------------------------------
__global__ __launch_bounds__(256) void transpose_cvt_kernel(
    const float* __restrict__ src, __nv_bfloat16* __restrict__ dhi,
    __nv_bfloat16* __restrict__ dlo, int K, int N)
{
    __shared__ float t[32][33];
    int bx = blockIdx.x * 32, by = blockIdx.y * 32;
    int x = threadIdx.x & 31, y0 = threadIdx.x >> 5;
#pragma unroll
    for (int j = 0; j < 32; j += 8)
        t[y0 + j][x] = src[(size_t)(by + y0 + j) * N + bx + x];
    __syncthreads();
#pragma unroll
    for (int j = 0; j < 32; j += 8) {
        float v = t[x][y0 + j];
        float h = bf16_hi_f(v);
        size_t idx = (size_t)(bx + y0 + j) * K + by + x;
        dhi[idx] = __float2bfloat16_rn(v);
        dlo[idx] = __float2bfloat16_rn(v - h);
    }
}

// ---------------------------------------------------------------------------
// bf16 mma.sync GEMM (3-product split): C[M,512] = act(A[M,K] @ Bt^T + bias)
// A: [M,K] f32. Bthi/Btlo: [512,K] bf16 planes (pre-transposed weights).
// Block 128x128, 8 warps (2M x 4N), warp tile 64x32, K-chunk 32.
// ---------------------------------------------------------------------------
#define RSTR 40
#define PLANE_B (128 * RSTR * 2)

template<bool RELU>
__global__ __launch_bounds__(256, 2)
void gemm_bf16_kernel(const float* __restrict__ A,
                      const __nv_bfloat16* __restrict__ Bthi,
                      const __nv_bfloat16* __restrict__ Btlo,
                      const float* __restrict__ bias, float* __restrict__ C,
                      int K)
{
    __shared__ __align__(16) char smem[4 * PLANE_B];
    char* AHI = smem;
    char* ALO = smem + PLANE_B;
    char* BHI = smem + 2 * PLANE_B;
    char* BLO = smem + 3 * PLANE_B;

    int tid = threadIdx.x;
    int wid = tid >> 5, lane = tid & 31;
    int g = lane >> 2, t = lane & 3;
    int bm = blockIdx.y * 128, bn = blockIdx.x * 128;
    int wm = (wid & 1) * 64, wn = (wid >> 1) * 32;
    int NC = K >> 5;

    int lrow[4], lkc[4];
#pragma unroll
    for (int i = 0; i < 4; i++) {
        int f = tid + i * 256;
        lrow[i] = f >> 3;
        lkc[i] = (f & 7) * 4;
    }
    int brow[2], bc8[2];
#pragma unroll
    for (int i = 0; i < 2; i++) {
        int f = tid + i * 256;
        brow[i] = f >> 2;
        bc8[i] = (f & 3) * 8;
    }

    float acc[4][4][4];
#pragma unroll
    for (int i = 0; i < 4; i++)
#pragma unroll
        for (int j = 0; j < 4; j++)
#pragma unroll
            for (int r = 0; r < 4; r++) acc[i][j][r] = 0.f;

    float4 sa[4];
    uint4 sbh[2], sbl[2];
#pragma unroll
    for (int i = 0; i < 4; i++)
        sa[i] = *reinterpret_cast<const float4*>(A + (size_t)(bm + lrow[i]) * K + lkc[i]);
#pragma unroll
    for (int i = 0; i < 2; i++) {
        sbh[i] = *reinterpret_cast<const uint4*>(Bthi + (size_t)(bn + brow[i]) * K + bc8[i]);
        sbl[i] = *reinterpret_cast<const uint4*>(Btlo + (size_t)(bn + brow[i]) * K + bc8[i]);
    }

    for (int chunk = 0; chunk < NC; chunk++) {
#pragma unroll
        for (int i = 0; i < 4; i++) {
            int off = lrow[i] * (RSTR * 2) + lkc[i] * 2;
            cvt_store4(sa[i], reinterpret_cast<__nv_bfloat16*>(AHI + off),
                              reinterpret_cast<__nv_bfloat16*>(ALO + off));
        }
#pragma unroll
        for (int i = 0; i < 2; i++) {
            int off = brow[i] * (RSTR * 2) + bc8[i] * 2;
            *reinterpret_cast<uint4*>(BHI + off) = sbh[i];
            *reinterpret_cast<uint4*>(BLO + off) = sbl[i];
        }
        __syncthreads();

        if (chunk + 1 < NC) {
            int k0 = (chunk + 1) << 5;
#pragma unroll
            for (int i = 0; i < 4; i++)
                sa[i] = *reinterpret_cast<const float4*>(A + (size_t)(bm + lrow[i]) * K + k0 + lkc[i]);
#pragma unroll
            for (int i = 0; i < 2; i++) {
                sbh[i] = *reinterpret_cast<const uint4*>(Bthi + (size_t)(bn + brow[i]) * K + k0 + bc8[i]);
                sbl[i] = *reinterpret_cast<const uint4*>(Btlo + (size_t)(bn + brow[i]) * K + k0 + bc8[i]);
            }
        }

#pragma unroll
        for (int s = 0; s < 2; s++) {
            int kb = (s * 16 + t * 2) * 2;
            uint32_t bh[4][2], bl[4][2];
#pragma unroll
            for (int j = 0; j < 4; j++) {
                int rb = (wn + j * 8 + g) * (RSTR * 2) + kb;
                bh[j][0] = *reinterpret_cast<uint32_t*>(BHI + rb);
                bh[j][1] = *reinterpret_cast<uint32_t*>(BHI + rb + 16);
                bl[j][0] = *reinterpret_cast<uint32_t*>(BLO + rb);
                bl[j][1] = *reinterpret_cast<uint32_t*>(BLO + rb + 16);
            }
#pragma unroll
            for (int i = 0; i < 4; i++) {
                int ra = (wm + i * 16 + g) * (RSTR * 2) + kb;
                uint32_t ah[4], al[4];
                ah[0] = *reinterpret_cast<uint32_t*>(AHI + ra);
                ah[1] = *reinterpret_cast<uint32_t*>(AHI + ra + 8 * RSTR * 2);
                ah[2] = *reinterpret_cast<uint32_t*>(AHI + ra + 16);
                ah[3] = *reinterpret_cast<uint32_t*>(AHI + ra + 8 * RSTR * 2 + 16);
                al[0] = *reinterpret_cast<uint32_t*>(ALO + ra);
                al[1] = *reinterpret_cast<uint32_t*>(ALO + ra + 8 * RSTR * 2);
                al[2] = *reinterpret_cast<uint32_t*>(ALO + ra + 16);
                al[3] = *reinterpret_cast<uint32_t*>(ALO + ra + 8 * RSTR * 2 + 16);
#pragma unroll
                for (int j = 0; j < 4; j++) {
                    mma_bf16(acc[i][j], ah, bh[j]);
                    mma_bf16(acc[i][j], al, bh[j]);
                    mma_bf16(acc[i][j], ah, bl[j]);
                }
            }
        }
        __syncthreads();
    }

#pragma unroll
    for (int i = 0; i < 4; i++) {
        int row0 = bm + wm + i * 16 + g;
#pragma unroll
        for (int j = 0; j < 4; j++) {
            int col = bn + wn + j * 8 + t * 2;
            float2 bv = *reinterpret_cast<const float2*>(bias + col);
            float v0 = acc[i][j][0] + bv.x, v1 = acc[i][j][1] + bv.y;
            float v2 = acc[i][j][2] + bv.x, v3 = acc[i][j][3] + bv.y;
            if (RELU) {
                v0 = fmaxf(v0, 0.f); v1 = fmaxf(v1, 0.f);
                v2 = fmaxf(v2, 0.f); v3 = fmaxf(v3, 0.f);
            }
            *reinterpret_cast<float2*>(C + (size_t)row0 * 512 + col)       = make_float2(v0, v1);
            *reinterpret_cast<float2*>(C + (size_t)(row0 + 8) * 512 + col) = make_float2(v2, v3);
        }
    }
}

// ---------------------------------------------------------------------------
// Tensor-core flash attention (bf16 mma, 3-product hi/lo, causal).
// CTA = (b, h, 128-q-row tile). 8 warps; warp owns 16 q rows x all 64 keys.
// K steps of 64 keys. Q,K row-major bf16 planes in smem; V transposed.
// ---------------------------------------------------------------------------
#define QSTR 72
#define VSTR 74
#define FBF_SMEM ((2 * 128 * QSTR + 2 * 64 * QSTR + 2 * 64 * VSTR) * 2)

__global__ __launch_bounds__(256, 2) void flash_bf16_kernel(
    const float* __restrict__ Qp, const float* __restrict__ Kp,
    const float* __restrict__ Vp, float* __restrict__ Op)
{
    extern __shared__ __align__(16) char fsm_raw[];
    __nv_bfloat16* Qhi  = reinterpret_cast<__nv_bfloat16*>(fsm_raw);
    __nv_bfloat16* Qlo  = Qhi + 128 * QSTR;
    __nv_bfloat16* Khi  = Qlo + 128 * QSTR;
    __nv_bfloat16* Klo  = Khi + 64 * QSTR;
    __nv_bfloat16* Vthi = Klo + 64 * QSTR;
    __nv_bfloat16* Vtlo = Vthi + 64 * VSTR;

    int tid = threadIdx.x;
    int wid = tid >> 5, lane = tid & 31;
    int g = lane >> 2, t = lane & 3;
    int qt = blockIdx.x, h = blockIdx.y, b = blockIdx.z;
    size_t qbase = ((size_t)b * SEQ + qt * 128) * EMB + h * DHD;
    size_t kvbase = ((size_t)b * SEQ) * EMB + h * DHD;

    // Q tile 128x64 -> hi/lo planes
#pragma unroll
    for (int i = 0; i < 8; i++) {
        int f = tid + i * 256;
        int r = f >> 4, c = (f & 15) * 4;
        float4 v = *reinterpret_cast<const float4*>(Qp + qbase + (size_t)r * EMB + c);
        cvt_store4(v, Qhi + r * QSTR + c, Qlo + r * QSTR + c);
    }

    float m0 = -INFINITY, m1 = -INFINITY, l0 = 0.f, l1 = 0.f;
    float acc[8][4];
#pragma unroll
    for (int j = 0; j < 8; j++)
#pragma unroll
        for (int r = 0; r < 4; r++) acc[j][r] = 0.f;

    int rb = wid * 16;
    int row0g = qt * 128 + rb + g;
    int row1g = row0g + 8;
    int ktmax = qt * 2 + 1;

    for (int kt = 0; kt <= ktmax; kt++) {
        __syncthreads();   // all warps done reading previous K/V
        size_t kb = kvbase + (size_t)kt * 64 * EMB;
#pragma unroll
        for (int i = 0; i < 4; i++) {
            int f = tid + i * 256;
            int r = f >> 4, c = (f & 15) * 4;
            float4 kv = *reinterpret_cast<const float4*>(Kp + kb + (size_t)r * EMB + c);
            cvt_store4(kv, Khi + r * QSTR + c, Klo + r * QSTR + c);
            float4 vv = *reinterpret_cast<const float4*>(Vp + kb + (size_t)r * EMB + c);
            float e[4] = {vv.x, vv.y, vv.z, vv.w};
#pragma unroll
            for (int j = 0; j < 4; j++) {
                __nv_bfloat16 hb = __float2bfloat16_rn(e[j]);
                Vthi[(c + j) * VSTR + r] = hb;
                Vtlo[(c + j) * VSTR + r] = __float2bfloat16_rn(e[j] - __bfloat162float(hb));
            }
        }
        __syncthreads();

        // ---- S = Q K^T (3-product) ----
        float s[8][4];
#pragma unroll
        for (int j = 0; j < 8; j++)
#pragma unroll
            for (int r = 0; r < 4; r++) s[j][r] = 0.f;
#pragma unroll
        for (int kk = 0; kk < 4; kk++) {
            int qo = (rb + g) * QSTR + kk * 16 + t * 2;
            uint32_t ah[4], al[4];
            ah[0] = *reinterpret_cast<uint32_t*>(Qhi + qo);
            ah[1] = *reinterpret_cast<uint32_t*>(Qhi + qo + 8 * QSTR);
            ah[2] = *reinterpret_cast<uint32_t*>(Qhi + qo + 8);
            ah[3] = *reinterpret_cast<uint32_t*>(Qhi + qo + 8 * QSTR + 8);
            al[0] = *reinterpret_cast<uint32_t*>(Qlo + qo);
            al[1] = *reinterpret_cast<uint32_t*>(Qlo + qo + 8 * QSTR);
            al[2] = *reinterpret_cast<uint32_t*>(Qlo + qo + 8);
            al[3] = *reinterpret_cast<uint32_t*>(Qlo + qo + 8 * QSTR + 8);
#pragma unroll
            for (int j = 0; j < 8; j++) {
                int ko = (j * 8 + g) * QSTR + kk * 16 + t * 2;
                uint32_t bh[2], bl[2];
                bh[0] = *reinterpret_cast<uint32_t*>(Khi + ko);
                bh[1] = *reinterpret_cast<uint32_t*>(Khi + ko + 8);
                bl[0] = *reinterpret_cast<uint32_t*>(Klo + ko);
                bl[1] = *reinterpret_cast<uint32_t*>(Klo + ko + 8);
                mma_bf16(s[j], ah, bh);
                mma_bf16(s[j], al, bh);
                mma_bf16(s[j], ah, bl);
            }
        }

        // ---- scale + causal mask ----
        int colbase = kt * 64 + t * 2;
#pragma unroll
        for (int j = 0; j < 8; j++) {
            int c0 = colbase + j * 8, c1 = c0 + 1;
            s[j][0] = (c0 > row0g) ? -INFINITY : s[j][0] * ATTN_SCALE;
            s[j][1] = (c1 > row0g) ? -INFINITY : s[j][1] * ATTN_SCALE;
            s[j][2] = (c0 > row1g) ? -INFINITY : s[j][2] * ATTN_SCALE;
            s[j][3] = (c1 > row1g) ? -INFINITY : s[j][3] * ATTN_SCALE;
        }

        // ---- online softmax (rows warp-local; quad = lanes sharing a row) ----
        float tm0 = -INFINITY, tm1 = -INFINITY;
#pragma unroll
        for (int j = 0; j < 8; j++) {
            tm0 = fmaxf(tm0, fmaxf(s[j][0], s[j][1]));
            tm1 = fmaxf(tm1, fmaxf(s[j][2], s[j][3]));
        }
        tm0 = fmaxf(tm0, __shfl_xor_sync(0xFFFFFFFFu, tm0, 1));
        tm0 = fmaxf(tm0, __shfl_xor_sync(0xFFFFFFFFu, tm0, 2));
        tm1 = fmaxf(tm1, __shfl_xor_sync(0xFFFFFFFFu, tm1, 1));
        tm1 = fmaxf(tm1, __shfl_xor_sync(0xFFFFFFFFu, tm1, 2));
        float m0n = fmaxf(m0, tm0), m1n = fmaxf(m1, tm1);
        float ms0 = fmaxf(m0n, -1e30f), ms1 = fmaxf(m1n, -1e30f);
        float alpha0 = __expf(m0 - ms0), alpha1 = __expf(m1 - ms1);
        m0 = m0n; m1 = m1n;

        float ps0 = 0.f, ps1 = 0.f;
        uint32_t ph01[8], ph23[8], pl01[8], pl23[8];
#pragma unroll
        for (int j = 0; j < 8; j++) {
            float p0 = __expf(s[j][0] - ms0);
            float p1 = __expf(s[j][1] - ms0);
            float p2 = __expf(s[j][2] - ms1);
            float p3 = __expf(s[j][3] - ms1);
            ps0 += p0 + p1; ps1 += p2 + p3;
            ph01[j] = pack_bf16(p0, p1);
            ph23[j] = pack_bf16(p2, p3);
            pl01[j] = pack_bf16(p0 - bf16_hi_f(p0), p1 - bf16_hi_f(p1));
            pl23[j] = pack_bf16(p2 - bf16_hi_f(p2), p3 - bf16_hi_f(p3));
        }
        ps0 += __shfl_xor_sync(0xFFFFFFFFu, ps0, 1);
        ps0 += __shfl_xor_sync(0xFFFFFFFFu, ps0, 2);
        ps1 += __shfl_xor_sync(0xFFFFFFFFu, ps1, 1);
        ps1 += __shfl_xor_sync(0xFFFFFFFFu, ps1, 2);
        l0 = l0 * alpha0 + ps0;
        l1 = l1 * alpha1 + ps1;
#pragma unroll
        for (int j = 0; j < 8; j++) {
            acc[j][0] *= alpha0; acc[j][1] *= alpha0;
            acc[j][2] *= alpha1; acc[j][3] *= alpha1;
        }

        // ---- O += P V (3-product); P fragments direct from registers ----
#pragma unroll
        for (int kk = 0; kk < 4; kk++) {
            uint32_t pah[4] = { ph01[2 * kk], ph23[2 * kk], ph01[2 * kk + 1], ph23[2 * kk + 1] };
            uint32_t pal[4] = { pl01[2 * kk], pl23[2 * kk], pl01[2 * kk + 1], pl23[2 * kk + 1] };
#pragma unroll
            for (int jd = 0; jd < 8; jd++) {
                int vo = (jd * 8 + g) * VSTR + kk * 16 + t * 2;
                uint32_t bh[2], bl[2];
                bh[0] = *reinterpret_cast<uint32_t*>(Vthi + vo);
                bh[1] = *reinterpret_cast<uint32_t*>(Vthi + vo + 8);
                bl[0] = *reinterpret_cast<uint32_t*>(Vtlo + vo);
                bl[1] = *reinterpret_cast<uint32_t*>(Vtlo + vo + 8);
                mma_bf16(acc[jd], pah, bh);
                mma_bf16(acc[jd], pal, bh);
                mma_bf16(acc[jd], pah, bl);
            }
        }
    }

    float inv0 = 1.f / l0, inv1 = 1.f / l1;
#pragma unroll
    for (int jd = 0; jd < 8; jd++) {
        int c = jd * 8 + t * 2;
        *reinterpret_cast<float2*>(Op + qbase + (size_t)(rb + g) * EMB + c) =
            make_float2(acc[jd][0] * inv0, acc[jd][1] * inv0);
        *reinterpret_cast<float2*>(Op + qbase + (size_t)(rb + g + 8) * EMB + c) =
            make_float2(acc[jd][2] * inv1, acc[jd][3] * inv1);
    }
}

// ---------------------------------------------------------------------------
__global__ __launch_bounds__(512) void add_relu_kernel(
    float* __restrict__ out, const float* __restrict__ res)
{
    size_t i = (size_t)blockIdx.x * blockDim.x + threadIdx.x;
    float4 o = reinterpret_cast<float4*>(out)[i];
    float4 r = reinterpret_cast<const float4*>(res)[i];
    o.x += fmaxf(r.x, 0.f); o.y += fmaxf(r.y, 0.f);
    o.z += fmaxf(r.z, 0.f); o.w += fmaxf(r.w, 0.f);
    reinterpret_cast<float4*>(out)[i] = o;
}

__global__ __launch_bounds__(256) void out_proj_kernel(
    const float* __restrict__ out, const float* __restrict__ Wout,
    const float* __restrict__ bout, float* __restrict__ y)
{
    int g = blockIdx.x * 8 + (threadIdx.x >> 5);
    int lane = threadIdx.x & 31;
    const float4* o4 = reinterpret_cast<const float4*>(out + (size_t)g * EMB);
    const float4* w4 = reinterpret_cast<const float4*>(Wout);
    float s = 0.f;
#pragma unroll
    for (int i = 0; i < 4; i++) {
        float4 a = o4[lane + 32 * i];
        float4 b = w4[lane + 32 * i];
        s += a.x * b.x + a.y * b.y + a.z * b.z + a.w * b.w;
    }
#pragma unroll
    for (int off = 16; off > 0; off >>= 1)
        s += __shfl_xor_sync(0xFFFFFFFFu, s, off);
    if (lane == 0) y[g] = s + bout[0];
}

// ---------------------------------------------------------------------------
extern "C" void kernel_launch(void* const* d_in, const int* in_sizes, int n_in,
                              void* d_out, int out_size)
{
    const int*   item_inputs  = (const int*)d_in[0];
    const int*   skill_inputs = (const int*)d_in[1];
    const int*   label_inputs = (const int*)d_in[2];
    const int*   item_ids     = (const int*)d_in[3];
    const int*   skill_ids    = (const int*)d_in[4];
    const float* item_emb     = (const float*)d_in[5];
    const float* skill_emb    = (const float*)d_in[6];
    const float* W_in         = (const float*)d_in[7];
    const float* b_in         = (const float*)d_in[8];
    const float* Wq           = (const float*)d_in[9];
    const float* bq           = (const float*)d_in[10];
    const float* Wk           = (const float*)d_in[11];
    const float* bk           = (const float*)d_in[12];
    const float* Wv           = (const float*)d_in[13];
    const float* bv           = (const float*)d_in[14];
    const float* W_out        = (const float*)d_in[22];
    const float* b_out        = (const float*)d_in[23];
    float* y = (float*)d_out;

    float *inputs, *query, *x, *Qb, *Kb, *Vb, *attn, *outb;
    __nv_bfloat16* w;
    cudaGetSymbolAddress((void**)&inputs, g_inputs);
    cudaGetSymbolAddress((void**)&query,  g_query);
    cudaGetSymbolAddress((void**)&x,      g_x);
    cudaGetSymbolAddress((void**)&Qb,     g_Qb);
    cudaGetSymbolAddress((void**)&Kb,     g_Kb);
    cudaGetSymbolAddress((void**)&Vb,     g_Vb);
    cudaGetSymbolAddress((void**)&attn,   g_attn);
    cudaGetSymbolAddress((void**)&outb,   g_outb);
    cudaGetSymbolAddress((void**)&w,      g_W);

    cudaFuncSetAttribute(flash_bf16_kernel,
                         cudaFuncAttributeMaxDynamicSharedMemorySize, FBF_SMEM);

    // weight plane layout in g_W
    __nv_bfloat16* win_hi = w;
    __nv_bfloat16* win_lo = w + 512 * 1024;
    __nv_bfloat16* qkv_hi[2][3];
    __nv_bfloat16* qkv_lo[2][3];
    {
        __nv_bfloat16* p = w + 2 * 512 * 1024;
        for (int l = 0; l < 2; l++)
            for (int m = 0; m < 3; m++) {
                qkv_hi[l][m] = p; p += 512 * 512;
                qkv_lo[l][m] = p; p += 512 * 512;
            }
    }

    // launch order puts the MLP GEMM at index 5 for the ncu sampler
    gather_kernel<<<TOT, 128>>>(item_inputs, skill_inputs, label_inputs,      // 0
                                item_ids, skill_ids, item_emb, skill_emb,
                                inputs, query);
    transpose_cvt_kernel<<<dim3(16, 32), 256>>>(W_in, win_hi, win_lo, 1024, 512); // 1
    transpose_cvt_kernel<<<dim3(16, 16), 256>>>(Wq, qkv_hi[0][0], qkv_lo[0][0], 512, 512); // 2
    transpose_cvt_kernel<<<dim3(16, 16), 256>>>(Wk, qkv_hi[0][1], qkv_lo[0][1], 512, 512); // 3
    transpose_cvt_kernel<<<dim3(16, 16), 256>>>(Wv, qkv_hi[0][2], qkv_lo[0][2], 512, 512); // 4

    gemm_bf16_kernel<true><<<dim3(4, 128), 256>>>(inputs, win_hi, win_lo, b_in, x, 1024); // 5

    const size_t wo = (size_t)EMB * EMB;
    transpose_cvt_kernel<<<dim3(16, 16), 256>>>(Wq + wo, qkv_hi[1][0], qkv_lo[1][0], 512, 512);
    transpose_cvt_kernel<<<dim3(16, 16), 256>>>(Wk + wo, qkv_hi[1][1], qkv_lo[1][1], 512, 512);
    transpose_cvt_kernel<<<dim3(16, 16), 256>>>(Wv + wo, qkv_hi[1][2], qkv_lo[1][2], 512, 512);

    for (int l = 0; l < 2; l++) {
        const float* src = (l == 0) ? x : outb;
        gemm_bf16_kernel<false><<<dim3(4, 128), 256>>>(query, qkv_hi[l][0], qkv_lo[l][0], bq + l * EMB, Qb, 512);
        gemm_bf16_kernel<false><<<dim3(4, 128), 256>>>(src,   qkv_hi[l][1], qkv_lo[l][1], bk + l * EMB, Kb, 512);
        gemm_bf16_kernel<false><<<dim3(4, 128), 256>>>(src,   qkv_hi[l][2], qkv_lo[l][2], bv + l * EMB, Vb, 512);
        flash_bf16_kernel<<<dim3(SEQ / 128, NH, Bsz), 256, FBF_SMEM>>>(
            Qb, Kb, Vb, (l == 0) ? outb : attn);
        if (l == 1)
            add_relu_kernel<<<(TOT * EMB / 4) / 512, 512>>>(outb, attn);
    }

    out_proj_kernel<<<TOT / 8, 256>>>(outb, W_out, b_out, y);
}

// round 5
// speedup vs baseline: 2.8046x; 1.2715x over previous
#include <cuda_runtime.h>
#include <cuda_bf16.h>
#include <cstdint>

// ---------------------------------------------------------------------------
// TSAKT: gather -> ReLU MLP -> 2x causal MHA -> output proj.
// glo/ts biases are key-constant pre-mask => softmax-shift-invariant => dropped.
// R5: ldmatrix fragments, cp.async B, 1-sync double-buffered GEMM,
//     QKV written as bf16 hi/lo planes (flash is conversion-free),
//     V via ldmatrix.trans, warp-level causal skip.
// ---------------------------------------------------------------------------

#define Bsz 32
#define SEQ 512
#define EMB 512
#define NH  8
#define DHD 64
#define TOT (Bsz * SEQ)
#define ATTN_SCALE 0.125f

// ---- device scratch ---------------------------------------------------------
__device__ float g_inputs[(size_t)TOT * 1024];
__device__ float g_query [(size_t)TOT * EMB];
__device__ float g_x     [(size_t)TOT * EMB];
__device__ float g_attn  [(size_t)TOT * EMB];
__device__ float g_outb  [(size_t)TOT * EMB];
__device__ __nv_bfloat16 g_W[2 * 512 * 1024 + 12 * 512 * 512];   // weight planes
__device__ __nv_bfloat16 g_Qh[(size_t)TOT * EMB], g_Ql[(size_t)TOT * EMB];
__device__ __nv_bfloat16 g_Kh[(size_t)TOT * EMB], g_Kl[(size_t)TOT * EMB];
__device__ __nv_bfloat16 g_Vh[(size_t)TOT * EMB], g_Vl[(size_t)TOT * EMB];

// ---------------------------------------------------------------------------
__device__ __forceinline__ uint32_t pack_bf16(float x, float y) {
    __nv_bfloat162 h = __floats2bfloat162_rn(x, y);
    return *reinterpret_cast<uint32_t*>(&h);
}
__device__ __forceinline__ float bf16_hi_f(float x) {
    return __bfloat162float(__float2bfloat16_rn(x));
}
__device__ __forceinline__ void mma_bf16(float* c, const uint32_t* a, const uint32_t* b) {
    asm volatile(
        "mma.sync.aligned.m16n8k16.row.col.f32.bf16.bf16.f32 "
        "{%0,%1,%2,%3}, {%4,%5,%6,%7}, {%8,%9}, {%0,%1,%2,%3};"
        : "+f"(c[0]), "+f"(c[1]), "+f"(c[2]), "+f"(c[3])
        : "r"(a[0]), "r"(a[1]), "r"(a[2]), "r"(a[3]), "r"(b[0]), "r"(b[1]));
}
__device__ __forceinline__ void ldm_x4(uint32_t* r, uint32_t a) {
    asm volatile("ldmatrix.sync.aligned.m8n8.x4.shared.b16 {%0,%1,%2,%3}, [%4];"
        : "=r"(r[0]), "=r"(r[1]), "=r"(r[2]), "=r"(r[3]) : "r"(a));
}
__device__ __forceinline__ void ldm_x4t(uint32_t* r, uint32_t a) {
    asm volatile("ldmatrix.sync.aligned.m8n8.x4.trans.shared.b16 {%0,%1,%2,%3}, [%4];"
        : "=r"(r[0]), "=r"(r[1]), "=r"(r[2]), "=r"(r[3]) : "r"(a));
}
__device__ __forceinline__ uint32_t smaddr(const void* p) {
    return (uint32_t)__cvta_generic_to_shared(p);
}
#define CPA16(dst, src) \
    asm volatile("cp.async.ca.shared.global [%0], [%1], 16;" :: "r"(dst), "l"(src))
#define CPA_COMMIT() asm volatile("cp.async.commit_group;")
#define CPA_WAIT0()  asm volatile("cp.async.wait_group 0;")

__device__ __forceinline__ void cvt_store4(float4 v, __nv_bfloat16* hi, __nv_bfloat16* lo) {
    float hx = bf16_hi_f(v.x), hy = bf16_hi_f(v.y);
    float hz = bf16_hi_f(v.z), hw = bf16_hi_f(v.w);
    *reinterpret_cast<uint2*>(hi) = make_uint2(pack_bf16(v.x, v.y), pack_bf16(v.z, v.w));
    *reinterpret_cast<uint2*>(lo) = make_uint2(pack_bf16(v.x - hx, v.y - hy),
                                               pack_bf16(v.z - hz, v.w - hw));
}

// ---------------------------------------------------------------------------
// Gather
// ---------------------------------------------------------------------------
__global__ __launch_bounds__(128) void gather_kernel(
    const int* __restrict__ item_inputs, const int* __restrict__ skill_inputs,
    const int* __restrict__ label_inputs,
    const int* __restrict__ item_ids, const int* __restrict__ skill_ids,
    const float* __restrict__ item_emb, const float* __restrict__ skill_emb,
    float* __restrict__ inputs, float* __restrict__ query)
{
    int g = blockIdx.x;
    int t = threadIdx.x;
    float lab = (float)label_inputs[g];
    float nlab = 1.0f - lab;
    if (t < 64) {
        const float4* ie = reinterpret_cast<const float4*>(item_emb + (size_t)item_inputs[g] * 256);
        float4 v = ie[t];
        float4 a = make_float4(v.x * lab, v.y * lab, v.z * lab, v.w * lab);
        float4 c = make_float4(v.x * nlab, v.y * nlab, v.z * nlab, v.w * nlab);
        *reinterpret_cast<float4*>(inputs + (size_t)g * 1024 + t * 4)       = a;
        *reinterpret_cast<float4*>(inputs + (size_t)g * 1024 + 512 + t * 4) = c;
        const float4* qe = reinterpret_cast<const float4*>(item_emb + (size_t)item_ids[g] * 256);
        *reinterpret_cast<float4*>(query + (size_t)g * 512 + t * 4) = qe[t];
    } else {
        int u = t - 64;
        const float4* se = reinterpret_cast<const float4*>(skill_emb + (size_t)skill_inputs[g] * 256);
        float4 v = se[u];
        float4 a = make_float4(v.x * lab, v.y * lab, v.z * lab, v.w * lab);
        float4 c = make_float4(v.x * nlab, v.y * nlab, v.z * nlab, v.w * nlab);
        *reinterpret_cast<float4*>(inputs + (size_t)g * 1024 + 256 + u * 4)       = a;
        *reinterpret_cast<float4*>(inputs + (size_t)g * 1024 + 512 + 256 + u * 4) = c;
        const float4* qs = reinterpret_cast<const float4*>(skill_emb + (size_t)skill_ids[g] * 256);
        *reinterpret_cast<float4*>(query + (size_t)g * 512 + 256 + u * 4) = qs[u];
    }
}

// ---------------------------------------------------------------------------
// Weight transpose + bf16 hi/lo split
// ---------------------------------------------------------------------------
__global__ __launch_bounds__(256) void transpose_cvt_kernel(
    const float* __restrict__ src, __nv_bfloat16* __restrict__ dhi,
    __nv_bfloat16* __restrict__ dlo, int K, int N)
{
    __shared__ float t[32][33];
    int bx = blockIdx.x * 32, by = blockIdx.y * 32;
    int x = threadIdx.x & 31, y0 = threadIdx.x >> 5;
#pragma unroll
    for (int j = 0; j < 32; j += 8)
        t[y0 + j][x] = src[(size_t)(by + y0 + j) * N + bx + x];
    __syncthreads();
#pragma unroll
    for (int j = 0; j < 32; j += 8) {
        float v = t[x][y0 + j];
        float h = bf16_hi_f(v);
        size_t idx = (size_t)(bx + y0 + j) * K + by + x;
        dhi[idx] = __float2bfloat16_rn(v);
        dlo[idx] = __float2bfloat16_rn(v - h);
    }
}

// ---------------------------------------------------------------------------
// bf16 GEMM, ldmatrix + cp.async + 2-stage double buffer, 1 sync/chunk.
// C = act(A[M,K]f32 @ Bt^T + bias). EPI: 0 = f32+relu, 2 = bf16 hi/lo planes.
// ---------------------------------------------------------------------------
#define RSTR 40
#define PLANE_B (128 * RSTR * 2)
#define STAGE_B (4 * PLANE_B)
#define GEMM_SMEM (2 * STAGE_B)

template<int EPI>
__global__ __launch_bounds__(256, 2)
void gemm_bf16_kernel(const float* __restrict__ A,
                      const __nv_bfloat16* __restrict__ Bthi,
                      const __nv_bfloat16* __restrict__ Btlo,
                      const float* __restrict__ bias,
                      float* __restrict__ C,
                      __nv_bfloat16* __restrict__ Chi,
                      __nv_bfloat16* __restrict__ Clo,
                      int K)
{
    extern __shared__ __align__(16) char dsm[];

    int tid = threadIdx.x;
    int wid = tid >> 5, lane = tid & 31;
    int g = lane >> 2, t = lane & 3;
    int bm = blockIdx.y * 128, bn = blockIdx.x * 128;
    int wm = (wid & 1) * 64, wn = (wid >> 1) * 32;
    int NC = K >> 5;

    // fragment lane coords
    int lm = lane & 15, kq = (lane >> 4) << 3;              // A frag
    int nb = (lane & 7) + ((lane >> 4) << 3);               // B frag row
    int kb2 = ((lane >> 3) & 1) * 8;                        // B frag k off

    // loader coords
    int lrow[4], lkc[4];
#pragma unroll
    for (int i = 0; i < 4; i++) {
        int f = tid + i * 256;
        lrow[i] = f >> 3;
        lkc[i] = (f & 7) * 4;
    }
    int brow[2], bc8[2];
#pragma unroll
    for (int i = 0; i < 2; i++) {
        int f = tid + i * 256;
        brow[i] = f >> 2;
        bc8[i] = (f & 3) * 8;
    }

    float acc[4][4][4];
#pragma unroll
    for (int i = 0; i < 4; i++)
#pragma unroll
        for (int j = 0; j < 4; j++)
#pragma unroll
            for (int r = 0; r < 4; r++) acc[i][j][r] = 0.f;

    // prologue: chunk 0
    {
        char* st0 = dsm;
        uint32_t bhi_u = smaddr(st0 + 2 * PLANE_B);
#pragma unroll
        for (int i = 0; i < 2; i++) {
            uint32_t doff = (uint32_t)(brow[i] * RSTR + bc8[i]) * 2;
            CPA16(bhi_u + doff, Bthi + (size_t)(bn + brow[i]) * K + bc8[i]);
            CPA16(bhi_u + PLANE_B + doff, Btlo + (size_t)(bn + brow[i]) * K + bc8[i]);
        }
        CPA_COMMIT();
        float4 sa[4];
#pragma unroll
        for (int i = 0; i < 4; i++)
            sa[i] = *reinterpret_cast<const float4*>(A + (size_t)(bm + lrow[i]) * K + lkc[i]);
#pragma unroll
        for (int i = 0; i < 4; i++) {
            int off = lrow[i] * RSTR + lkc[i];
            cvt_store4(sa[i], reinterpret_cast<__nv_bfloat16*>(st0) + off,
                              reinterpret_cast<__nv_bfloat16*>(st0 + PLANE_B) + off);
        }
        CPA_WAIT0();
        __syncthreads();
    }

    for (int chunk = 0; chunk < NC; chunk++) {
        char* cur = dsm + (chunk & 1) * STAGE_B;
        char* nxt = dsm + ((chunk + 1) & 1) * STAGE_B;
        bool more = (chunk + 1 < NC);

        float4 sa[4];
        if (more) {
            int k0 = (chunk + 1) << 5;
            uint32_t bhi_u = smaddr(nxt + 2 * PLANE_B);
#pragma unroll
            for (int i = 0; i < 2; i++) {
                uint32_t doff = (uint32_t)(brow[i] * RSTR + bc8[i]) * 2;
                CPA16(bhi_u + doff, Bthi + (size_t)(bn + brow[i]) * K + k0 + bc8[i]);
                CPA16(bhi_u + PLANE_B + doff, Btlo + (size_t)(bn + brow[i]) * K + k0 + bc8[i]);
            }
            CPA_COMMIT();
#pragma unroll
            for (int i = 0; i < 4; i++)
                sa[i] = *reinterpret_cast<const float4*>(A + (size_t)(bm + lrow[i]) * K + k0 + lkc[i]);
        }

        // ---- compute current chunk ----
        uint32_t ahi_u = smaddr(cur);
        uint32_t bhi_u = smaddr(cur + 2 * PLANE_B);
#pragma unroll
        for (int s = 0; s < 2; s++) {
            uint32_t bh[4][2], bl[4][2];
#pragma unroll
            for (int jp = 0; jp < 2; jp++) {
                uint32_t off = (uint32_t)((wn + jp * 16 + nb) * RSTR + s * 16 + kb2) * 2;
                uint32_t r[4];
                ldm_x4(r, bhi_u + off);
                bh[jp * 2][0] = r[0]; bh[jp * 2][1] = r[1];
                bh[jp * 2 + 1][0] = r[2]; bh[jp * 2 + 1][1] = r[3];
                ldm_x4(r, bhi_u + PLANE_B + off);
                bl[jp * 2][0] = r[0]; bl[jp * 2][1] = r[1];
                bl[jp * 2 + 1][0] = r[2]; bl[jp * 2 + 1][1] = r[3];
            }
#pragma unroll
            for (int i = 0; i < 4; i++) {
                uint32_t off = (uint32_t)((wm + i * 16 + lm) * RSTR + s * 16 + kq) * 2;
                uint32_t ah[4], al[4];
                ldm_x4(ah, ahi_u + off);
                ldm_x4(al, ahi_u + PLANE_B + off);
#pragma unroll
                for (int j = 0; j < 4; j++) {
                    mma_bf16(acc[i][j], ah, bh[j]);
                    mma_bf16(acc[i][j], al, bh[j]);
                    mma_bf16(acc[i][j], ah, bl[j]);
                }
            }
        }

        if (more) {
#pragma unroll
            for (int i = 0; i < 4; i++) {
                int off = lrow[i] * RSTR + lkc[i];
                cvt_store4(sa[i], reinterpret_cast<__nv_bfloat16*>(nxt) + off,
                                  reinterpret_cast<__nv_bfloat16*>(nxt + PLANE_B) + off);
            }
            CPA_WAIT0();
            __syncthreads();
        }
    }

    // ---- epilogue ----
#pragma unroll
    for (int i = 0; i < 4; i++) {
        int row0 = bm + wm + i * 16 + g;
#pragma unroll
        for (int j = 0; j < 4; j++) {
            int col = bn + wn + j * 8 + t * 2;
            float2 bv = *reinterpret_cast<const float2*>(bias + col);
            float v0 = acc[i][j][0] + bv.x, v1 = acc[i][j][1] + bv.y;
            float v2 = acc[i][j][2] + bv.x, v3 = acc[i][j][3] + bv.y;
            if (EPI == 0) {
                v0 = fmaxf(v0, 0.f); v1 = fmaxf(v1, 0.f);
                v2 = fmaxf(v2, 0.f); v3 = fmaxf(v3, 0.f);
                *reinterpret_cast<float2*>(C + (size_t)row0 * 512 + col)       = make_float2(v0, v1);
                *reinterpret_cast<float2*>(C + (size_t)(row0 + 8) * 512 + col) = make_float2(v2, v3);
            } else {
                size_t i0 = (size_t)row0 * 512 + col;
                size_t i1 = (size_t)(row0 + 8) * 512 + col;
                *reinterpret_cast<uint32_t*>(Chi + i0) = pack_bf16(v0, v1);
                *reinterpret_cast<uint32_t*>(Clo + i0) =
                    pack_bf16(v0 - bf16_hi_f(v0), v1 - bf16_hi_f(v1));
                *reinterpret_cast<uint32_t*>(Chi + i1) = pack_bf16(v2, v3);
                *reinterpret_cast<uint32_t*>(Clo + i1) =
                    pack_bf16(v2 - bf16_hi_f(v2), v3 - bf16_hi_f(v3));
            }
        }
    }
}

// ---------------------------------------------------------------------------
// Flash attention: bf16 planes in, f32 out. ldmatrix everywhere; V via trans.
// CTA = (b, h, 128 q rows); warp = 16 q rows. 64-key steps, warp-level skip.
// ---------------------------------------------------------------------------
#define QS 72
#define FL_SMEM ((2 * 128 * QS + 4 * 64 * QS) * 2)

__global__ __launch_bounds__(256, 2) void flash_bf16_kernel(
    const __nv_bfloat16* __restrict__ Qh, const __nv_bfloat16* __restrict__ Ql,
    const __nv_bfloat16* __restrict__ Kh, const __nv_bfloat16* __restrict__ Kl,
    const __nv_bfloat16* __restrict__ Vh, const __nv_bfloat16* __restrict__ Vl,
    float* __restrict__ Op)
{
    extern __shared__ __align__(16) char fsm[];
    __nv_bfloat16* sQh = reinterpret_cast<__nv_bfloat16*>(fsm);
    __nv_bfloat16* sQl = sQh + 128 * QS;
    __nv_bfloat16* sKh = sQl + 128 * QS;
    __nv_bfloat16* sKl = sKh + 64 * QS;
    __nv_bfloat16* sVh = sKl + 64 * QS;
    __nv_bfloat16* sVl = sVh + 64 * QS;
    uint32_t uQh = smaddr(sQh), uQl = smaddr(sQl);
    uint32_t uKh = smaddr(sKh), uKl = smaddr(sKl);
    uint32_t uVh = smaddr(sVh), uVl = smaddr(sVl);

    int tid = threadIdx.x;
    int wid = tid >> 5, lane = tid & 31;
    int g = lane >> 2, t = lane & 3;
    int qt = (SEQ / 128 - 1) - blockIdx.x;      // heavy CTAs first
    int h = blockIdx.y, b = blockIdx.z;
    size_t qoff = ((size_t)(b * SEQ + qt * 128)) * EMB + h * DHD;
    size_t kvoff = ((size_t)b * SEQ) * EMB + h * DHD;

    // Q planes -> smem
#pragma unroll
    for (int i = 0; i < 4; i++) {
        int f = tid + i * 256;
        int r = f >> 3, c = (f & 7) * 8;
        *reinterpret_cast<uint4*>(sQh + r * QS + c) =
            *reinterpret_cast<const uint4*>(Qh + qoff + (size_t)r * EMB + c);
        *reinterpret_cast<uint4*>(sQl + r * QS + c) =
            *reinterpret_cast<const uint4*>(Ql + qoff + (size_t)r * EMB + c);
    }

    float m0 = -INFINITY, m1 = -INFINITY, l0 = 0.f, l1 = 0.f;
    float acc[8][4];
#pragma unroll
    for (int j = 0; j < 8; j++)
#pragma unroll
        for (int r = 0; r < 4; r++) acc[j][r] = 0.f;

    int rb = wid * 16;
    int row0g = qt * 128 + rb + g, row1g = row0g + 8;
    int wmaxrow = qt * 128 + rb + 15;
    int ktmax = qt * 2 + 1;

    int lm = lane & 15, kq = (lane >> 4) << 3;             // QK A-frag
    int nbk = (lane & 7) + ((lane >> 4) << 3);             // QK B-frag (K rows)
    int kb2 = ((lane >> 3) & 1) * 8;
    int kv = (lane & 7) + ((lane >> 3) & 1) * 8;           // PV B-frag (V rows=keys)
    int nv = (lane >> 4) << 3;                             // PV B-frag (V cols=d)

    for (int kt = 0; kt <= ktmax; kt++) {
        __syncthreads();
        size_t ko = kvoff + (size_t)kt * 64 * EMB;
#pragma unroll
        for (int i = 0; i < 2; i++) {
            int f = tid + i * 256;
            int r = f >> 3, c = (f & 7) * 8;
            *reinterpret_cast<uint4*>(sKh + r * QS + c) =
                *reinterpret_cast<const uint4*>(Kh + ko + (size_t)r * EMB + c);
            *reinterpret_cast<uint4*>(sKl + r * QS + c) =
                *reinterpret_cast<const uint4*>(Kl + ko + (size_t)r * EMB + c);
            *reinterpret_cast<uint4*>(sVh + r * QS + c) =
                *reinterpret_cast<const uint4*>(Vh + ko + (size_t)r * EMB + c);
            *reinterpret_cast<uint4*>(sVl + r * QS + c) =
                *reinterpret_cast<const uint4*>(Vl + ko + (size_t)r * EMB + c);
        }
        __syncthreads();

        if (kt * 64 > wmaxrow) continue;   // whole key tile masked for this warp

        // ---- S = Q K^T ----
        float s[8][4];
#pragma unroll
        for (int j = 0; j < 8; j++)
#pragma unroll
            for (int r = 0; r < 4; r++) s[j][r] = 0.f;
#pragma unroll
        for (int kk = 0; kk < 4; kk++) {
            uint32_t qo = (uint32_t)((rb + lm) * QS + kk * 16 + kq) * 2;
            uint32_t ah[4], al[4];
            ldm_x4(ah, uQh + qo);
            ldm_x4(al, uQl + qo);
#pragma unroll
            for (int jp = 0; jp < 4; jp++) {
                uint32_t koff = (uint32_t)((jp * 16 + nbk) * QS + kk * 16 + kb2) * 2;
                uint32_t rh[4], rl[4];
                ldm_x4(rh, uKh + koff);
                ldm_x4(rl, uKl + koff);
                {
                    uint32_t b0[2] = { rh[0], rh[1] }, c0[2] = { rl[0], rl[1] };
                    mma_bf16(s[2 * jp], ah, b0);
                    mma_bf16(s[2 * jp], al, b0);
                    mma_bf16(s[2 * jp], ah, c0);
                }
                {
                    uint32_t b1[2] = { rh[2], rh[3] }, c1[2] = { rl[2], rl[3] };
                    mma_bf16(s[2 * jp + 1], ah, b1);
                    mma_bf16(s[2 * jp + 1], al, b1);
                    mma_bf16(s[2 * jp + 1], ah, c1);
                }
            }
        }

        // ---- scale + causal mask ----
        int colb = kt * 64 + t * 2;
#pragma unroll
        for (int j = 0; j < 8; j++) {
            int c0 = colb + j * 8, c1 = c0 + 1;
            s[j][0] = (c0 > row0g) ? -INFINITY : s[j][0] * ATTN_SCALE;
            s[j][1] = (c1 > row0g) ? -INFINITY : s[j][1] * ATTN_SCALE;
            s[j][2] = (c0 > row1g) ? -INFINITY : s[j][2] * ATTN_SCALE;
            s[j][3] = (c1 > row1g) ? -INFINITY : s[j][3] * ATTN_SCALE;
        }

        // ---- online softmax ----
        float tm0 = -INFINITY, tm1 = -INFINITY;
#pragma unroll
        for (int j = 0; j < 8; j++) {
            tm0 = fmaxf(tm0, fmaxf(s[j][0], s[j][1]));
            tm1 = fmaxf(tm1, fmaxf(s[j][2], s[j][3]));
        }
        tm0 = fmaxf(tm0, __shfl_xor_sync(0xFFFFFFFFu, tm0, 1));
        tm0 = fmaxf(tm0, __shfl_xor_sync(0xFFFFFFFFu, tm0, 2));
        tm1 = fmaxf(tm1, __shfl_xor_sync(0xFFFFFFFFu, tm1, 1));
        tm1 = fmaxf(tm1, __shfl_xor_sync(0xFFFFFFFFu, tm1, 2));
        float m0n = fmaxf(m0, tm0), m1n = fmaxf(m1, tm1);
        float ms0 = fmaxf(m0n, -1e30f), ms1 = fmaxf(m1n, -1e30f);
        float alpha0 = __expf(m0 - ms0), alpha1 = __expf(m1 - ms1);
        m0 = m0n; m1 = m1n;
#pragma unroll
        for (int j = 0; j < 8; j++) {
            acc[j][0] *= alpha0; acc[j][1] *= alpha0;
            acc[j][2] *= alpha1; acc[j][3] *= alpha1;
        }

        // ---- P = exp(S), fused with O += P V per 16-key block ----
        float ps0 = 0.f, ps1 = 0.f;
#pragma unroll
        for (int kk = 0; kk < 4; kk++) {
            int j0 = 2 * kk, j1 = 2 * kk + 1;
            float p00 = __expf(s[j0][0] - ms0), p01 = __expf(s[j0][1] - ms0);
            float p02 = __expf(s[j0][2] - ms1), p03 = __expf(s[j0][3] - ms1);
            float p10 = __expf(s[j1][0] - ms0), p11 = __expf(s[j1][1] - ms0);
            float p12 = __expf(s[j1][2] - ms1), p13 = __expf(s[j1][3] - ms1);
            ps0 += p00 + p01 + p10 + p11;
            ps1 += p02 + p03 + p12 + p13;
            uint32_t pah[4], pal[4];
            pah[0] = pack_bf16(p00, p01);
            pah[1] = pack_bf16(p02, p03);
            pah[2] = pack_bf16(p10, p11);
            pah[3] = pack_bf16(p12, p13);
            pal[0] = pack_bf16(p00 - bf16_hi_f(p00), p01 - bf16_hi_f(p01));
            pal[1] = pack_bf16(p02 - bf16_hi_f(p02), p03 - bf16_hi_f(p03));
            pal[2] = pack_bf16(p10 - bf16_hi_f(p10), p11 - bf16_hi_f(p11));
            pal[3] = pack_bf16(p12 - bf16_hi_f(p12), p13 - bf16_hi_f(p13));
#pragma unroll
            for (int jdp = 0; jdp < 4; jdp++) {
                uint32_t voff = (uint32_t)((kk * 16 + kv) * QS + jdp * 16 + nv) * 2;
                uint32_t rh[4], rl[4];
                ldm_x4t(rh, uVh + voff);
                ldm_x4t(rl, uVl + voff);
                {
                    uint32_t b0[2] = { rh[0], rh[1] }, c0[2] = { rl[0], rl[1] };
                    mma_bf16(acc[2 * jdp], pah, b0);
                    mma_bf16(acc[2 * jdp], pal, b0);
                    mma_bf16(acc[2 * jdp], pah, c0);
                }
                {
                    uint32_t b1[2] = { rh[2], rh[3] }, c1[2] = { rl[2], rl[3] };
                    mma_bf16(acc[2 * jdp + 1], pah, b1);
                    mma_bf16(acc[2 * jdp + 1], pal, b1);
                    mma_bf16(acc[2 * jdp + 1], pah, c1);
                }
            }
        }
        ps0 += __shfl_xor_sync(0xFFFFFFFFu, ps0, 1);
        ps0 += __shfl_xor_sync(0xFFFFFFFFu, ps0, 2);
        ps1 += __shfl_xor_sync(0xFFFFFFFFu, ps1, 1);
        ps1 += __shfl_xor_sync(0xFFFFFFFFu, ps1, 2);
        l0 = l0 * alpha0 + ps0;
        l1 = l1 * alpha1 + ps1;
    }

    float inv0 = 1.f / l0, inv1 = 1.f / l1;
#pragma unroll
    for (int jd = 0; jd < 8; jd++) {
        int c = jd * 8 + t * 2;
        *reinterpret_cast<float2*>(Op + qoff + (size_t)(rb + g) * EMB + c) =
            make_float2(acc[jd][0] * inv0, acc[jd][1] * inv0);
        *reinterpret_cast<float2*>(Op + qoff + (size_t)(rb + g + 8) * EMB + c) =
            make_float2(acc[jd][2] * inv1, acc[jd][3] * inv1);
    }
}

// ---------------------------------------------------------------------------
__global__ __launch_bounds__(512) void add_relu_kernel(
    float* __restrict__ out, const float* __restrict__ res)
{
    size_t i = (size_t)blockIdx.x * blockDim.x + threadIdx.x;
    float4 o = reinterpret_cast<float4*>(out)[i];
    float4 r = reinterpret_cast<const float4*>(res)[i];
    o.x += fmaxf(r.x, 0.f); o.y += fmaxf(r.y, 0.f);
    o.z += fmaxf(r.z, 0.f); o.w += fmaxf(r.w, 0.f);
    reinterpret_cast<float4*>(out)[i] = o;
}

__global__ __launch_bounds__(256) void out_proj_kernel(
    const float* __restrict__ out, const float* __restrict__ Wout,
    const float* __restrict__ bout, float* __restrict__ y)
{
    int g = blockIdx.x * 8 + (threadIdx.x >> 5);
    int lane = threadIdx.x & 31;
    const float4* o4 = reinterpret_cast<const float4*>(out + (size_t)g * EMB);
    const float4* w4 = reinterpret_cast<const float4*>(Wout);
    float s = 0.f;
#pragma unroll
    for (int i = 0; i < 4; i++) {
        float4 a = o4[lane + 32 * i];
        float4 b = w4[lane + 32 * i];
        s += a.x * b.x + a.y * b.y + a.z * b.z + a.w * b.w;
    }
#pragma unroll
    for (int off = 16; off > 0; off >>= 1)
        s += __shfl_xor_sync(0xFFFFFFFFu, s, off);
    if (lane == 0) y[g] = s + bout[0];
}

// ---------------------------------------------------------------------------
extern "C" void kernel_launch(void* const* d_in, const int* in_sizes, int n_in,
                              void* d_out, int out_size)
{
    const int*   item_inputs  = (const int*)d_in[0];
    const int*   skill_inputs = (const int*)d_in[1];
    const int*   label_inputs = (const int*)d_in[2];
    const int*   item_ids     = (const int*)d_in[3];
    const int*   skill_ids    = (const int*)d_in[4];
    const float* item_emb     = (const float*)d_in[5];
    const float* skill_emb    = (const float*)d_in[6];
    const float* W_in         = (const float*)d_in[7];
    const float* b_in         = (const float*)d_in[8];
    const float* Wq           = (const float*)d_in[9];
    const float* bq           = (const float*)d_in[10];
    const float* Wk           = (const float*)d_in[11];
    const float* bk           = (const float*)d_in[12];
    const float* Wv           = (const float*)d_in[13];
    const float* bv           = (const float*)d_in[14];
    const float* W_out        = (const float*)d_in[22];
    const float* b_out        = (const float*)d_in[23];
    float* y = (float*)d_out;

    float *inputs, *query, *x, *attn, *outb;
    __nv_bfloat16 *w, *qh, *ql, *kh, *kl, *vh, *vl;
    cudaGetSymbolAddress((void**)&inputs, g_inputs);
    cudaGetSymbolAddress((void**)&query,  g_query);
    cudaGetSymbolAddress((void**)&x,      g_x);
    cudaGetSymbolAddress((void**)&attn,   g_attn);
    cudaGetSymbolAddress((void**)&outb,   g_outb);
    cudaGetSymbolAddress((void**)&w,      g_W);
    cudaGetSymbolAddress((void**)&qh,     g_Qh);
    cudaGetSymbolAddress((void**)&ql,     g_Ql);
    cudaGetSymbolAddress((void**)&kh,     g_Kh);
    cudaGetSymbolAddress((void**)&kl,     g_Kl);
    cudaGetSymbolAddress((void**)&vh,     g_Vh);
    cudaGetSymbolAddress((void**)&vl,     g_Vl);

    cudaFuncSetAttribute(flash_bf16_kernel,
                         cudaFuncAttributeMaxDynamicSharedMemorySize, FL_SMEM);
    cudaFuncSetAttribute(gemm_bf16_kernel<0>,
                         cudaFuncAttributeMaxDynamicSharedMemorySize, GEMM_SMEM);
    cudaFuncSetAttribute(gemm_bf16_kernel<2>,
                         cudaFuncAttributeMaxDynamicSharedMemorySize, GEMM_SMEM);

    __nv_bfloat16* win_hi = w;
    __nv_bfloat16* win_lo = w + 512 * 1024;
    __nv_bfloat16* qkv_hi[2][3];
    __nv_bfloat16* qkv_lo[2][3];
    {
        __nv_bfloat16* p = w + 2 * 512 * 1024;
        for (int l = 0; l < 2; l++)
            for (int m = 0; m < 3; m++) {
                qkv_hi[l][m] = p; p += 512 * 512;
                qkv_lo[l][m] = p; p += 512 * 512;
            }
    }

    gather_kernel<<<TOT, 128>>>(item_inputs, skill_inputs, label_inputs,
                                item_ids, skill_ids, item_emb, skill_emb,
                                inputs, query);
    transpose_cvt_kernel<<<dim3(16, 32), 256>>>(W_in, win_hi, win_lo, 1024, 512);
    const size_t wo = (size_t)EMB * EMB;
    for (int l = 0; l < 2; l++) {
        transpose_cvt_kernel<<<dim3(16, 16), 256>>>(Wq + l * wo, qkv_hi[l][0], qkv_lo[l][0], 512, 512);
        transpose_cvt_kernel<<<dim3(16, 16), 256>>>(Wk + l * wo, qkv_hi[l][1], qkv_lo[l][1], 512, 512);
        transpose_cvt_kernel<<<dim3(16, 16), 256>>>(Wv + l * wo, qkv_hi[l][2], qkv_lo[l][2], 512, 512);
    }

    // x = relu(inputs @ W_in + b_in)
    gemm_bf16_kernel<0><<<dim3(4, 128), 256, GEMM_SMEM>>>(
        inputs, win_hi, win_lo, b_in, x, nullptr, nullptr, 1024);

    for (int l = 0; l < 2; l++) {
        const float* src = (l == 0) ? x : outb;
        gemm_bf16_kernel<2><<<dim3(4, 128), 256, GEMM_SMEM>>>(
            query, qkv_hi[l][0], qkv_lo[l][0], bq + l * EMB, nullptr, qh, ql, 512);
        gemm_bf16_kernel<2><<<dim3(4, 128), 256, GEMM_SMEM>>>(
            src, qkv_hi[l][1], qkv_lo[l][1], bk + l * EMB, nullptr, kh, kl, 512);
        gemm_bf16_kernel<2><<<dim3(4, 128), 256, GEMM_SMEM>>>(
            src, qkv_hi[l][2], qkv_lo[l][2], bv + l * EMB, nullptr, vh, vl, 512);
        flash_bf16_kernel<<<dim3(SEQ / 128, NH, Bsz), 256, FL_SMEM>>>(
            qh, ql, kh, kl, vh, vl, (l == 0) ? outb : attn);
        if (l == 1)
            add_relu_kernel<<<(TOT * EMB / 4) / 512, 512>>>(outb, attn);
    }

    out_proj_kernel<<<TOT / 8, 256>>>(outb, W_out, b_out, y);
}

// round 6
// speedup vs baseline: 3.0640x; 1.0925x over previous
#include <cuda_runtime.h>
#include <cuda_bf16.h>
#include <cstdint>

// ---------------------------------------------------------------------------
// TSAKT: gather -> ReLU MLP -> 2x causal MHA -> output proj.
// glo/ts biases are key-constant pre-mask => softmax-shift-invariant => dropped.
// R6: flash with cp.async double-buffered K/V + register-hoisted Q frags,
//     fused QKV GEMM launch (blockIdx.z), batched transposes, fused add_relu.
// ---------------------------------------------------------------------------

#define Bsz 32
#define SEQ 512
#define EMB 512
#define NH  8
#define DHD 64
#define TOT (Bsz * SEQ)
#define ATTN_SCALE 0.125f

// ---- device scratch ---------------------------------------------------------
__device__ float g_inputs[(size_t)TOT * 1024];
__device__ float g_query [(size_t)TOT * EMB];
__device__ float g_x     [(size_t)TOT * EMB];
__device__ float g_outb  [(size_t)TOT * EMB];
__device__ __nv_bfloat16 g_W[2 * 512 * 1024 + 12 * 512 * 512];
__device__ __nv_bfloat16 g_Qh[(size_t)TOT * EMB], g_Ql[(size_t)TOT * EMB];
__device__ __nv_bfloat16 g_Kh[(size_t)TOT * EMB], g_Kl[(size_t)TOT * EMB];
__device__ __nv_bfloat16 g_Vh[(size_t)TOT * EMB], g_Vl[(size_t)TOT * EMB];

// ---------------------------------------------------------------------------
__device__ __forceinline__ uint32_t pack_bf16(float x, float y) {
    __nv_bfloat162 h = __floats2bfloat162_rn(x, y);
    return *reinterpret_cast<uint32_t*>(&h);
}
__device__ __forceinline__ float bf16_hi_f(float x) {
    return __bfloat162float(__float2bfloat16_rn(x));
}
__device__ __forceinline__ void mma_bf16(float* c, const uint32_t* a, const uint32_t* b) {
    asm volatile(
        "mma.sync.aligned.m16n8k16.row.col.f32.bf16.bf16.f32 "
        "{%0,%1,%2,%3}, {%4,%5,%6,%7}, {%8,%9}, {%0,%1,%2,%3};"
        : "+f"(c[0]), "+f"(c[1]), "+f"(c[2]), "+f"(c[3])
        : "r"(a[0]), "r"(a[1]), "r"(a[2]), "r"(a[3]), "r"(b[0]), "r"(b[1]));
}
__device__ __forceinline__ void ldm_x4(uint32_t* r, uint32_t a) {
    asm volatile("ldmatrix.sync.aligned.m8n8.x4.shared.b16 {%0,%1,%2,%3}, [%4];"
        : "=r"(r[0]), "=r"(r[1]), "=r"(r[2]), "=r"(r[3]) : "r"(a));
}
__device__ __forceinline__ void ldm_x4t(uint32_t* r, uint32_t a) {
    asm volatile("ldmatrix.sync.aligned.m8n8.x4.trans.shared.b16 {%0,%1,%2,%3}, [%4];"
        : "=r"(r[0]), "=r"(r[1]), "=r"(r[2]), "=r"(r[3]) : "r"(a));
}
__device__ __forceinline__ uint32_t smaddr(const void* p) {
    return (uint32_t)__cvta_generic_to_shared(p);
}
#define CPA16(dst, src) \
    asm volatile("cp.async.ca.shared.global [%0], [%1], 16;" :: "r"(dst), "l"(src))
#define CPA_COMMIT() asm volatile("cp.async.commit_group;")
#define CPA_WAIT(n)  asm volatile("cp.async.wait_group %0;" :: "n"(n))

__device__ __forceinline__ void cvt_store4(float4 v, __nv_bfloat16* hi, __nv_bfloat16* lo) {
    float hx = bf16_hi_f(v.x), hy = bf16_hi_f(v.y);
    float hz = bf16_hi_f(v.z), hw = bf16_hi_f(v.w);
    *reinterpret_cast<uint2*>(hi) = make_uint2(pack_bf16(v.x, v.y), pack_bf16(v.z, v.w));
    *reinterpret_cast<uint2*>(lo) = make_uint2(pack_bf16(v.x - hx, v.y - hy),
                                               pack_bf16(v.z - hz, v.w - hw));
}

// ---------------------------------------------------------------------------
// Gather
// ---------------------------------------------------------------------------
__global__ __launch_bounds__(128) void gather_kernel(
    const int* __restrict__ item_inputs, const int* __restrict__ skill_inputs,
    const int* __restrict__ label_inputs,
    const int* __restrict__ item_ids, const int* __restrict__ skill_ids,
    const float* __restrict__ item_emb, const float* __restrict__ skill_emb,
    float* __restrict__ inputs, float* __restrict__ query)
{
    int g = blockIdx.x;
    int t = threadIdx.x;
    float lab = (float)label_inputs[g];
    float nlab = 1.0f - lab;
    if (t < 64) {
        const float4* ie = reinterpret_cast<const float4*>(item_emb + (size_t)item_inputs[g] * 256);
        float4 v = ie[t];
        float4 a = make_float4(v.x * lab, v.y * lab, v.z * lab, v.w * lab);
        float4 c = make_float4(v.x * nlab, v.y * nlab, v.z * nlab, v.w * nlab);
        *reinterpret_cast<float4*>(inputs + (size_t)g * 1024 + t * 4)       = a;
        *reinterpret_cast<float4*>(inputs + (size_t)g * 1024 + 512 + t * 4) = c;
        const float4* qe = reinterpret_cast<const float4*>(item_emb + (size_t)item_ids[g] * 256);
        *reinterpret_cast<float4*>(query + (size_t)g * 512 + t * 4) = qe[t];
    } else {
        int u = t - 64;
        const float4* se = reinterpret_cast<const float4*>(skill_emb + (size_t)skill_inputs[g] * 256);
        float4 v = se[u];
        float4 a = make_float4(v.x * lab, v.y * lab, v.z * lab, v.w * lab);
        float4 c = make_float4(v.x * nlab, v.y * nlab, v.z * nlab, v.w * nlab);
        *reinterpret_cast<float4*>(inputs + (size_t)g * 1024 + 256 + u * 4)       = a;
        *reinterpret_cast<float4*>(inputs + (size_t)g * 1024 + 512 + 256 + u * 4) = c;
        const float4* qs = reinterpret_cast<const float4*>(skill_emb + (size_t)skill_ids[g] * 256);
        *reinterpret_cast<float4*>(query + (size_t)g * 512 + 256 + u * 4) = qs[u];
    }
}

// ---------------------------------------------------------------------------
// Weight transposes (+ bf16 hi/lo split)
// ---------------------------------------------------------------------------
__global__ __launch_bounds__(256) void transpose_cvt_kernel(
    const float* __restrict__ src, __nv_bfloat16* __restrict__ dhi,
    __nv_bfloat16* __restrict__ dlo, int K, int N)
{
    __shared__ float t[32][33];
    int bx = blockIdx.x * 32, by = blockIdx.y * 32;
    int x = threadIdx.x & 31, y0 = threadIdx.x >> 5;
#pragma unroll
    for (int j = 0; j < 32; j += 8)
        t[y0 + j][x] = src[(size_t)(by + y0 + j) * N + bx + x];
    __syncthreads();
#pragma unroll
    for (int j = 0; j < 32; j += 8) {
        float v = t[x][y0 + j];
        float h = bf16_hi_f(v);
        size_t idx = (size_t)(bx + y0 + j) * K + by + x;
        dhi[idx] = __float2bfloat16_rn(v);
        dlo[idx] = __float2bfloat16_rn(v - h);
    }
}

struct TrArgs {
    const float* src[6];
    __nv_bfloat16* dhi[6];
    __nv_bfloat16* dlo[6];
};
__global__ __launch_bounds__(256) void transpose_qkv_kernel(TrArgs a)
{
    __shared__ float t[32][33];
    int z = blockIdx.z;
    const float* src = a.src[z];
    __nv_bfloat16* dhi = a.dhi[z];
    __nv_bfloat16* dlo = a.dlo[z];
    int bx = blockIdx.x * 32, by = blockIdx.y * 32;
    int x = threadIdx.x & 31, y0 = threadIdx.x >> 5;
#pragma unroll
    for (int j = 0; j < 32; j += 8)
        t[y0 + j][x] = src[(size_t)(by + y0 + j) * 512 + bx + x];
    __syncthreads();
#pragma unroll
    for (int j = 0; j < 32; j += 8) {
        float v = t[x][y0 + j];
        float h = bf16_hi_f(v);
        size_t idx = (size_t)(bx + y0 + j) * 512 + by + x;
        dhi[idx] = __float2bfloat16_rn(v);
        dlo[idx] = __float2bfloat16_rn(v - h);
    }
}

// ---------------------------------------------------------------------------
// GEMM core (shared by MLP and fused-QKV kernels)
// ---------------------------------------------------------------------------
#define RSTR 40
#define PLANE_B (128 * RSTR * 2)
#define STAGE_B (4 * PLANE_B)
#define GEMM_SMEM (2 * STAGE_B)

// MLP: C = relu(A @ Bt^T + bias), f32 out
__global__ __launch_bounds__(256, 2)
void gemm_mlp_kernel(const float* __restrict__ A,
                     const __nv_bfloat16* __restrict__ Bthi,
                     const __nv_bfloat16* __restrict__ Btlo,
                     const float* __restrict__ bias,
                     float* __restrict__ C, int K)
{
    extern __shared__ __align__(16) char dsm[];
    int tid = threadIdx.x;
    int wid = tid >> 5, lane = tid & 31;
    int g = lane >> 2, t = lane & 3;
    int bm = blockIdx.y * 128, bn = blockIdx.x * 128;
    int wm = (wid & 1) * 64, wn = (wid >> 1) * 32;
    int NC = K >> 5;
    int lm = lane & 15, kq = (lane >> 4) << 3;
    int nb = (lane & 7) + ((lane >> 4) << 3);
    int kb2 = ((lane >> 3) & 1) * 8;

    int lrow[4], lkc[4];
#pragma unroll
    for (int i = 0; i < 4; i++) { int f = tid + i * 256; lrow[i] = f >> 3; lkc[i] = (f & 7) * 4; }
    int brow[2], bc8[2];
#pragma unroll
    for (int i = 0; i < 2; i++) { int f = tid + i * 256; brow[i] = f >> 2; bc8[i] = (f & 3) * 8; }

    float acc[4][4][4];
#pragma unroll
    for (int i = 0; i < 4; i++)
#pragma unroll
        for (int j = 0; j < 4; j++)
#pragma unroll
            for (int r = 0; r < 4; r++) acc[i][j][r] = 0.f;

    {
        char* st0 = dsm;
        uint32_t bhi_u = smaddr(st0 + 2 * PLANE_B);
#pragma unroll
        for (int i = 0; i < 2; i++) {
            uint32_t doff = (uint32_t)(brow[i] * RSTR + bc8[i]) * 2;
            CPA16(bhi_u + doff, Bthi + (size_t)(bn + brow[i]) * K + bc8[i]);
            CPA16(bhi_u + PLANE_B + doff, Btlo + (size_t)(bn + brow[i]) * K + bc8[i]);
        }
        CPA_COMMIT();
        float4 sa[4];
#pragma unroll
        for (int i = 0; i < 4; i++)
            sa[i] = *reinterpret_cast<const float4*>(A + (size_t)(bm + lrow[i]) * K + lkc[i]);
#pragma unroll
        for (int i = 0; i < 4; i++) {
            int off = lrow[i] * RSTR + lkc[i];
            cvt_store4(sa[i], reinterpret_cast<__nv_bfloat16*>(st0) + off,
                              reinterpret_cast<__nv_bfloat16*>(st0 + PLANE_B) + off);
        }
        CPA_WAIT(0);
        __syncthreads();
    }

    for (int chunk = 0; chunk < NC; chunk++) {
        char* cur = dsm + (chunk & 1) * STAGE_B;
        char* nxt = dsm + ((chunk + 1) & 1) * STAGE_B;
        bool more = (chunk + 1 < NC);
        float4 sa[4];
        if (more) {
            int k0 = (chunk + 1) << 5;
            uint32_t bhi_u = smaddr(nxt + 2 * PLANE_B);
#pragma unroll
            for (int i = 0; i < 2; i++) {
                uint32_t doff = (uint32_t)(brow[i] * RSTR + bc8[i]) * 2;
                CPA16(bhi_u + doff, Bthi + (size_t)(bn + brow[i]) * K + k0 + bc8[i]);
                CPA16(bhi_u + PLANE_B + doff, Btlo + (size_t)(bn + brow[i]) * K + k0 + bc8[i]);
            }
            CPA_COMMIT();
#pragma unroll
            for (int i = 0; i < 4; i++)
                sa[i] = *reinterpret_cast<const float4*>(A + (size_t)(bm + lrow[i]) * K + k0 + lkc[i]);
        }
        uint32_t ahi_u = smaddr(cur);
        uint32_t bhi_u = smaddr(cur + 2 * PLANE_B);
#pragma unroll
        for (int s = 0; s < 2; s++) {
            uint32_t bh[4][2], bl[4][2];
#pragma unroll
            for (int jp = 0; jp < 2; jp++) {
                uint32_t off = (uint32_t)((wn + jp * 16 + nb) * RSTR + s * 16 + kb2) * 2;
                uint32_t r[4];
                ldm_x4(r, bhi_u + off);
                bh[jp * 2][0] = r[0]; bh[jp * 2][1] = r[1];
                bh[jp * 2 + 1][0] = r[2]; bh[jp * 2 + 1][1] = r[3];
                ldm_x4(r, bhi_u + PLANE_B + off);
                bl[jp * 2][0] = r[0]; bl[jp * 2][1] = r[1];
                bl[jp * 2 + 1][0] = r[2]; bl[jp * 2 + 1][1] = r[3];
            }
#pragma unroll
            for (int i = 0; i < 4; i++) {
                uint32_t off = (uint32_t)((wm + i * 16 + lm) * RSTR + s * 16 + kq) * 2;
                uint32_t ah[4], al[4];
                ldm_x4(ah, ahi_u + off);
                ldm_x4(al, ahi_u + PLANE_B + off);
#pragma unroll
                for (int j = 0; j < 4; j++) {
                    mma_bf16(acc[i][j], ah, bh[j]);
                    mma_bf16(acc[i][j], al, bh[j]);
                    mma_bf16(acc[i][j], ah, bl[j]);
                }
            }
        }
        if (more) {
#pragma unroll
            for (int i = 0; i < 4; i++) {
                int off = lrow[i] * RSTR + lkc[i];
                cvt_store4(sa[i], reinterpret_cast<__nv_bfloat16*>(nxt) + off,
                                  reinterpret_cast<__nv_bfloat16*>(nxt + PLANE_B) + off);
            }
            CPA_WAIT(0);
            __syncthreads();
        }
    }

#pragma unroll
    for (int i = 0; i < 4; i++) {
        int row0 = bm + wm + i * 16 + g;
#pragma unroll
        for (int j = 0; j < 4; j++) {
            int col = bn + wn + j * 8 + t * 2;
            float2 bv = *reinterpret_cast<const float2*>(bias + col);
            float v0 = fmaxf(acc[i][j][0] + bv.x, 0.f);
            float v1 = fmaxf(acc[i][j][1] + bv.y, 0.f);
            float v2 = fmaxf(acc[i][j][2] + bv.x, 0.f);
            float v3 = fmaxf(acc[i][j][3] + bv.y, 0.f);
            *reinterpret_cast<float2*>(C + (size_t)row0 * 512 + col)       = make_float2(v0, v1);
            *reinterpret_cast<float2*>(C + (size_t)(row0 + 8) * 512 + col) = make_float2(v2, v3);
        }
    }
}

// Fused QKV: z in {0,1,2} selects (A, weight planes, bias, outputs); bf16-plane out
struct QKVArgs {
    const float* A[3];
    const __nv_bfloat16* Bh[3];
    const __nv_bfloat16* Bl[3];
    const float* bias[3];
    __nv_bfloat16* Ch[3];
    __nv_bfloat16* Cl[3];
};
__global__ __launch_bounds__(256, 2)
void gemm_qkv_kernel(QKVArgs args)
{
    extern __shared__ __align__(16) char dsm[];
    const int K = 512;
    int z = blockIdx.z;
    const float* A = args.A[z];
    const __nv_bfloat16* Bthi = args.Bh[z];
    const __nv_bfloat16* Btlo = args.Bl[z];
    const float* bias = args.bias[z];
    __nv_bfloat16* Chi = args.Ch[z];
    __nv_bfloat16* Clo = args.Cl[z];

    int tid = threadIdx.x;
    int wid = tid >> 5, lane = tid & 31;
    int g = lane >> 2, t = lane & 3;
    int bm = blockIdx.y * 128, bn = blockIdx.x * 128;
    int wm = (wid & 1) * 64, wn = (wid >> 1) * 32;
    const int NC = 16;
    int lm = lane & 15, kq = (lane >> 4) << 3;
    int nb = (lane & 7) + ((lane >> 4) << 3);
    int kb2 = ((lane >> 3) & 1) * 8;

    int lrow[4], lkc[4];
#pragma unroll
    for (int i = 0; i < 4; i++) { int f = tid + i * 256; lrow[i] = f >> 3; lkc[i] = (f & 7) * 4; }
    int brow[2], bc8[2];
#pragma unroll
    for (int i = 0; i < 2; i++) { int f = tid + i * 256; brow[i] = f >> 2; bc8[i] = (f & 3) * 8; }

    float acc[4][4][4];
#pragma unroll
    for (int i = 0; i < 4; i++)
#pragma unroll
        for (int j = 0; j < 4; j++)
#pragma unroll
            for (int r = 0; r < 4; r++) acc[i][j][r] = 0.f;

    {
        char* st0 = dsm;
        uint32_t bhi_u = smaddr(st0 + 2 * PLANE_B);
#pragma unroll
        for (int i = 0; i < 2; i++) {
            uint32_t doff = (uint32_t)(brow[i] * RSTR + bc8[i]) * 2;
            CPA16(bhi_u + doff, Bthi + (size_t)(bn + brow[i]) * K + bc8[i]);
            CPA16(bhi_u + PLANE_B + doff, Btlo + (size_t)(bn + brow[i]) * K + bc8[i]);
        }
        CPA_COMMIT();
        float4 sa[4];
#pragma unroll
        for (int i = 0; i < 4; i++)
            sa[i] = *reinterpret_cast<const float4*>(A + (size_t)(bm + lrow[i]) * K + lkc[i]);
#pragma unroll
        for (int i = 0; i < 4; i++) {
            int off = lrow[i] * RSTR + lkc[i];
            cvt_store4(sa[i], reinterpret_cast<__nv_bfloat16*>(st0) + off,
                              reinterpret_cast<__nv_bfloat16*>(st0 + PLANE_B) + off);
        }
        CPA_WAIT(0);
        __syncthreads();
    }

    for (int chunk = 0; chunk < NC; chunk++) {
        char* cur = dsm + (chunk & 1) * STAGE_B;
        char* nxt = dsm + ((chunk + 1) & 1) * STAGE_B;
        bool more = (chunk + 1 < NC);
        float4 sa[4];
        if (more) {
            int k0 = (chunk + 1) << 5;
            uint32_t bhi_u = smaddr(nxt + 2 * PLANE_B);
#pragma unroll
            for (int i = 0; i < 2; i++) {
                uint32_t doff = (uint32_t)(brow[i] * RSTR + bc8[i]) * 2;
                CPA16(bhi_u + doff, Bthi + (size_t)(bn + brow[i]) * K + k0 + bc8[i]);
                CPA16(bhi_u + PLANE_B + doff, Btlo + (size_t)(bn + brow[i]) * K + k0 + bc8[i]);
            }
            CPA_COMMIT();
#pragma unroll
            for (int i = 0; i < 4; i++)
                sa[i] = *reinterpret_cast<const float4*>(A + (size_t)(bm + lrow[i]) * K + k0 + lkc[i]);
        }
        uint32_t ahi_u = smaddr(cur);
        uint32_t bhi_u = smaddr(cur + 2 * PLANE_B);
#pragma unroll
        for (int s = 0; s < 2; s++) {
            uint32_t bh[4][2], bl[4][2];
#pragma unroll
            for (int jp = 0; jp < 2; jp++) {
                uint32_t off = (uint32_t)((wn + jp * 16 + nb) * RSTR + s * 16 + kb2) * 2;
                uint32_t r[4];
                ldm_x4(r, bhi_u + off);
                bh[jp * 2][0] = r[0]; bh[jp * 2][1] = r[1];
                bh[jp * 2 + 1][0] = r[2]; bh[jp * 2 + 1][1] = r[3];
                ldm_x4(r, bhi_u + PLANE_B + off);
                bl[jp * 2][0] = r[0]; bl[jp * 2][1] = r[1];
                bl[jp * 2 + 1][0] = r[2]; bl[jp * 2 + 1][1] = r[3];
            }
#pragma unroll
            for (int i = 0; i < 4; i++) {
                uint32_t off = (uint32_t)((wm + i * 16 + lm) * RSTR + s * 16 + kq) * 2;
                uint32_t ah[4], al[4];
                ldm_x4(ah, ahi_u + off);
                ldm_x4(al, ahi_u + PLANE_B + off);
#pragma unroll
                for (int j = 0; j < 4; j++) {
                    mma_bf16(acc[i][j], ah, bh[j]);
                    mma_bf16(acc[i][j], al, bh[j]);
                    mma_bf16(acc[i][j], ah, bl[j]);
                }
            }
        }
        if (more) {
#pragma unroll
            for (int i = 0; i < 4; i++) {
                int off = lrow[i] * RSTR + lkc[i];
                cvt_store4(sa[i], reinterpret_cast<__nv_bfloat16*>(nxt) + off,
                                  reinterpret_cast<__nv_bfloat16*>(nxt + PLANE_B) + off);
            }
            CPA_WAIT(0);
            __syncthreads();
        }
    }

#pragma unroll
    for (int i = 0; i < 4; i++) {
        int row0 = bm + wm + i * 16 + g;
#pragma unroll
        for (int j = 0; j < 4; j++) {
            int col = bn + wn + j * 8 + t * 2;
            float2 bv = *reinterpret_cast<const float2*>(bias + col);
            float v0 = acc[i][j][0] + bv.x, v1 = acc[i][j][1] + bv.y;
            float v2 = acc[i][j][2] + bv.x, v3 = acc[i][j][3] + bv.y;
            size_t i0 = (size_t)row0 * 512 + col;
            size_t i1 = (size_t)(row0 + 8) * 512 + col;
            *reinterpret_cast<uint32_t*>(Chi + i0) = pack_bf16(v0, v1);
            *reinterpret_cast<uint32_t*>(Clo + i0) =
                pack_bf16(v0 - bf16_hi_f(v0), v1 - bf16_hi_f(v1));
            *reinterpret_cast<uint32_t*>(Chi + i1) = pack_bf16(v2, v3);
            *reinterpret_cast<uint32_t*>(Clo + i1) =
                pack_bf16(v2 - bf16_hi_f(v2), v3 - bf16_hi_f(v3));
        }
    }
}

// ---------------------------------------------------------------------------
// Flash attention: cp.async double-buffered K/V stages, Q frags in registers.
// smem: 2 stages x [Kh|Kl|Vh|Vl] (64 x QS halves each). Q staged via stage0.
// OUT=0: write f32. OUT=1: Op += relu(result)  (layer-2 residual fuse).
// ---------------------------------------------------------------------------
#define QS 72
#define FPL (64 * QS)                    // halves per K/V plane
#define FSTG_B (4 * FPL * 2)             // stage bytes (36864)
#define FL_SMEM (2 * FSTG_B)

template<int OUT>
__global__ __launch_bounds__(256, 2) void flash_bf16_kernel(
    const __nv_bfloat16* __restrict__ Qh, const __nv_bfloat16* __restrict__ Ql,
    const __nv_bfloat16* __restrict__ Kh, const __nv_bfloat16* __restrict__ Kl,
    const __nv_bfloat16* __restrict__ Vh, const __nv_bfloat16* __restrict__ Vl,
    float* __restrict__ Op)
{
    extern __shared__ __align__(16) char fsm[];

    int tid = threadIdx.x;
    int wid = tid >> 5, lane = tid & 31;
    int g = lane >> 2, t = lane & 3;
    int qt = (SEQ / 128 - 1) - blockIdx.x;
    int h = blockIdx.y, b = blockIdx.z;
    size_t qoff = ((size_t)(b * SEQ + qt * 128)) * EMB + h * DHD;
    size_t kvoff = ((size_t)b * SEQ) * EMB + h * DHD;

    int rb = wid * 16;
    int lm = lane & 15, kq = (lane >> 4) << 3;
    int nbk = (lane & 7) + ((lane >> 4) << 3);
    int kb2 = ((lane >> 3) & 1) * 8;
    int kv = (lane & 7) + ((lane >> 3) & 1) * 8;
    int nv = (lane >> 4) << 3;

    // ---- stage Q through smem, hoist fragments to registers ----
    uint32_t qah[4][4], qal[4][4];
    {
        __nv_bfloat16* sQh = reinterpret_cast<__nv_bfloat16*>(fsm);
        __nv_bfloat16* sQl = sQh + 128 * QS;
#pragma unroll
        for (int i = 0; i < 4; i++) {
            int f = tid + i * 256;
            int r = f >> 3, c = (f & 7) * 8;
            *reinterpret_cast<uint4*>(sQh + r * QS + c) =
                *reinterpret_cast<const uint4*>(Qh + qoff + (size_t)r * EMB + c);
            *reinterpret_cast<uint4*>(sQl + r * QS + c) =
                *reinterpret_cast<const uint4*>(Ql + qoff + (size_t)r * EMB + c);
        }
        __syncthreads();
        uint32_t uQh = smaddr(sQh), uQl = smaddr(sQl);
#pragma unroll
        for (int kk = 0; kk < 4; kk++) {
            uint32_t qo = (uint32_t)((rb + lm) * QS + kk * 16 + kq) * 2;
            ldm_x4(qah[kk], uQh + qo);
            ldm_x4(qal[kk], uQl + qo);
        }
        __syncthreads();
    }

    int ktmax = qt * 2 + 1;
    int wmaxrow = qt * 128 + rb + 15;
    int row0g = qt * 128 + rb + g, row1g = row0g + 8;

    // cp.async loader lambda-ish (manual): per tile, 2 f-iterations x 4 planes
    int fr[2], fc[2];
#pragma unroll
    for (int i = 0; i < 2; i++) {
        int f = tid + i * 256;
        fr[i] = f >> 3; fc[i] = (f & 7) * 8;
    }

    // prologue: load tile 0 into stage 0
    {
        uint32_t st = smaddr(fsm);
        size_t ko = kvoff;
#pragma unroll
        for (int i = 0; i < 2; i++) {
            uint32_t doff = (uint32_t)(fr[i] * QS + fc[i]) * 2;
            const __nv_bfloat16* gk = Kh + ko + (size_t)fr[i] * EMB + fc[i];
            CPA16(st + doff, gk);
            CPA16(st + FPL * 2 + doff, Kl + ko + (size_t)fr[i] * EMB + fc[i]);
            CPA16(st + 2 * FPL * 2 + doff, Vh + ko + (size_t)fr[i] * EMB + fc[i]);
            CPA16(st + 3 * FPL * 2 + doff, Vl + ko + (size_t)fr[i] * EMB + fc[i]);
        }
        CPA_COMMIT();
    }

    float m0 = -INFINITY, m1 = -INFINITY, l0 = 0.f, l1 = 0.f;
    float acc[8][4];
#pragma unroll
    for (int j = 0; j < 8; j++)
#pragma unroll
        for (int r = 0; r < 4; r++) acc[j][r] = 0.f;

    for (int kt = 0; kt <= ktmax; kt++) {
        uint32_t cur = smaddr(fsm) + (kt & 1) * FSTG_B;
        bool more = (kt < ktmax);
        if (more) {
            uint32_t nxt = smaddr(fsm) + ((kt + 1) & 1) * FSTG_B;
            size_t ko = kvoff + (size_t)(kt + 1) * 64 * EMB;
#pragma unroll
            for (int i = 0; i < 2; i++) {
                uint32_t doff = (uint32_t)(fr[i] * QS + fc[i]) * 2;
                CPA16(nxt + doff, Kh + ko + (size_t)fr[i] * EMB + fc[i]);
                CPA16(nxt + FPL * 2 + doff, Kl + ko + (size_t)fr[i] * EMB + fc[i]);
                CPA16(nxt + 2 * FPL * 2 + doff, Vh + ko + (size_t)fr[i] * EMB + fc[i]);
                CPA16(nxt + 3 * FPL * 2 + doff, Vl + ko + (size_t)fr[i] * EMB + fc[i]);
            }
            CPA_COMMIT();
            CPA_WAIT(1);
        } else {
            CPA_WAIT(0);
        }
        __syncthreads();

        if (kt * 64 <= wmaxrow) {
            uint32_t uKh = cur, uKl = cur + FPL * 2;
            uint32_t uVh = cur + 2 * FPL * 2, uVl = cur + 3 * FPL * 2;

            // ---- S = Q K^T ----
            float s[8][4];
#pragma unroll
            for (int j = 0; j < 8; j++)
#pragma unroll
                for (int r = 0; r < 4; r++) s[j][r] = 0.f;
#pragma unroll
            for (int kk = 0; kk < 4; kk++) {
#pragma unroll
                for (int jp = 0; jp < 4; jp++) {
                    uint32_t koff = (uint32_t)((jp * 16 + nbk) * QS + kk * 16 + kb2) * 2;
                    uint32_t rh[4], rl[4];
                    ldm_x4(rh, uKh + koff);
                    ldm_x4(rl, uKl + koff);
                    {
                        uint32_t b0[2] = { rh[0], rh[1] }, c0[2] = { rl[0], rl[1] };
                        mma_bf16(s[2 * jp], qah[kk], b0);
                        mma_bf16(s[2 * jp], qal[kk], b0);
                        mma_bf16(s[2 * jp], qah[kk], c0);
                    }
                    {
                        uint32_t b1[2] = { rh[2], rh[3] }, c1[2] = { rl[2], rl[3] };
                        mma_bf16(s[2 * jp + 1], qah[kk], b1);
                        mma_bf16(s[2 * jp + 1], qal[kk], b1);
                        mma_bf16(s[2 * jp + 1], qah[kk], c1);
                    }
                }
            }

            // ---- scale + causal mask ----
            int colb = kt * 64 + t * 2;
#pragma unroll
            for (int j = 0; j < 8; j++) {
                int c0 = colb + j * 8, c1 = c0 + 1;
                s[j][0] = (c0 > row0g) ? -INFINITY : s[j][0] * ATTN_SCALE;
                s[j][1] = (c1 > row0g) ? -INFINITY : s[j][1] * ATTN_SCALE;
                s[j][2] = (c0 > row1g) ? -INFINITY : s[j][2] * ATTN_SCALE;
                s[j][3] = (c1 > row1g) ? -INFINITY : s[j][3] * ATTN_SCALE;
            }

            // ---- online softmax ----
            float tm0 = -INFINITY, tm1 = -INFINITY;
#pragma unroll
            for (int j = 0; j < 8; j++) {
                tm0 = fmaxf(tm0, fmaxf(s[j][0], s[j][1]));
                tm1 = fmaxf(tm1, fmaxf(s[j][2], s[j][3]));
            }
            tm0 = fmaxf(tm0, __shfl_xor_sync(0xFFFFFFFFu, tm0, 1));
            tm0 = fmaxf(tm0, __shfl_xor_sync(0xFFFFFFFFu, tm0, 2));
            tm1 = fmaxf(tm1, __shfl_xor_sync(0xFFFFFFFFu, tm1, 1));
            tm1 = fmaxf(tm1, __shfl_xor_sync(0xFFFFFFFFu, tm1, 2));
            float m0n = fmaxf(m0, tm0), m1n = fmaxf(m1, tm1);
            float ms0 = fmaxf(m0n, -1e30f), ms1 = fmaxf(m1n, -1e30f);
            float alpha0 = __expf(m0 - ms0), alpha1 = __expf(m1 - ms1);
            m0 = m0n; m1 = m1n;
#pragma unroll
            for (int j = 0; j < 8; j++) {
                acc[j][0] *= alpha0; acc[j][1] *= alpha0;
                acc[j][2] *= alpha1; acc[j][3] *= alpha1;
            }

            // ---- P = exp(S) fused with O += P V ----
            float ps0 = 0.f, ps1 = 0.f;
#pragma unroll
            for (int kk = 0; kk < 4; kk++) {
                int j0 = 2 * kk, j1 = 2 * kk + 1;
                float p00 = __expf(s[j0][0] - ms0), p01 = __expf(s[j0][1] - ms0);
                float p02 = __expf(s[j0][2] - ms1), p03 = __expf(s[j0][3] - ms1);
                float p10 = __expf(s[j1][0] - ms0), p11 = __expf(s[j1][1] - ms0);
                float p12 = __expf(s[j1][2] - ms1), p13 = __expf(s[j1][3] - ms1);
                ps0 += p00 + p01 + p10 + p11;
                ps1 += p02 + p03 + p12 + p13;
                uint32_t pah[4], pal[4];
                pah[0] = pack_bf16(p00, p01);
                pah[1] = pack_bf16(p02, p03);
                pah[2] = pack_bf16(p10, p11);
                pah[3] = pack_bf16(p12, p13);
                pal[0] = pack_bf16(p00 - bf16_hi_f(p00), p01 - bf16_hi_f(p01));
                pal[1] = pack_bf16(p02 - bf16_hi_f(p02), p03 - bf16_hi_f(p03));
                pal[2] = pack_bf16(p10 - bf16_hi_f(p10), p11 - bf16_hi_f(p11));
                pal[3] = pack_bf16(p12 - bf16_hi_f(p12), p13 - bf16_hi_f(p13));
#pragma unroll
                for (int jdp = 0; jdp < 4; jdp++) {
                    uint32_t voff = (uint32_t)((kk * 16 + kv) * QS + jdp * 16 + nv) * 2;
                    uint32_t rh[4], rl[4];
                    ldm_x4t(rh, uVh + voff);
                    ldm_x4t(rl, uVl + voff);
                    {
                        uint32_t b0[2] = { rh[0], rh[1] }, c0[2] = { rl[0], rl[1] };
                        mma_bf16(acc[2 * jdp], pah, b0);
                        mma_bf16(acc[2 * jdp], pal, b0);
                        mma_bf16(acc[2 * jdp], pah, c0);
                    }
                    {
                        uint32_t b1[2] = { rh[2], rh[3] }, c1[2] = { rl[2], rl[3] };
                        mma_bf16(acc[2 * jdp + 1], pah, b1);
                        mma_bf16(acc[2 * jdp + 1], pal, b1);
                        mma_bf16(acc[2 * jdp + 1], pah, c1);
                    }
                }
            }
            ps0 += __shfl_xor_sync(0xFFFFFFFFu, ps0, 1);
            ps0 += __shfl_xor_sync(0xFFFFFFFFu, ps0, 2);
            ps1 += __shfl_xor_sync(0xFFFFFFFFu, ps1, 1);
            ps1 += __shfl_xor_sync(0xFFFFFFFFu, ps1, 2);
            l0 = l0 * alpha0 + ps0;
            l1 = l1 * alpha1 + ps1;
        }
        __syncthreads();   // all warps done reading cur before it is overwritten
    }

    float inv0 = 1.f / l0, inv1 = 1.f / l1;
#pragma unroll
    for (int jd = 0; jd < 8; jd++) {
        int c = jd * 8 + t * 2;
        float* p0 = Op + qoff + (size_t)(rb + g) * EMB + c;
        float* p1 = Op + qoff + (size_t)(rb + g + 8) * EMB + c;
        float o00 = acc[jd][0] * inv0, o01 = acc[jd][1] * inv0;
        float o10 = acc[jd][2] * inv1, o11 = acc[jd][3] * inv1;
        if (OUT == 0) {
            *reinterpret_cast<float2*>(p0) = make_float2(o00, o01);
            *reinterpret_cast<float2*>(p1) = make_float2(o10, o11);
        } else {
            float2 e0 = *reinterpret_cast<float2*>(p0);
            float2 e1 = *reinterpret_cast<float2*>(p1);
            *reinterpret_cast<float2*>(p0) =
                make_float2(e0.x + fmaxf(o00, 0.f), e0.y + fmaxf(o01, 0.f));
            *reinterpret_cast<float2*>(p1) =
                make_float2(e1.x + fmaxf(o10, 0.f), e1.y + fmaxf(o11, 0.f));
        }
    }
}

// ---------------------------------------------------------------------------
__global__ __launch_bounds__(256) void out_proj_kernel(
    const float* __restrict__ out, const float* __restrict__ Wout,
    const float* __restrict__ bout, float* __restrict__ y)
{
    int g = blockIdx.x * 8 + (threadIdx.x >> 5);
    int lane = threadIdx.x & 31;
    const float4* o4 = reinterpret_cast<const float4*>(out + (size_t)g * EMB);
    const float4* w4 = reinterpret_cast<const float4*>(Wout);
    float s = 0.f;
#pragma unroll
    for (int i = 0; i < 4; i++) {
        float4 a = o4[lane + 32 * i];
        float4 b = w4[lane + 32 * i];
        s += a.x * b.x + a.y * b.y + a.z * b.z + a.w * b.w;
    }
#pragma unroll
    for (int off = 16; off > 0; off >>= 1)
        s += __shfl_xor_sync(0xFFFFFFFFu, s, off);
    if (lane == 0) y[g] = s + bout[0];
}

// ---------------------------------------------------------------------------
extern "C" void kernel_launch(void* const* d_in, const int* in_sizes, int n_in,
                              void* d_out, int out_size)
{
    const int*   item_inputs  = (const int*)d_in[0];
    const int*   skill_inputs = (const int*)d_in[1];
    const int*   label_inputs = (const int*)d_in[2];
    const int*   item_ids     = (const int*)d_in[3];
    const int*   skill_ids    = (const int*)d_in[4];
    const float* item_emb     = (const float*)d_in[5];
    const float* skill_emb    = (const float*)d_in[6];
    const float* W_in         = (const float*)d_in[7];
    const float* b_in         = (const float*)d_in[8];
    const float* Wq           = (const float*)d_in[9];
    const float* bq           = (const float*)d_in[10];
    const float* Wk           = (const float*)d_in[11];
    const float* bk           = (const float*)d_in[12];
    const float* Wv           = (const float*)d_in[13];
    const float* bv           = (const float*)d_in[14];
    const float* W_out        = (const float*)d_in[22];
    const float* b_out        = (const float*)d_in[23];
    float* y = (float*)d_out;

    float *inputs, *query, *x, *outb;
    __nv_bfloat16 *w, *qh, *ql, *kh, *kl, *vh, *vl;
    cudaGetSymbolAddress((void**)&inputs, g_inputs);
    cudaGetSymbolAddress((void**)&query,  g_query);
    cudaGetSymbolAddress((void**)&x,      g_x);
    cudaGetSymbolAddress((void**)&outb,   g_outb);
    cudaGetSymbolAddress((void**)&w,      g_W);
    cudaGetSymbolAddress((void**)&qh,     g_Qh);
    cudaGetSymbolAddress((void**)&ql,     g_Ql);
    cudaGetSymbolAddress((void**)&kh,     g_Kh);
    cudaGetSymbolAddress((void**)&kl,     g_Kl);
    cudaGetSymbolAddress((void**)&vh,     g_Vh);
    cudaGetSymbolAddress((void**)&vl,     g_Vl);

    cudaFuncSetAttribute(flash_bf16_kernel<0>,
                         cudaFuncAttributeMaxDynamicSharedMemorySize, FL_SMEM);
    cudaFuncSetAttribute(flash_bf16_kernel<1>,
                         cudaFuncAttributeMaxDynamicSharedMemorySize, FL_SMEM);
    cudaFuncSetAttribute(gemm_mlp_kernel,
                         cudaFuncAttributeMaxDynamicSharedMemorySize, GEMM_SMEM);
    cudaFuncSetAttribute(gemm_qkv_kernel,
                         cudaFuncAttributeMaxDynamicSharedMemorySize, GEMM_SMEM);

    __nv_bfloat16* win_hi = w;
    __nv_bfloat16* win_lo = w + 512 * 1024;
    __nv_bfloat16* qkv_hi[2][3];
    __nv_bfloat16* qkv_lo[2][3];
    {
        __nv_bfloat16* p = w + 2 * 512 * 1024;
        for (int l = 0; l < 2; l++)
            for (int m = 0; m < 3; m++) {
                qkv_hi[l][m] = p; p += 512 * 512;
                qkv_lo[l][m] = p; p += 512 * 512;
            }
    }

    // 0: gather
    gather_kernel<<<TOT, 128>>>(item_inputs, skill_inputs, label_inputs,
                                item_ids, skill_ids, item_emb, skill_emb,
                                inputs, query);
    // 1: W_in transpose
    transpose_cvt_kernel<<<dim3(16, 32), 256>>>(W_in, win_hi, win_lo, 1024, 512);
    // 2: batched qkv transposes
    {
        TrArgs ta;
        const float* srcs[3] = { Wq, Wk, Wv };
        for (int l = 0; l < 2; l++)
            for (int m = 0; m < 3; m++) {
                ta.src[l * 3 + m] = srcs[m] + (size_t)l * 512 * 512;
                ta.dhi[l * 3 + m] = qkv_hi[l][m];
                ta.dlo[l * 3 + m] = qkv_lo[l][m];
            }
        transpose_qkv_kernel<<<dim3(16, 16, 6), 256>>>(ta);
    }
    // 3: MLP
    gemm_mlp_kernel<<<dim3(4, 128), 256, GEMM_SMEM>>>(
        inputs, win_hi, win_lo, b_in, x, 1024);

    for (int l = 0; l < 2; l++) {
        const float* src = (l == 0) ? x : outb;
        QKVArgs qa;
        qa.A[0] = query; qa.A[1] = src; qa.A[2] = src;
        qa.Bh[0] = qkv_hi[l][0]; qa.Bh[1] = qkv_hi[l][1]; qa.Bh[2] = qkv_hi[l][2];
        qa.Bl[0] = qkv_lo[l][0]; qa.Bl[1] = qkv_lo[l][1]; qa.Bl[2] = qkv_lo[l][2];
        qa.bias[0] = bq + l * EMB; qa.bias[1] = bk + l * EMB; qa.bias[2] = bv + l * EMB;
        qa.Ch[0] = qh; qa.Ch[1] = kh; qa.Ch[2] = vh;
        qa.Cl[0] = ql; qa.Cl[1] = kl; qa.Cl[2] = vl;
        // 4 / 6: fused QKV
        gemm_qkv_kernel<<<dim3(4, 128, 3), 256, GEMM_SMEM>>>(qa);
        // 5 / 7: flash
        if (l == 0)
            flash_bf16_kernel<0><<<dim3(SEQ / 128, NH, Bsz), 256, FL_SMEM>>>(
                qh, ql, kh, kl, vh, vl, outb);
        else
            flash_bf16_kernel<1><<<dim3(SEQ / 128, NH, Bsz), 256, FL_SMEM>>>(
                qh, ql, kh, kl, vh, vl, outb);
    }

    // 8: output projection
    out_proj_kernel<<<TOT / 8, 256>>>(outb, W_out, b_out, y);
}

// round 7
// speedup vs baseline: 3.0993x; 1.0115x over previous
#include <cuda_runtime.h>
#include <cuda_bf16.h>
#include <cstdint>

// ---------------------------------------------------------------------------
// TSAKT: gather -> ReLU MLP -> 2x causal MHA -> output proj.
// glo/ts biases are key-constant pre-mask => softmax-shift-invariant => dropped.
// R7: whole net bf16 hi/lo plane-resident; GEMM operands 100% cp.async;
//     Q2 folded into layer-1 fused GEMM launch.
// ---------------------------------------------------------------------------

#define Bsz 32
#define SEQ 512
#define EMB 512
#define NH  8
#define DHD 64
#define TOT (Bsz * SEQ)
#define ATTN_SCALE 0.125f

// ---- device scratch ---------------------------------------------------------
__device__ float g_outb [(size_t)TOT * EMB];
__device__ __nv_bfloat16 g_W[2 * 512 * 1024 + 12 * 512 * 512];
__device__ __nv_bfloat16 g_Ih[(size_t)TOT * 1024], g_Il[(size_t)TOT * 1024];
__device__ __nv_bfloat16 g_QRh[(size_t)TOT * EMB], g_QRl[(size_t)TOT * EMB];
__device__ __nv_bfloat16 g_Xh[(size_t)TOT * EMB],  g_Xl[(size_t)TOT * EMB];
__device__ __nv_bfloat16 g_Oh[(size_t)TOT * EMB],  g_Ol[(size_t)TOT * EMB];
__device__ __nv_bfloat16 g_Q1h[(size_t)TOT * EMB], g_Q1l[(size_t)TOT * EMB];
__device__ __nv_bfloat16 g_Q2h[(size_t)TOT * EMB], g_Q2l[(size_t)TOT * EMB];
__device__ __nv_bfloat16 g_Kh[(size_t)TOT * EMB],  g_Kl[(size_t)TOT * EMB];
__device__ __nv_bfloat16 g_Vh[(size_t)TOT * EMB],  g_Vl[(size_t)TOT * EMB];

// ---------------------------------------------------------------------------
__device__ __forceinline__ uint32_t pack_bf16(float x, float y) {
    __nv_bfloat162 h = __floats2bfloat162_rn(x, y);
    return *reinterpret_cast<uint32_t*>(&h);
}
__device__ __forceinline__ float bf16_hi_f(float x) {
    return __bfloat162float(__float2bfloat16_rn(x));
}
__device__ __forceinline__ void mma_bf16(float* c, const uint32_t* a, const uint32_t* b) {
    asm volatile(
        "mma.sync.aligned.m16n8k16.row.col.f32.bf16.bf16.f32 "
        "{%0,%1,%2,%3}, {%4,%5,%6,%7}, {%8,%9}, {%0,%1,%2,%3};"
        : "+f"(c[0]), "+f"(c[1]), "+f"(c[2]), "+f"(c[3])
        : "r"(a[0]), "r"(a[1]), "r"(a[2]), "r"(a[3]), "r"(b[0]), "r"(b[1]));
}
__device__ __forceinline__ void ldm_x4(uint32_t* r, uint32_t a) {
    asm volatile("ldmatrix.sync.aligned.m8n8.x4.shared.b16 {%0,%1,%2,%3}, [%4];"
        : "=r"(r[0]), "=r"(r[1]), "=r"(r[2]), "=r"(r[3]) : "r"(a));
}
__device__ __forceinline__ void ldm_x4t(uint32_t* r, uint32_t a) {
    asm volatile("ldmatrix.sync.aligned.m8n8.x4.trans.shared.b16 {%0,%1,%2,%3}, [%4];"
        : "=r"(r[0]), "=r"(r[1]), "=r"(r[2]), "=r"(r[3]) : "r"(a));
}
__device__ __forceinline__ uint32_t smaddr(const void* p) {
    return (uint32_t)__cvta_generic_to_shared(p);
}
#define CPA16(dst, src) \
    asm volatile("cp.async.cg.shared.global [%0], [%1], 16;" :: "r"(dst), "l"(src))
#define CPA_COMMIT() asm volatile("cp.async.commit_group;")
#define CPA_WAIT(n)  asm volatile("cp.async.wait_group %0;" :: "n"(n))

__device__ __forceinline__ void cvt_store4(float4 v, __nv_bfloat16* hi, __nv_bfloat16* lo) {
    float hx = bf16_hi_f(v.x), hy = bf16_hi_f(v.y);
    float hz = bf16_hi_f(v.z), hw = bf16_hi_f(v.w);
    *reinterpret_cast<uint2*>(hi) = make_uint2(pack_bf16(v.x, v.y), pack_bf16(v.z, v.w));
    *reinterpret_cast<uint2*>(lo) = make_uint2(pack_bf16(v.x - hx, v.y - hy),
                                               pack_bf16(v.z - hz, v.w - hw));
}

// ---------------------------------------------------------------------------
// Gather: emits inputs planes [g,1024] and query planes [g,512]
// ---------------------------------------------------------------------------
__global__ __launch_bounds__(128) void gather_kernel(
    const int* __restrict__ item_inputs, const int* __restrict__ skill_inputs,
    const int* __restrict__ label_inputs,
    const int* __restrict__ item_ids, const int* __restrict__ skill_ids,
    const float* __restrict__ item_emb, const float* __restrict__ skill_emb,
    __nv_bfloat16* __restrict__ Ih, __nv_bfloat16* __restrict__ Il,
    __nv_bfloat16* __restrict__ QRh, __nv_bfloat16* __restrict__ QRl)
{
    int g = blockIdx.x;
    int t = threadIdx.x;
    float lab = (float)label_inputs[g];
    float nlab = 1.0f - lab;
    size_t ib = (size_t)g * 1024, qb = (size_t)g * 512;
    if (t < 64) {
        const float4* ie = reinterpret_cast<const float4*>(item_emb + (size_t)item_inputs[g] * 256);
        float4 v = ie[t];
        float4 a = make_float4(v.x * lab, v.y * lab, v.z * lab, v.w * lab);
        float4 c = make_float4(v.x * nlab, v.y * nlab, v.z * nlab, v.w * nlab);
        cvt_store4(a, Ih + ib + t * 4, Il + ib + t * 4);
        cvt_store4(c, Ih + ib + 512 + t * 4, Il + ib + 512 + t * 4);
        const float4* qe = reinterpret_cast<const float4*>(item_emb + (size_t)item_ids[g] * 256);
        cvt_store4(qe[t], QRh + qb + t * 4, QRl + qb + t * 4);
    } else {
        int u = t - 64;
        const float4* se = reinterpret_cast<const float4*>(skill_emb + (size_t)skill_inputs[g] * 256);
        float4 v = se[u];
        float4 a = make_float4(v.x * lab, v.y * lab, v.z * lab, v.w * lab);
        float4 c = make_float4(v.x * nlab, v.y * nlab, v.z * nlab, v.w * nlab);
        cvt_store4(a, Ih + ib + 256 + u * 4, Il + ib + 256 + u * 4);
        cvt_store4(c, Ih + ib + 512 + 256 + u * 4, Il + ib + 512 + 256 + u * 4);
        const float4* qs = reinterpret_cast<const float4*>(skill_emb + (size_t)skill_ids[g] * 256);
        cvt_store4(qs[u], QRh + qb + 256 + u * 4, QRl + qb + 256 + u * 4);
    }
}

// ---------------------------------------------------------------------------
// Weight transposes (+ bf16 hi/lo split)
// ---------------------------------------------------------------------------
__global__ __launch_bounds__(256) void transpose_cvt_kernel(
    const float* __restrict__ src, __nv_bfloat16* __restrict__ dhi,
    __nv_bfloat16* __restrict__ dlo, int K, int N)
{
    __shared__ float t[32][33];
    int bx = blockIdx.x * 32, by = blockIdx.y * 32;
    int x = threadIdx.x & 31, y0 = threadIdx.x >> 5;
#pragma unroll
    for (int j = 0; j < 32; j += 8)
        t[y0 + j][x] = src[(size_t)(by + y0 + j) * N + bx + x];
    __syncthreads();
#pragma unroll
    for (int j = 0; j < 32; j += 8) {
        float v = t[x][y0 + j];
        float h = bf16_hi_f(v);
        size_t idx = (size_t)(bx + y0 + j) * K + by + x;
        dhi[idx] = __float2bfloat16_rn(v);
        dlo[idx] = __float2bfloat16_rn(v - h);
    }
}

struct TrArgs {
    const float* src[6];
    __nv_bfloat16* dhi[6];
    __nv_bfloat16* dlo[6];
};
__global__ __launch_bounds__(256) void transpose_qkv_kernel(TrArgs a)
{
    __shared__ float t[32][33];
    int z = blockIdx.z;
    const float* src = a.src[z];
    __nv_bfloat16* dhi = a.dhi[z];
    __nv_bfloat16* dlo = a.dlo[z];
    int bx = blockIdx.x * 32, by = blockIdx.y * 32;
    int x = threadIdx.x & 31, y0 = threadIdx.x >> 5;
#pragma unroll
    for (int j = 0; j < 32; j += 8)
        t[y0 + j][x] = src[(size_t)(by + y0 + j) * 512 + bx + x];
    __syncthreads();
#pragma unroll
    for (int j = 0; j < 32; j += 8) {
        float v = t[x][y0 + j];
        float h = bf16_hi_f(v);
        size_t idx = (size_t)(bx + y0 + j) * 512 + by + x;
        dhi[idx] = __float2bfloat16_rn(v);
        dlo[idx] = __float2bfloat16_rn(v - h);
    }
}

// ---------------------------------------------------------------------------
// GEMM: all operands bf16 hi/lo planes, 100% cp.async loads.
// C = act(A @ Bt^T + bias). 128x128 tile, 8 warps, K-chunk 32, double buffer.
// ---------------------------------------------------------------------------
#define RSTR 40
#define PLANE_B (128 * RSTR * 2)
#define STAGE_B (4 * PLANE_B)
#define GEMM_SMEM (2 * STAGE_B)

// stage layout: [Ahi | Alo | Bhi | Blo]
__device__ __forceinline__ void gemm_load_stage(
    uint32_t st, const __nv_bfloat16* Ah, const __nv_bfloat16* Al,
    const __nv_bfloat16* Bh, const __nv_bfloat16* Bl,
    int bm, int bn, int k0, int K, const int* fr, const int* fc)
{
#pragma unroll
    for (int i = 0; i < 2; i++) {
        uint32_t doff = (uint32_t)(fr[i] * RSTR + fc[i]) * 2;
        size_t ga = (size_t)(bm + fr[i]) * K + k0 + fc[i];
        size_t gb = (size_t)(bn + fr[i]) * K + k0 + fc[i];
        CPA16(st + doff, Ah + ga);
        CPA16(st + PLANE_B + doff, Al + ga);
        CPA16(st + 2 * PLANE_B + doff, Bh + gb);
        CPA16(st + 3 * PLANE_B + doff, Bl + gb);
    }
    CPA_COMMIT();
}

__device__ __forceinline__ void gemm_compute_chunk(
    uint32_t cur, float acc[4][4][4], int wm, int wn,
    int lm, int kq, int nb, int kb2)
{
    uint32_t ahi_u = cur;
    uint32_t bhi_u = cur + 2 * PLANE_B;
#pragma unroll
    for (int s = 0; s < 2; s++) {
        uint32_t bh[4][2], bl[4][2];
#pragma unroll
        for (int jp = 0; jp < 2; jp++) {
            uint32_t off = (uint32_t)((wn + jp * 16 + nb) * RSTR + s * 16 + kb2) * 2;
            uint32_t r[4];
            ldm_x4(r, bhi_u + off);
            bh[jp * 2][0] = r[0]; bh[jp * 2][1] = r[1];
            bh[jp * 2 + 1][0] = r[2]; bh[jp * 2 + 1][1] = r[3];
            ldm_x4(r, bhi_u + PLANE_B + off);
            bl[jp * 2][0] = r[0]; bl[jp * 2][1] = r[1];
            bl[jp * 2 + 1][0] = r[2]; bl[jp * 2 + 1][1] = r[3];
        }
#pragma unroll
        for (int i = 0; i < 4; i++) {
            uint32_t off = (uint32_t)((wm + i * 16 + lm) * RSTR + s * 16 + kq) * 2;
            uint32_t ah[4], al[4];
            ldm_x4(ah, ahi_u + off);
            ldm_x4(al, ahi_u + PLANE_B + off);
#pragma unroll
            for (int j = 0; j < 4; j++) {
                mma_bf16(acc[i][j], ah, bh[j]);
                mma_bf16(acc[i][j], al, bh[j]);
                mma_bf16(acc[i][j], ah, bl[j]);
            }
        }
    }
}

// MLP: f32 relu output is replaced by plane output consumed by next GEMMs.
__global__ __launch_bounds__(256, 2)
void gemm_mlp_kernel(const __nv_bfloat16* __restrict__ Ah,
                     const __nv_bfloat16* __restrict__ Al,
                     const __nv_bfloat16* __restrict__ Bthi,
                     const __nv_bfloat16* __restrict__ Btlo,
                     const float* __restrict__ bias,
                     __nv_bfloat16* __restrict__ Xh,
                     __nv_bfloat16* __restrict__ Xl, int K)
{
    extern __shared__ __align__(16) char dsm[];
    int tid = threadIdx.x;
    int wid = tid >> 5, lane = tid & 31;
    int g = lane >> 2, t = lane & 3;
    int bm = blockIdx.y * 128, bn = blockIdx.x * 128;
    int wm = (wid & 1) * 64, wn = (wid >> 1) * 32;
    int NC = K >> 5;
    int lm = lane & 15, kq = (lane >> 4) << 3;
    int nb = (lane & 7) + ((lane >> 4) << 3);
    int kb2 = ((lane >> 3) & 1) * 8;

    int fr[2], fc[2];
#pragma unroll
    for (int i = 0; i < 2; i++) { int f = tid + i * 256; fr[i] = f >> 2; fc[i] = (f & 3) * 8; }

    float acc[4][4][4];
#pragma unroll
    for (int i = 0; i < 4; i++)
#pragma unroll
        for (int j = 0; j < 4; j++)
#pragma unroll
            for (int r = 0; r < 4; r++) acc[i][j][r] = 0.f;

    gemm_load_stage(smaddr(dsm), Ah, Al, Bthi, Btlo, bm, bn, 0, K, fr, fc);
    CPA_WAIT(0);
    __syncthreads();

    for (int chunk = 0; chunk < NC; chunk++) {
        uint32_t cur = smaddr(dsm) + (chunk & 1) * STAGE_B;
        bool more = (chunk + 1 < NC);
        if (more)
            gemm_load_stage(smaddr(dsm) + ((chunk + 1) & 1) * STAGE_B,
                            Ah, Al, Bthi, Btlo, bm, bn, (chunk + 1) << 5, K, fr, fc);
        gemm_compute_chunk(cur, acc, wm, wn, lm, kq, nb, kb2);
        if (more) { CPA_WAIT(0); }
        __syncthreads();
    }

#pragma unroll
    for (int i = 0; i < 4; i++) {
        int row0 = bm + wm + i * 16 + g;
#pragma unroll
        for (int j = 0; j < 4; j++) {
            int col = bn + wn + j * 8 + t * 2;
            float2 bv = *reinterpret_cast<const float2*>(bias + col);
            float v0 = fmaxf(acc[i][j][0] + bv.x, 0.f);
            float v1 = fmaxf(acc[i][j][1] + bv.y, 0.f);
            float v2 = fmaxf(acc[i][j][2] + bv.x, 0.f);
            float v3 = fmaxf(acc[i][j][3] + bv.y, 0.f);
            size_t i0 = (size_t)row0 * 512 + col;
            size_t i1 = (size_t)(row0 + 8) * 512 + col;
            *reinterpret_cast<uint32_t*>(Xh + i0) = pack_bf16(v0, v1);
            *reinterpret_cast<uint32_t*>(Xl + i0) =
                pack_bf16(v0 - bf16_hi_f(v0), v1 - bf16_hi_f(v1));
            *reinterpret_cast<uint32_t*>(Xh + i1) = pack_bf16(v2, v3);
            *reinterpret_cast<uint32_t*>(Xl + i1) =
                pack_bf16(v2 - bf16_hi_f(v2), v3 - bf16_hi_f(v3));
        }
    }
}

// Fused projections: z selects (A planes, weights, bias, output planes). K=512.
struct QKVArgs {
    const __nv_bfloat16* Ah[4];
    const __nv_bfloat16* Al[4];
    const __nv_bfloat16* Bh[4];
    const __nv_bfloat16* Bl[4];
    const float* bias[4];
    __nv_bfloat16* Ch[4];
    __nv_bfloat16* Cl[4];
};
__global__ __launch_bounds__(256, 2)
void gemm_qkv_kernel(QKVArgs args)
{
    extern __shared__ __align__(16) char dsm[];
    const int K = 512;
    int z = blockIdx.z;
    const __nv_bfloat16* Ah = args.Ah[z];
    const __nv_bfloat16* Al = args.Al[z];
    const __nv_bfloat16* Bthi = args.Bh[z];
    const __nv_bfloat16* Btlo = args.Bl[z];
    const float* bias = args.bias[z];
    __nv_bfloat16* Chi = args.Ch[z];
    __nv_bfloat16* Clo = args.Cl[z];

    int tid = threadIdx.x;
    int wid = tid >> 5, lane = tid & 31;
    int g = lane >> 2, t = lane & 3;
    int bm = blockIdx.y * 128, bn = blockIdx.x * 128;
    int wm = (wid & 1) * 64, wn = (wid >> 1) * 32;
    const int NC = 16;
    int lm = lane & 15, kq = (lane >> 4) << 3;
    int nb = (lane & 7) + ((lane >> 4) << 3);
    int kb2 = ((lane >> 3) & 1) * 8;

    int fr[2], fc[2];
#pragma unroll
    for (int i = 0; i < 2; i++) { int f = tid + i * 256; fr[i] = f >> 2; fc[i] = (f & 3) * 8; }

    float acc[4][4][4];
#pragma unroll
    for (int i = 0; i < 4; i++)
#pragma unroll
        for (int j = 0; j < 4; j++)
#pragma unroll
            for (int r = 0; r < 4; r++) acc[i][j][r] = 0.f;

    gemm_load_stage(smaddr(dsm), Ah, Al, Bthi, Btlo, bm, bn, 0, K, fr, fc);
    CPA_WAIT(0);
    __syncthreads();

    for (int chunk = 0; chunk < NC; chunk++) {
        uint32_t cur = smaddr(dsm) + (chunk & 1) * STAGE_B;
        bool more = (chunk + 1 < NC);
        if (more)
            gemm_load_stage(smaddr(dsm) + ((chunk + 1) & 1) * STAGE_B,
                            Ah, Al, Bthi, Btlo, bm, bn, (chunk + 1) << 5, K, fr, fc);
        gemm_compute_chunk(cur, acc, wm, wn, lm, kq, nb, kb2);
        if (more) { CPA_WAIT(0); }
        __syncthreads();
    }

#pragma unroll
    for (int i = 0; i < 4; i++) {
        int row0 = bm + wm + i * 16 + g;
#pragma unroll
        for (int j = 0; j < 4; j++) {
            int col = bn + wn + j * 8 + t * 2;
            float2 bv = *reinterpret_cast<const float2*>(bias + col);
            float v0 = acc[i][j][0] + bv.x, v1 = acc[i][j][1] + bv.y;
            float v2 = acc[i][j][2] + bv.x, v3 = acc[i][j][3] + bv.y;
            size_t i0 = (size_t)row0 * 512 + col;
            size_t i1 = (size_t)(row0 + 8) * 512 + col;
            *reinterpret_cast<uint32_t*>(Chi + i0) = pack_bf16(v0, v1);
            *reinterpret_cast<uint32_t*>(Clo + i0) =
                pack_bf16(v0 - bf16_hi_f(v0), v1 - bf16_hi_f(v1));
            *reinterpret_cast<uint32_t*>(Chi + i1) = pack_bf16(v2, v3);
            *reinterpret_cast<uint32_t*>(Clo + i1) =
                pack_bf16(v2 - bf16_hi_f(v2), v3 - bf16_hi_f(v3));
        }
    }
}

// ---------------------------------------------------------------------------
// Flash attention: cp.async double-buffered K/V stages, Q frags in registers.
// OUT=0: write f32 Op and bf16 planes (Ohp/Olp). OUT=1: Op += relu(result).
// ---------------------------------------------------------------------------
#define QS 72
#define FPL (64 * QS)
#define FSTG_B (4 * FPL * 2)
#define FL_SMEM (2 * FSTG_B)

template<int OUT>
__global__ __launch_bounds__(256, 2) void flash_bf16_kernel(
    const __nv_bfloat16* __restrict__ Qh, const __nv_bfloat16* __restrict__ Ql,
    const __nv_bfloat16* __restrict__ Kh, const __nv_bfloat16* __restrict__ Kl,
    const __nv_bfloat16* __restrict__ Vh, const __nv_bfloat16* __restrict__ Vl,
    float* __restrict__ Op,
    __nv_bfloat16* __restrict__ Ohp, __nv_bfloat16* __restrict__ Olp)
{
    extern __shared__ __align__(16) char fsm[];

    int tid = threadIdx.x;
    int wid = tid >> 5, lane = tid & 31;
    int g = lane >> 2, t = lane & 3;
    int qt = (SEQ / 128 - 1) - blockIdx.x;
    int h = blockIdx.y, b = blockIdx.z;
    size_t qoff = ((size_t)(b * SEQ + qt * 128)) * EMB + h * DHD;
    size_t kvoff = ((size_t)b * SEQ) * EMB + h * DHD;

    int rb = wid * 16;
    int lm = lane & 15, kq = (lane >> 4) << 3;
    int nbk = (lane & 7) + ((lane >> 4) << 3);
    int kb2 = ((lane >> 3) & 1) * 8;
    int kv = (lane & 7) + ((lane >> 3) & 1) * 8;
    int nv = (lane >> 4) << 3;

    uint32_t qah[4][4], qal[4][4];
    {
        __nv_bfloat16* sQh = reinterpret_cast<__nv_bfloat16*>(fsm);
        __nv_bfloat16* sQl = sQh + 128 * QS;
#pragma unroll
        for (int i = 0; i < 4; i++) {
            int f = tid + i * 256;
            int r = f >> 3, c = (f & 7) * 8;
            *reinterpret_cast<uint4*>(sQh + r * QS + c) =
                *reinterpret_cast<const uint4*>(Qh + qoff + (size_t)r * EMB + c);
            *reinterpret_cast<uint4*>(sQl + r * QS + c) =
                *reinterpret_cast<const uint4*>(Ql + qoff + (size_t)r * EMB + c);
        }
        __syncthreads();
        uint32_t uQh = smaddr(sQh), uQl = smaddr(sQl);
#pragma unroll
        for (int kk = 0; kk < 4; kk++) {
            uint32_t qo = (uint32_t)((rb + lm) * QS + kk * 16 + kq) * 2;
            ldm_x4(qah[kk], uQh + qo);
            ldm_x4(qal[kk], uQl + qo);
        }
        __syncthreads();
    }

    int ktmax = qt * 2 + 1;
    int wmaxrow = qt * 128 + rb + 15;
    int row0g = qt * 128 + rb + g, row1g = row0g + 8;

    int fr[2], fc[2];
#pragma unroll
    for (int i = 0; i < 2; i++) {
        int f = tid + i * 256;
        fr[i] = f >> 3; fc[i] = (f & 7) * 8;
    }

    {
        uint32_t st = smaddr(fsm);
#pragma unroll
        for (int i = 0; i < 2; i++) {
            uint32_t doff = (uint32_t)(fr[i] * QS + fc[i]) * 2;
            size_t go = kvoff + (size_t)fr[i] * EMB + fc[i];
            CPA16(st + doff, Kh + go);
            CPA16(st + FPL * 2 + doff, Kl + go);
            CPA16(st + 2 * FPL * 2 + doff, Vh + go);
            CPA16(st + 3 * FPL * 2 + doff, Vl + go);
        }
        CPA_COMMIT();
    }

    float m0 = -INFINITY, m1 = -INFINITY, l0 = 0.f, l1 = 0.f;
    float acc[8][4];
#pragma unroll
    for (int j = 0; j < 8; j++)
#pragma unroll
        for (int r = 0; r < 4; r++) acc[j][r] = 0.f;

    for (int kt = 0; kt <= ktmax; kt++) {
        uint32_t cur = smaddr(fsm) + (kt & 1) * FSTG_B;
        bool more = (kt < ktmax);
        if (more) {
            uint32_t nxt = smaddr(fsm) + ((kt + 1) & 1) * FSTG_B;
            size_t ko = kvoff + (size_t)(kt + 1) * 64 * EMB;
#pragma unroll
            for (int i = 0; i < 2; i++) {
                uint32_t doff = (uint32_t)(fr[i] * QS + fc[i]) * 2;
                size_t go = ko + (size_t)fr[i] * EMB + fc[i];
                CPA16(nxt + doff, Kh + go);
                CPA16(nxt + FPL * 2 + doff, Kl + go);
                CPA16(nxt + 2 * FPL * 2 + doff, Vh + go);
                CPA16(nxt + 3 * FPL * 2 + doff, Vl + go);
            }
            CPA_COMMIT();
            CPA_WAIT(1);
        } else {
            CPA_WAIT(0);
        }
        __syncthreads();

        if (kt * 64 <= wmaxrow) {
            uint32_t uKh = cur, uKl = cur + FPL * 2;
            uint32_t uVh = cur + 2 * FPL * 2, uVl = cur + 3 * FPL * 2;

            float s[8][4];
#pragma unroll
            for (int j = 0; j < 8; j++)
#pragma unroll
                for (int r = 0; r < 4; r++) s[j][r] = 0.f;
#pragma unroll
            for (int kk = 0; kk < 4; kk++) {
#pragma unroll
                for (int jp = 0; jp < 4; jp++) {
                    uint32_t koff = (uint32_t)((jp * 16 + nbk) * QS + kk * 16 + kb2) * 2;
                    uint32_t rh[4], rl[4];
                    ldm_x4(rh, uKh + koff);
                    ldm_x4(rl, uKl + koff);
                    {
                        uint32_t b0[2] = { rh[0], rh[1] }, c0[2] = { rl[0], rl[1] };
                        mma_bf16(s[2 * jp], qah[kk], b0);
                        mma_bf16(s[2 * jp], qal[kk], b0);
                        mma_bf16(s[2 * jp], qah[kk], c0);
                    }
                    {
                        uint32_t b1[2] = { rh[2], rh[3] }, c1[2] = { rl[2], rl[3] };
                        mma_bf16(s[2 * jp + 1], qah[kk], b1);
                        mma_bf16(s[2 * jp + 1], qal[kk], b1);
                        mma_bf16(s[2 * jp + 1], qah[kk], c1);
                    }
                }
            }

            int colb = kt * 64 + t * 2;
#pragma unroll
            for (int j = 0; j < 8; j++) {
                int c0 = colb + j * 8, c1 = c0 + 1;
                s[j][0] = (c0 > row0g) ? -INFINITY : s[j][0] * ATTN_SCALE;
                s[j][1] = (c1 > row0g) ? -INFINITY : s[j][1] * ATTN_SCALE;
                s[j][2] = (c0 > row1g) ? -INFINITY : s[j][2] * ATTN_SCALE;
                s[j][3] = (c1 > row1g) ? -INFINITY : s[j][3] * ATTN_SCALE;
            }

            float tm0 = -INFINITY, tm1 = -INFINITY;
#pragma unroll
            for (int j = 0; j < 8; j++) {
                tm0 = fmaxf(tm0, fmaxf(s[j][0], s[j][1]));
                tm1 = fmaxf(tm1, fmaxf(s[j][2], s[j][3]));
            }
            tm0 = fmaxf(tm0, __shfl_xor_sync(0xFFFFFFFFu, tm0, 1));
            tm0 = fmaxf(tm0, __shfl_xor_sync(0xFFFFFFFFu, tm0, 2));
            tm1 = fmaxf(tm1, __shfl_xor_sync(0xFFFFFFFFu, tm1, 1));
            tm1 = fmaxf(tm1, __shfl_xor_sync(0xFFFFFFFFu, tm1, 2));
            float m0n = fmaxf(m0, tm0), m1n = fmaxf(m1, tm1);
            float ms0 = fmaxf(m0n, -1e30f), ms1 = fmaxf(m1n, -1e30f);
            float alpha0 = __expf(m0 - ms0), alpha1 = __expf(m1 - ms1);
            m0 = m0n; m1 = m1n;
#pragma unroll
            for (int j = 0; j < 8; j++) {
                acc[j][0] *= alpha0; acc[j][1] *= alpha0;
                acc[j][2] *= alpha1; acc[j][3] *= alpha1;
            }

            float ps0 = 0.f, ps1 = 0.f;
#pragma unroll
            for (int kk = 0; kk < 4; kk++) {
                int j0 = 2 * kk, j1 = 2 * kk + 1;
                float p00 = __expf(s[j0][0] - ms0), p01 = __expf(s[j0][1] - ms0);
                float p02 = __expf(s[j0][2] - ms1), p03 = __expf(s[j0][3] - ms1);
                float p10 = __expf(s[j1][0] - ms0), p11 = __expf(s[j1][1] - ms0);
                float p12 = __expf(s[j1][2] - ms1), p13 = __expf(s[j1][3] - ms1);
                ps0 += p00 + p01 + p10 + p11;
                ps1 += p02 + p03 + p12 + p13;
                uint32_t pah[4], pal[4];
                pah[0] = pack_bf16(p00, p01);
                pah[1] = pack_bf16(p02, p03);
                pah[2] = pack_bf16(p10, p11);
                pah[3] = pack_bf16(p12, p13);
                pal[0] = pack_bf16(p00 - bf16_hi_f(p00), p01 - bf16_hi_f(p01));
                pal[1] = pack_bf16(p02 - bf16_hi_f(p02), p03 - bf16_hi_f(p03));
                pal[2] = pack_bf16(p10 - bf16_hi_f(p10), p11 - bf16_hi_f(p11));
                pal[3] = pack_bf16(p12 - bf16_hi_f(p12), p13 - bf16_hi_f(p13));
#pragma unroll
                for (int jdp = 0; jdp < 4; jdp++) {
                    uint32_t voff = (uint32_t)((kk * 16 + kv) * QS + jdp * 16 + nv) * 2;
                    uint32_t rh[4], rl[4];
                    ldm_x4t(rh, uVh + voff);
                    ldm_x4t(rl, uVl + voff);
                    {
                        uint32_t b0[2] = { rh[0], rh[1] }, c0[2] = { rl[0], rl[1] };
                        mma_bf16(acc[2 * jdp], pah, b0);
                        mma_bf16(acc[2 * jdp], pal, b0);
                        mma_bf16(acc[2 * jdp], pah, c0);
                    }
                    {
                        uint32_t b1[2] = { rh[2], rh[3] }, c1[2] = { rl[2], rl[3] };
                        mma_bf16(acc[2 * jdp + 1], pah, b1);
                        mma_bf16(acc[2 * jdp + 1], pal, b1);
                        mma_bf16(acc[2 * jdp + 1], pah, c1);
                    }
                }
            }
            ps0 += __shfl_xor_sync(0xFFFFFFFFu, ps0, 1);
            ps0 += __shfl_xor_sync(0xFFFFFFFFu, ps0, 2);
            ps1 += __shfl_xor_sync(0xFFFFFFFFu, ps1, 1);
            ps1 += __shfl_xor_sync(0xFFFFFFFFu, ps1, 2);
            l0 = l0 * alpha0 + ps0;
            l1 = l1 * alpha1 + ps1;
        }
        __syncthreads();
    }

    float inv0 = 1.f / l0, inv1 = 1.f / l1;
#pragma unroll
    for (int jd = 0; jd < 8; jd++) {
        int c = jd * 8 + t * 2;
        size_t i0 = qoff + (size_t)(rb + g) * EMB + c;
        size_t i1 = qoff + (size_t)(rb + g + 8) * EMB + c;
        float o00 = acc[jd][0] * inv0, o01 = acc[jd][1] * inv0;
        float o10 = acc[jd][2] * inv1, o11 = acc[jd][3] * inv1;
        if (OUT == 0) {
            *reinterpret_cast<float2*>(Op + i0) = make_float2(o00, o01);
            *reinterpret_cast<float2*>(Op + i1) = make_float2(o10, o11);
            *reinterpret_cast<uint32_t*>(Ohp + i0) = pack_bf16(o00, o01);
            *reinterpret_cast<uint32_t*>(Olp + i0) =
                pack_bf16(o00 - bf16_hi_f(o00), o01 - bf16_hi_f(o01));
            *reinterpret_cast<uint32_t*>(Ohp + i1) = pack_bf16(o10, o11);
            *reinterpret_cast<uint32_t*>(Olp + i1) =
                pack_bf16(o10 - bf16_hi_f(o10), o11 - bf16_hi_f(o11));
        } else {
            float2 e0 = *reinterpret_cast<float2*>(Op + i0);
            float2 e1 = *reinterpret_cast<float2*>(Op + i1);
            *reinterpret_cast<float2*>(Op + i0) =
                make_float2(e0.x + fmaxf(o00, 0.f), e0.y + fmaxf(o01, 0.f));
            *reinterpret_cast<float2*>(Op + i1) =
                make_float2(e1.x + fmaxf(o10, 0.f), e1.y + fmaxf(o11, 0.f));
        }
    }
}

// ---------------------------------------------------------------------------
__global__ __launch_bounds__(256) void out_proj_kernel(
    const float* __restrict__ out, const float* __restrict__ Wout,
    const float* __restrict__ bout, float* __restrict__ y)
{
    int g = blockIdx.x * 8 + (threadIdx.x >> 5);
    int lane = threadIdx.x & 31;
    const float4* o4 = reinterpret_cast<const float4*>(out + (size_t)g * EMB);
    const float4* w4 = reinterpret_cast<const float4*>(Wout);
    float s = 0.f;
#pragma unroll
    for (int i = 0; i < 4; i++) {
        float4 a = o4[lane + 32 * i];
        float4 b = w4[lane + 32 * i];
        s += a.x * b.x + a.y * b.y + a.z * b.z + a.w * b.w;
    }
#pragma unroll
    for (int off = 16; off > 0; off >>= 1)
        s += __shfl_xor_sync(0xFFFFFFFFu, s, off);
    if (lane == 0) y[g] = s + bout[0];
}

// ---------------------------------------------------------------------------
extern "C" void kernel_launch(void* const* d_in, const int* in_sizes, int n_in,
                              void* d_out, int out_size)
{
    const int*   item_inputs  = (const int*)d_in[0];
    const int*   skill_inputs = (const int*)d_in[1];
    const int*   label_inputs = (const int*)d_in[2];
    const int*   item_ids     = (const int*)d_in[3];
    const int*   skill_ids    = (const int*)d_in[4];
    const float* item_emb     = (const float*)d_in[5];
    const float* skill_emb    = (const float*)d_in[6];
    const float* W_in         = (const float*)d_in[7];
    const float* b_in         = (const float*)d_in[8];
    const float* Wq           = (const float*)d_in[9];
    const float* bq           = (const float*)d_in[10];
    const float* Wk           = (const float*)d_in[11];
    const float* bk           = (const float*)d_in[12];
    const float* Wv           = (const float*)d_in[13];
    const float* bv           = (const float*)d_in[14];
    const float* W_out        = (const float*)d_in[22];
    const float* b_out        = (const float*)d_in[23];
    float* y = (float*)d_out;

    float* outb;
    __nv_bfloat16 *w, *ih, *il, *qrh, *qrl, *xh, *xl, *oh, *ol;
    __nv_bfloat16 *q1h, *q1l, *q2h, *q2l, *kh, *kl, *vh, *vl;
    cudaGetSymbolAddress((void**)&outb, g_outb);
    cudaGetSymbolAddress((void**)&w,    g_W);
    cudaGetSymbolAddress((void**)&ih,   g_Ih);
    cudaGetSymbolAddress((void**)&il,   g_Il);
    cudaGetSymbolAddress((void**)&qrh,  g_QRh);
    cudaGetSymbolAddress((void**)&qrl,  g_QRl);
    cudaGetSymbolAddress((void**)&xh,   g_Xh);
    cudaGetSymbolAddress((void**)&xl,   g_Xl);
    cudaGetSymbolAddress((void**)&oh,   g_Oh);
    cudaGetSymbolAddress((void**)&ol,   g_Ol);
    cudaGetSymbolAddress((void**)&q1h,  g_Q1h);
    cudaGetSymbolAddress((void**)&q1l,  g_Q1l);
    cudaGetSymbolAddress((void**)&q2h,  g_Q2h);
    cudaGetSymbolAddress((void**)&q2l,  g_Q2l);
    cudaGetSymbolAddress((void**)&kh,   g_Kh);
    cudaGetSymbolAddress((void**)&kl,   g_Kl);
    cudaGetSymbolAddress((void**)&vh,   g_Vh);
    cudaGetSymbolAddress((void**)&vl,   g_Vl);

    cudaFuncSetAttribute(flash_bf16_kernel<0>,
                         cudaFuncAttributeMaxDynamicSharedMemorySize, FL_SMEM);
    cudaFuncSetAttribute(flash_bf16_kernel<1>,
                         cudaFuncAttributeMaxDynamicSharedMemorySize, FL_SMEM);
    cudaFuncSetAttribute(gemm_mlp_kernel,
                         cudaFuncAttributeMaxDynamicSharedMemorySize, GEMM_SMEM);
    cudaFuncSetAttribute(gemm_qkv_kernel,
                         cudaFuncAttributeMaxDynamicSharedMemorySize, GEMM_SMEM);

    __nv_bfloat16* win_hi = w;
    __nv_bfloat16* win_lo = w + 512 * 1024;
    __nv_bfloat16* qkv_hi[2][3];
    __nv_bfloat16* qkv_lo[2][3];
    {
        __nv_bfloat16* p = w + 2 * 512 * 1024;
        for (int l = 0; l < 2; l++)
            for (int m = 0; m < 3; m++) {
                qkv_hi[l][m] = p; p += 512 * 512;
                qkv_lo[l][m] = p; p += 512 * 512;
            }
    }

    // 0: gather (emit input+query planes)
    gather_kernel<<<TOT, 128>>>(item_inputs, skill_inputs, label_inputs,
                                item_ids, skill_ids, item_emb, skill_emb,
                                ih, il, qrh, qrl);
    // 1: W_in transpose
    transpose_cvt_kernel<<<dim3(16, 32), 256>>>(W_in, win_hi, win_lo, 1024, 512);
    // 2: batched qkv transposes
    {
        TrArgs ta;
        const float* srcs[3] = { Wq, Wk, Wv };
        for (int l = 0; l < 2; l++)
            for (int m = 0; m < 3; m++) {
                ta.src[l * 3 + m] = srcs[m] + (size_t)l * 512 * 512;
                ta.dhi[l * 3 + m] = qkv_hi[l][m];
                ta.dlo[l * 3 + m] = qkv_lo[l][m];
            }
        transpose_qkv_kernel<<<dim3(16, 16, 6), 256>>>(ta);
    }
    // 3: MLP -> x planes
    gemm_mlp_kernel<<<dim3(4, 128), 256, GEMM_SMEM>>>(
        ih, il, win_hi, win_lo, b_in, xh, xl, 1024);

    // 4: fused Q1,K1,V1,Q2
    {
        QKVArgs qa;
        qa.Ah[0] = qrh; qa.Al[0] = qrl;   // Q1
        qa.Ah[1] = xh;  qa.Al[1] = xl;    // K1
        qa.Ah[2] = xh;  qa.Al[2] = xl;    // V1
        qa.Ah[3] = qrh; qa.Al[3] = qrl;   // Q2
        qa.Bh[0] = qkv_hi[0][0]; qa.Bl[0] = qkv_lo[0][0];
        qa.Bh[1] = qkv_hi[0][1]; qa.Bl[1] = qkv_lo[0][1];
        qa.Bh[2] = qkv_hi[0][2]; qa.Bl[2] = qkv_lo[0][2];
        qa.Bh[3] = qkv_hi[1][0]; qa.Bl[3] = qkv_lo[1][0];
        qa.bias[0] = bq;       qa.bias[1] = bk;
        qa.bias[2] = bv;       qa.bias[3] = bq + EMB;
        qa.Ch[0] = q1h; qa.Cl[0] = q1l;
        qa.Ch[1] = kh;  qa.Cl[1] = kl;
        qa.Ch[2] = vh;  qa.Cl[2] = vl;
        qa.Ch[3] = q2h; qa.Cl[3] = q2l;
        gemm_qkv_kernel<<<dim3(4, 128, 4), 256, GEMM_SMEM>>>(qa);
    }
    // 5: flash layer 1 (f32 out + planes)
    flash_bf16_kernel<0><<<dim3(SEQ / 128, NH, Bsz), 256, FL_SMEM>>>(
        q1h, q1l, kh, kl, vh, vl, outb, oh, ol);
    // 6: fused K2,V2
    {
        QKVArgs qa;
        qa.Ah[0] = oh; qa.Al[0] = ol;
        qa.Ah[1] = oh; qa.Al[1] = ol;
        qa.Bh[0] = qkv_hi[1][1]; qa.Bl[0] = qkv_lo[1][1];
        qa.Bh[1] = qkv_hi[1][2]; qa.Bl[1] = qkv_lo[1][2];
        qa.bias[0] = bk + EMB; qa.bias[1] = bv + EMB;
        qa.Ch[0] = kh; qa.Cl[0] = kl;
        qa.Ch[1] = vh; qa.Cl[1] = vl;
        qa.Ah[2] = oh; qa.Al[2] = ol; qa.Bh[2] = qkv_hi[1][1]; qa.Bl[2] = qkv_lo[1][1];
        qa.bias[2] = bk + EMB; qa.Ch[2] = kh; qa.Cl[2] = kl;
        qa.Ah[3] = oh; qa.Al[3] = ol; qa.Bh[3] = qkv_hi[1][2]; qa.Bl[3] = qkv_lo[1][2];
        qa.bias[3] = bv + EMB; qa.Ch[3] = vh; qa.Cl[3] = vl;
        gemm_qkv_kernel<<<dim3(4, 128, 2), 256, GEMM_SMEM>>>(qa);
    }
    // 7: flash layer 2 (residual add)
    flash_bf16_kernel<1><<<dim3(SEQ / 128, NH, Bsz), 256, FL_SMEM>>>(
        q2h, q2l, kh, kl, vh, vl, outb, nullptr, nullptr);

    // 8: output projection
    out_proj_kernel<<<TOT / 8, 256>>>(outb, W_out, b_out, y);
}

// round 9
// speedup vs baseline: 3.1009x; 1.0005x over previous
#include <cuda_runtime.h>
#include <cuda_bf16.h>
#include <cstdint>

// ---------------------------------------------------------------------------
// TSAKT: gather -> ReLU MLP -> 2x causal MHA -> output proj.
// glo/ts biases are key-constant pre-mask => softmax-shift-invariant => dropped.
// R9: revert to bf16 3-product (R7, rel_err 1e-5); fix tensor-pipe RAW chains:
//     the 3 compensation MMAs per accumulator are now interleaved across
//     accumulators (dependency distance 4 in GEMM, 2 in flash).
// ---------------------------------------------------------------------------

#define Bsz 32
#define SEQ 512
#define EMB 512
#define NH  8
#define DHD 64
#define TOT (Bsz * SEQ)
#define ATTN_SCALE 0.125f

// ---- device scratch ---------------------------------------------------------
__device__ float g_outb [(size_t)TOT * EMB];
__device__ __nv_bfloat16 g_W[2 * 512 * 1024 + 12 * 512 * 512];
__device__ __nv_bfloat16 g_Ih[(size_t)TOT * 1024], g_Il[(size_t)TOT * 1024];
__device__ __nv_bfloat16 g_QRh[(size_t)TOT * EMB], g_QRl[(size_t)TOT * EMB];
__device__ __nv_bfloat16 g_Xh[(size_t)TOT * EMB],  g_Xl[(size_t)TOT * EMB];
__device__ __nv_bfloat16 g_Oh[(size_t)TOT * EMB],  g_Ol[(size_t)TOT * EMB];
__device__ __nv_bfloat16 g_Q1h[(size_t)TOT * EMB], g_Q1l[(size_t)TOT * EMB];
__device__ __nv_bfloat16 g_Q2h[(size_t)TOT * EMB], g_Q2l[(size_t)TOT * EMB];
__device__ __nv_bfloat16 g_Kh[(size_t)TOT * EMB],  g_Kl[(size_t)TOT * EMB];
__device__ __nv_bfloat16 g_Vh[(size_t)TOT * EMB],  g_Vl[(size_t)TOT * EMB];

// ---------------------------------------------------------------------------
__device__ __forceinline__ uint32_t pack_bf16(float x, float y) {
    __nv_bfloat162 h = __floats2bfloat162_rn(x, y);
    return *reinterpret_cast<uint32_t*>(&h);
}
__device__ __forceinline__ float bf16_hi_f(float x) {
    return __bfloat162float(__float2bfloat16_rn(x));
}
__device__ __forceinline__ void mma_bf16(float* c, const uint32_t* a, const uint32_t* b) {
    asm volatile(
        "mma.sync.aligned.m16n8k16.row.col.f32.bf16.bf16.f32 "
        "{%0,%1,%2,%3}, {%4,%5,%6,%7}, {%8,%9}, {%0,%1,%2,%3};"
        : "+f"(c[0]), "+f"(c[1]), "+f"(c[2]), "+f"(c[3])
        : "r"(a[0]), "r"(a[1]), "r"(a[2]), "r"(a[3]), "r"(b[0]), "r"(b[1]));
}
__device__ __forceinline__ void ldm_x4(uint32_t* r, uint32_t a) {
    asm volatile("ldmatrix.sync.aligned.m8n8.x4.shared.b16 {%0,%1,%2,%3}, [%4];"
        : "=r"(r[0]), "=r"(r[1]), "=r"(r[2]), "=r"(r[3]) : "r"(a));
}
__device__ __forceinline__ void ldm_x4t(uint32_t* r, uint32_t a) {
    asm volatile("ldmatrix.sync.aligned.m8n8.x4.trans.shared.b16 {%0,%1,%2,%3}, [%4];"
        : "=r"(r[0]), "=r"(r[1]), "=r"(r[2]), "=r"(r[3]) : "r"(a));
}
__device__ __forceinline__ uint32_t smaddr(const void* p) {
    return (uint32_t)__cvta_generic_to_shared(p);
}
#define CPA16(dst, src) \
    asm volatile("cp.async.cg.shared.global [%0], [%1], 16;" :: "r"(dst), "l"(src))
#define CPA_COMMIT() asm volatile("cp.async.commit_group;")
#define CPA_WAIT(n)  asm volatile("cp.async.wait_group %0;" :: "n"(n))

__device__ __forceinline__ void cvt_store4(float4 v, __nv_bfloat16* hi, __nv_bfloat16* lo) {
    float hx = bf16_hi_f(v.x), hy = bf16_hi_f(v.y);
    float hz = bf16_hi_f(v.z), hw = bf16_hi_f(v.w);
    *reinterpret_cast<uint2*>(hi) = make_uint2(pack_bf16(v.x, v.y), pack_bf16(v.z, v.w));
    *reinterpret_cast<uint2*>(lo) = make_uint2(pack_bf16(v.x - hx, v.y - hy),
                                               pack_bf16(v.z - hz, v.w - hw));
}

// ---------------------------------------------------------------------------
// Gather: emits inputs planes [g,1024] and query planes [g,512]
// ---------------------------------------------------------------------------
__global__ __launch_bounds__(128) void gather_kernel(
    const int* __restrict__ item_inputs, const int* __restrict__ skill_inputs,
    const int* __restrict__ label_inputs,
    const int* __restrict__ item_ids, const int* __restrict__ skill_ids,
    const float* __restrict__ item_emb, const float* __restrict__ skill_emb,
    __nv_bfloat16* __restrict__ Ih, __nv_bfloat16* __restrict__ Il,
    __nv_bfloat16* __restrict__ QRh, __nv_bfloat16* __restrict__ QRl)
{
    int g = blockIdx.x;
    int t = threadIdx.x;
    float lab = (float)label_inputs[g];
    float nlab = 1.0f - lab;
    size_t ib = (size_t)g * 1024, qb = (size_t)g * 512;
    if (t < 64) {
        const float4* ie = reinterpret_cast<const float4*>(item_emb + (size_t)item_inputs[g] * 256);
        float4 v = ie[t];
        float4 a = make_float4(v.x * lab, v.y * lab, v.z * lab, v.w * lab);
        float4 c = make_float4(v.x * nlab, v.y * nlab, v.z * nlab, v.w * nlab);
        cvt_store4(a, Ih + ib + t * 4, Il + ib + t * 4);
        cvt_store4(c, Ih + ib + 512 + t * 4, Il + ib + 512 + t * 4);
        const float4* qe = reinterpret_cast<const float4*>(item_emb + (size_t)item_ids[g] * 256);
        cvt_store4(qe[t], QRh + qb + t * 4, QRl + qb + t * 4);
    } else {
        int u = t - 64;
        const float4* se = reinterpret_cast<const float4*>(skill_emb + (size_t)skill_inputs[g] * 256);
        float4 v = se[u];
        float4 a = make_float4(v.x * lab, v.y * lab, v.z * lab, v.w * lab);
        float4 c = make_float4(v.x * nlab, v.y * nlab, v.z * nlab, v.w * nlab);
        cvt_store4(a, Ih + ib + 256 + u * 4, Il + ib + 256 + u * 4);
        cvt_store4(c, Ih + ib + 512 + 256 + u * 4, Il + ib + 512 + 256 + u * 4);
        const float4* qs = reinterpret_cast<const float4*>(skill_emb + (size_t)skill_ids[g] * 256);
        cvt_store4(qs[u], QRh + qb + 256 + u * 4, QRl + qb + 256 + u * 4);
    }
}

// ---------------------------------------------------------------------------
// Weight transposes (+ bf16 hi/lo split)
// ---------------------------------------------------------------------------
__global__ __launch_bounds__(256) void transpose_cvt_kernel(
    const float* __restrict__ src, __nv_bfloat16* __restrict__ dhi,
    __nv_bfloat16* __restrict__ dlo, int K, int N)
{
    __shared__ float t[32][33];
    int bx = blockIdx.x * 32, by = blockIdx.y * 32;
    int x = threadIdx.x & 31, y0 = threadIdx.x >> 5;
#pragma unroll
    for (int j = 0; j < 32; j += 8)
        t[y0 + j][x] = src[(size_t)(by + y0 + j) * N + bx + x];
    __syncthreads();
#pragma unroll
    for (int j = 0; j < 32; j += 8) {
        float v = t[x][y0 + j];
        float h = bf16_hi_f(v);
        size_t idx = (size_t)(bx + y0 + j) * K + by + x;
        dhi[idx] = __float2bfloat16_rn(v);
        dlo[idx] = __float2bfloat16_rn(v - h);
    }
}

struct TrArgs {
    const float* src[6];
    __nv_bfloat16* dhi[6];
    __nv_bfloat16* dlo[6];
};
__global__ __launch_bounds__(256) void transpose_qkv_kernel(TrArgs a)
{
    __shared__ float t[32][33];
    int z = blockIdx.z;
    const float* src = a.src[z];
    __nv_bfloat16* dhi = a.dhi[z];
    __nv_bfloat16* dlo = a.dlo[z];
    int bx = blockIdx.x * 32, by = blockIdx.y * 32;
    int x = threadIdx.x & 31, y0 = threadIdx.x >> 5;
#pragma unroll
    for (int j = 0; j < 32; j += 8)
        t[y0 + j][x] = src[(size_t)(by + y0 + j) * 512 + bx + x];
    __syncthreads();
#pragma unroll
    for (int j = 0; j < 32; j += 8) {
        float v = t[x][y0 + j];
        float h = bf16_hi_f(v);
        size_t idx = (size_t)(bx + y0 + j) * 512 + by + x;
        dhi[idx] = __float2bfloat16_rn(v);
        dlo[idx] = __float2bfloat16_rn(v - h);
    }
}

// ---------------------------------------------------------------------------
// GEMM: all operands bf16 hi/lo planes, 100% cp.async loads.
// 128x128 tile, 8 warps, K-chunk 32, double buffer.
// ---------------------------------------------------------------------------
#define RSTR 40
#define PLANE_B (128 * RSTR * 2)
#define STAGE_B (4 * PLANE_B)
#define GEMM_SMEM (2 * STAGE_B)

__device__ __forceinline__ void gemm_load_stage(
    uint32_t st, const __nv_bfloat16* Ah, const __nv_bfloat16* Al,
    const __nv_bfloat16* Bh, const __nv_bfloat16* Bl,
    int bm, int bn, int k0, int K, const int* fr, const int* fc)
{
#pragma unroll
    for (int i = 0; i < 2; i++) {
        uint32_t doff = (uint32_t)(fr[i] * RSTR + fc[i]) * 2;
        size_t ga = (size_t)(bm + fr[i]) * K + k0 + fc[i];
        size_t gb = (size_t)(bn + fr[i]) * K + k0 + fc[i];
        CPA16(st + doff, Ah + ga);
        CPA16(st + PLANE_B + doff, Al + ga);
        CPA16(st + 2 * PLANE_B + doff, Bh + gb);
        CPA16(st + 3 * PLANE_B + doff, Bl + gb);
    }
    CPA_COMMIT();
}

// RAW-distance-4 MMA ordering: product-type outer, accumulator inner.
__device__ __forceinline__ void gemm_compute_chunk(
    uint32_t cur, float acc[4][4][4], int wm, int wn,
    int lm, int kq, int nb, int kb2)
{
    uint32_t ahi_u = cur;
    uint32_t bhi_u = cur + 2 * PLANE_B;
#pragma unroll
    for (int s = 0; s < 2; s++) {
        uint32_t bh[4][2], bl[4][2];
#pragma unroll
        for (int jp = 0; jp < 2; jp++) {
            uint32_t off = (uint32_t)((wn + jp * 16 + nb) * RSTR + s * 16 + kb2) * 2;
            uint32_t r[4];
            ldm_x4(r, bhi_u + off);
            bh[jp * 2][0] = r[0]; bh[jp * 2][1] = r[1];
            bh[jp * 2 + 1][0] = r[2]; bh[jp * 2 + 1][1] = r[3];
            ldm_x4(r, bhi_u + PLANE_B + off);
            bl[jp * 2][0] = r[0]; bl[jp * 2][1] = r[1];
            bl[jp * 2 + 1][0] = r[2]; bl[jp * 2 + 1][1] = r[3];
        }
#pragma unroll
        for (int i = 0; i < 4; i++) {
            uint32_t off = (uint32_t)((wm + i * 16 + lm) * RSTR + s * 16 + kq) * 2;
            uint32_t ah[4], al[4];
            ldm_x4(ah, ahi_u + off);
            ldm_x4(al, ahi_u + PLANE_B + off);
#pragma unroll
            for (int j = 0; j < 4; j++) mma_bf16(acc[i][j], ah, bh[j]);
#pragma unroll
            for (int j = 0; j < 4; j++) mma_bf16(acc[i][j], al, bh[j]);
#pragma unroll
            for (int j = 0; j < 4; j++) mma_bf16(acc[i][j], ah, bl[j]);
        }
    }
}

// MLP (K variable, relu, plane output)
__global__ __launch_bounds__(256, 2)
void gemm_mlp_kernel(const __nv_bfloat16* __restrict__ Ah,
                     const __nv_bfloat16* __restrict__ Al,
                     const __nv_bfloat16* __restrict__ Bthi,
                     const __nv_bfloat16* __restrict__ Btlo,
                     const float* __restrict__ bias,
                     __nv_bfloat16* __restrict__ Xh,
                     __nv_bfloat16* __restrict__ Xl, int K)
{
    extern __shared__ __align__(16) char dsm[];
    int tid = threadIdx.x;
    int wid = tid >> 5, lane = tid & 31;
    int g = lane >> 2, t = lane & 3;
    int bm = blockIdx.y * 128, bn = blockIdx.x * 128;
    int wm = (wid & 1) * 64, wn = (wid >> 1) * 32;
    int NC = K >> 5;
    int lm = lane & 15, kq = (lane >> 4) << 3;
    int nb = (lane & 7) + ((lane >> 4) << 3);
    int kb2 = ((lane >> 3) & 1) * 8;

    int fr[2], fc[2];
#pragma unroll
    for (int i = 0; i < 2; i++) { int f = tid + i * 256; fr[i] = f >> 2; fc[i] = (f & 3) * 8; }

    float acc[4][4][4];
#pragma unroll
    for (int i = 0; i < 4; i++)
#pragma unroll
        for (int j = 0; j < 4; j++)
#pragma unroll
            for (int r = 0; r < 4; r++) acc[i][j][r] = 0.f;

    gemm_load_stage(smaddr(dsm), Ah, Al, Bthi, Btlo, bm, bn, 0, K, fr, fc);
    CPA_WAIT(0);
    __syncthreads();

    for (int chunk = 0; chunk < NC; chunk++) {
        uint32_t cur = smaddr(dsm) + (chunk & 1) * STAGE_B;
        bool more = (chunk + 1 < NC);
        if (more)
            gemm_load_stage(smaddr(dsm) + ((chunk + 1) & 1) * STAGE_B,
                            Ah, Al, Bthi, Btlo, bm, bn, (chunk + 1) << 5, K, fr, fc);
        gemm_compute_chunk(cur, acc, wm, wn, lm, kq, nb, kb2);
        if (more) { CPA_WAIT(0); }
        __syncthreads();
    }

#pragma unroll
    for (int i = 0; i < 4; i++) {
        int row0 = bm + wm + i * 16 + g;
#pragma unroll
        for (int j = 0; j < 4; j++) {
            int col = bn + wn + j * 8 + t * 2;
            float2 bv = *reinterpret_cast<const float2*>(bias + col);
            float v0 = fmaxf(acc[i][j][0] + bv.x, 0.f);
            float v1 = fmaxf(acc[i][j][1] + bv.y, 0.f);
            float v2 = fmaxf(acc[i][j][2] + bv.x, 0.f);
            float v3 = fmaxf(acc[i][j][3] + bv.y, 0.f);
            size_t i0 = (size_t)row0 * 512 + col;
            size_t i1 = (size_t)(row0 + 8) * 512 + col;
            *reinterpret_cast<uint32_t*>(Xh + i0) = pack_bf16(v0, v1);
            *reinterpret_cast<uint32_t*>(Xl + i0) =
                pack_bf16(v0 - bf16_hi_f(v0), v1 - bf16_hi_f(v1));
            *reinterpret_cast<uint32_t*>(Xh + i1) = pack_bf16(v2, v3);
            *reinterpret_cast<uint32_t*>(Xl + i1) =
                pack_bf16(v2 - bf16_hi_f(v2), v3 - bf16_hi_f(v3));
        }
    }
}

// Fused projections: z selects problem (K=512), plane output.
struct QKVArgs {
    const __nv_bfloat16* Ah[4];
    const __nv_bfloat16* Al[4];
    const __nv_bfloat16* Bh[4];
    const __nv_bfloat16* Bl[4];
    const float* bias[4];
    __nv_bfloat16* Ch[4];
    __nv_bfloat16* Cl[4];
};
__global__ __launch_bounds__(256, 2)
void gemm_qkv_kernel(QKVArgs args)
{
    extern __shared__ __align__(16) char dsm[];
    const int K = 512;
    int z = blockIdx.z;
    const __nv_bfloat16* Ah = args.Ah[z];
    const __nv_bfloat16* Al = args.Al[z];
    const __nv_bfloat16* Bthi = args.Bh[z];
    const __nv_bfloat16* Btlo = args.Bl[z];
    const float* bias = args.bias[z];
    __nv_bfloat16* Chi = args.Ch[z];
    __nv_bfloat16* Clo = args.Cl[z];

    int tid = threadIdx.x;
    int wid = tid >> 5, lane = tid & 31;
    int g = lane >> 2, t = lane & 3;
    int bm = blockIdx.y * 128, bn = blockIdx.x * 128;
    int wm = (wid & 1) * 64, wn = (wid >> 1) * 32;
    const int NC = 16;
    int lm = lane & 15, kq = (lane >> 4) << 3;
    int nb = (lane & 7) + ((lane >> 4) << 3);
    int kb2 = ((lane >> 3) & 1) * 8;

    int fr[2], fc[2];
#pragma unroll
    for (int i = 0; i < 2; i++) { int f = tid + i * 256; fr[i] = f >> 2; fc[i] = (f & 3) * 8; }

    float acc[4][4][4];
#pragma unroll
    for (int i = 0; i < 4; i++)
#pragma unroll
        for (int j = 0; j < 4; j++)
#pragma unroll
            for (int r = 0; r < 4; r++) acc[i][j][r] = 0.f;

    gemm_load_stage(smaddr(dsm), Ah, Al, Bthi, Btlo, bm, bn, 0, K, fr, fc);
    CPA_WAIT(0);
    __syncthreads();

    for (int chunk = 0; chunk < NC; chunk++) {
        uint32_t cur = smaddr(dsm) + (chunk & 1) * STAGE_B;
        bool more = (chunk + 1 < NC);
        if (more)
            gemm_load_stage(smaddr(dsm) + ((chunk + 1) & 1) * STAGE_B,
                            Ah, Al, Bthi, Btlo, bm, bn, (chunk + 1) << 5, K, fr, fc);
        gemm_compute_chunk(cur, acc, wm, wn, lm, kq, nb, kb2);
        if (more) { CPA_WAIT(0); }
        __syncthreads();
    }

#pragma unroll
    for (int i = 0; i < 4; i++) {
        int row0 = bm + wm + i * 16 + g;
#pragma unroll
        for (int j = 0; j < 4; j++) {
            int col = bn + wn + j * 8 + t * 2;
            float2 bv = *reinterpret_cast<const float2*>(bias + col);
            float v0 = acc[i][j][0] + bv.x, v1 = acc[i][j][1] + bv.y;
            float v2 = acc[i][j][2] + bv.x, v3 = acc[i][j][3] + bv.y;
            size_t i0 = (size_t)row0 * 512 + col;
            size_t i1 = (size_t)(row0 + 8) * 512 + col;
            *reinterpret_cast<uint32_t*>(Chi + i0) = pack_bf16(v0, v1);
            *reinterpret_cast<uint32_t*>(Clo + i0) =
                pack_bf16(v0 - bf16_hi_f(v0), v1 - bf16_hi_f(v1));
            *reinterpret_cast<uint32_t*>(Chi + i1) = pack_bf16(v2, v3);
            *reinterpret_cast<uint32_t*>(Clo + i1) =
                pack_bf16(v2 - bf16_hi_f(v2), v3 - bf16_hi_f(v3));
        }
    }
}

// ---------------------------------------------------------------------------
// Flash attention: cp.async double-buffered K/V, Q frags in registers.
// OUT=0: write f32 Op + planes. OUT=1: Op += relu(result).
// MMA ordering interleaves the paired accumulators (RAW distance 2).
// ---------------------------------------------------------------------------
#define QS 72
#define FPL (64 * QS)
#define FSTG_B (4 * FPL * 2)
#define FL_SMEM (2 * FSTG_B)

template<int OUT>
__global__ __launch_bounds__(256, 2) void flash_bf16_kernel(
    const __nv_bfloat16* __restrict__ Qh, const __nv_bfloat16* __restrict__ Ql,
    const __nv_bfloat16* __restrict__ Kh, const __nv_bfloat16* __restrict__ Kl,
    const __nv_bfloat16* __restrict__ Vh, const __nv_bfloat16* __restrict__ Vl,
    float* __restrict__ Op,
    __nv_bfloat16* __restrict__ Ohp, __nv_bfloat16* __restrict__ Olp)
{
    extern __shared__ __align__(16) char fsm[];

    int tid = threadIdx.x;
    int wid = tid >> 5, lane = tid & 31;
    int g = lane >> 2, t = lane & 3;
    int qt = (SEQ / 128 - 1) - blockIdx.x;
    int h = blockIdx.y, b = blockIdx.z;
    size_t qoff = ((size_t)(b * SEQ + qt * 128)) * EMB + h * DHD;
    size_t kvoff = ((size_t)b * SEQ) * EMB + h * DHD;

    int rb = wid * 16;
    int lm = lane & 15, kq = (lane >> 4) << 3;
    int nbk = (lane & 7) + ((lane >> 4) << 3);
    int kb2 = ((lane >> 3) & 1) * 8;
    int kv = (lane & 7) + ((lane >> 3) & 1) * 8;
    int nv = (lane >> 4) << 3;

    uint32_t qah[4][4], qal[4][4];
    {
        __nv_bfloat16* sQh = reinterpret_cast<__nv_bfloat16*>(fsm);
        __nv_bfloat16* sQl = sQh + 128 * QS;
#pragma unroll
        for (int i = 0; i < 4; i++) {
            int f = tid + i * 256;
            int r = f >> 3, c = (f & 7) * 8;
            *reinterpret_cast<uint4*>(sQh + r * QS + c) =
                *reinterpret_cast<const uint4*>(Qh + qoff + (size_t)r * EMB + c);
            *reinterpret_cast<uint4*>(sQl + r * QS + c) =
                *reinterpret_cast<const uint4*>(Ql + qoff + (size_t)r * EMB + c);
        }
        __syncthreads();
        uint32_t uQh = smaddr(sQh), uQl = smaddr(sQl);
#pragma unroll
        for (int kk = 0; kk < 4; kk++) {
            uint32_t qo = (uint32_t)((rb + lm) * QS + kk * 16 + kq) * 2;
            ldm_x4(qah[kk], uQh + qo);
            ldm_x4(qal[kk], uQl + qo);
        }
        __syncthreads();
    }

    int ktmax = qt * 2 + 1;
    int wmaxrow = qt * 128 + rb + 15;
    int row0g = qt * 128 + rb + g, row1g = row0g + 8;

    int fr[2], fc[2];
#pragma unroll
    for (int i = 0; i < 2; i++) {
        int f = tid + i * 256;
        fr[i] = f >> 3; fc[i] = (f & 7) * 8;
    }

    {
        uint32_t st = smaddr(fsm);
#pragma unroll
        for (int i = 0; i < 2; i++) {
            uint32_t doff = (uint32_t)(fr[i] * QS + fc[i]) * 2;
            size_t go = kvoff + (size_t)fr[i] * EMB + fc[i];
            CPA16(st + doff, Kh + go);
            CPA16(st + FPL * 2 + doff, Kl + go);
            CPA16(st + 2 * FPL * 2 + doff, Vh + go);
            CPA16(st + 3 * FPL * 2 + doff, Vl + go);
        }
        CPA_COMMIT();
    }

    float m0 = -INFINITY, m1 = -INFINITY, l0 = 0.f, l1 = 0.f;
    float acc[8][4];
#pragma unroll
    for (int j = 0; j < 8; j++)
#pragma unroll
        for (int r = 0; r < 4; r++) acc[j][r] = 0.f;

    for (int kt = 0; kt <= ktmax; kt++) {
        uint32_t cur = smaddr(fsm) + (kt & 1) * FSTG_B;
        bool more = (kt < ktmax);
        if (more) {
            uint32_t nxt = smaddr(fsm) + ((kt + 1) & 1) * FSTG_B;
            size_t ko = kvoff + (size_t)(kt + 1) * 64 * EMB;
#pragma unroll
            for (int i = 0; i < 2; i++) {
                uint32_t doff = (uint32_t)(fr[i] * QS + fc[i]) * 2;
                size_t go = ko + (size_t)fr[i] * EMB + fc[i];
                CPA16(nxt + doff, Kh + go);
                CPA16(nxt + FPL * 2 + doff, Kl + go);
                CPA16(nxt + 2 * FPL * 2 + doff, Vh + go);
                CPA16(nxt + 3 * FPL * 2 + doff, Vl + go);
            }
            CPA_COMMIT();
            CPA_WAIT(1);
        } else {
            CPA_WAIT(0);
        }
        __syncthreads();

        if (kt * 64 <= wmaxrow) {
            uint32_t uKh = cur, uKl = cur + FPL * 2;
            uint32_t uVh = cur + 2 * FPL * 2, uVl = cur + 3 * FPL * 2;

            float s[8][4];
#pragma unroll
            for (int j = 0; j < 8; j++)
#pragma unroll
                for (int r = 0; r < 4; r++) s[j][r] = 0.f;
#pragma unroll
            for (int kk = 0; kk < 4; kk++) {
#pragma unroll
                for (int jp = 0; jp < 4; jp++) {
                    uint32_t koff = (uint32_t)((jp * 16 + nbk) * QS + kk * 16 + kb2) * 2;
                    uint32_t rh[4], rl[4];
                    ldm_x4(rh, uKh + koff);
                    ldm_x4(rl, uKl + koff);
                    uint32_t b0[2] = { rh[0], rh[1] }, b1[2] = { rh[2], rh[3] };
                    uint32_t c0[2] = { rl[0], rl[1] }, c1[2] = { rl[2], rl[3] };
                    // interleaved: RAW distance 2
                    mma_bf16(s[2 * jp],     qah[kk], b0);
                    mma_bf16(s[2 * jp + 1], qah[kk], b1);
                    mma_bf16(s[2 * jp],     qal[kk], b0);
                    mma_bf16(s[2 * jp + 1], qal[kk], b1);
                    mma_bf16(s[2 * jp],     qah[kk], c0);
                    mma_bf16(s[2 * jp + 1], qah[kk], c1);
                }
            }

            int colb = kt * 64 + t * 2;
#pragma unroll
            for (int j = 0; j < 8; j++) {
                int c0 = colb + j * 8, c1 = c0 + 1;
                s[j][0] = (c0 > row0g) ? -INFINITY : s[j][0] * ATTN_SCALE;
                s[j][1] = (c1 > row0g) ? -INFINITY : s[j][1] * ATTN_SCALE;
                s[j][2] = (c0 > row1g) ? -INFINITY : s[j][2] * ATTN_SCALE;
                s[j][3] = (c1 > row1g) ? -INFINITY : s[j][3] * ATTN_SCALE;
            }

            float tm0 = -INFINITY, tm1 = -INFINITY;
#pragma unroll
            for (int j = 0; j < 8; j++) {
                tm0 = fmaxf(tm0, fmaxf(s[j][0], s[j][1]));
                tm1 = fmaxf(tm1, fmaxf(s[j][2], s[j][3]));
            }
            tm0 = fmaxf(tm0, __shfl_xor_sync(0xFFFFFFFFu, tm0, 1));
            tm0 = fmaxf(tm0, __shfl_xor_sync(0xFFFFFFFFu, tm0, 2));
            tm1 = fmaxf(tm1, __shfl_xor_sync(0xFFFFFFFFu, tm1, 1));
            tm1 = fmaxf(tm1, __shfl_xor_sync(0xFFFFFFFFu, tm1, 2));
            float m0n = fmaxf(m0, tm0), m1n = fmaxf(m1, tm1);
            float ms0 = fmaxf(m0n, -1e30f), ms1 = fmaxf(m1n, -1e30f);
            float alpha0 = __expf(m0 - ms0), alpha1 = __expf(m1 - ms1);
            m0 = m0n; m1 = m1n;
#pragma unroll
            for (int j = 0; j < 8; j++) {
                acc[j][0] *= alpha0; acc[j][1] *= alpha0;
                acc[j][2] *= alpha1; acc[j][3] *= alpha1;
            }

            float ps0 = 0.f, ps1 = 0.f;
#pragma unroll
            for (int kk = 0; kk < 4; kk++) {
                int j0 = 2 * kk, j1 = 2 * kk + 1;
                float p00 = __expf(s[j0][0] - ms0), p01 = __expf(s[j0][1] - ms0);
                float p02 = __expf(s[j0][2] - ms1), p03 = __expf(s[j0][3] - ms1);
                float p10 = __expf(s[j1][0] - ms0), p11 = __expf(s[j1][1] - ms0);
                float p12 = __expf(s[j1][2] - ms1), p13 = __expf(s[j1][3] - ms1);
                ps0 += p00 + p01 + p10 + p11;
                ps1 += p02 + p03 + p12 + p13;
                uint32_t pah[4], pal[4];
                pah[0] = pack_bf16(p00, p01);
                pah[1] = pack_bf16(p02, p03);
                pah[2] = pack_bf16(p10, p11);
                pah[3] = pack_bf16(p12, p13);
                pal[0] = pack_bf16(p00 - bf16_hi_f(p00), p01 - bf16_hi_f(p01));
                pal[1] = pack_bf16(p02 - bf16_hi_f(p02), p03 - bf16_hi_f(p03));
                pal[2] = pack_bf16(p10 - bf16_hi_f(p10), p11 - bf16_hi_f(p11));
                pal[3] = pack_bf16(p12 - bf16_hi_f(p12), p13 - bf16_hi_f(p13));
#pragma unroll
                for (int jdp = 0; jdp < 4; jdp++) {
                    uint32_t voff = (uint32_t)((kk * 16 + kv) * QS + jdp * 16 + nv) * 2;
                    uint32_t rh[4], rl[4];
                    ldm_x4t(rh, uVh + voff);
                    ldm_x4t(rl, uVl + voff);
                    uint32_t b0[2] = { rh[0], rh[1] }, b1[2] = { rh[2], rh[3] };
                    uint32_t c0[2] = { rl[0], rl[1] }, c1[2] = { rl[2], rl[3] };
                    // interleaved: RAW distance 2
                    mma_bf16(acc[2 * jdp],     pah, b0);
                    mma_bf16(acc[2 * jdp + 1], pah, b1);
                    mma_bf16(acc[2 * jdp],     pal, b0);
                    mma_bf16(acc[2 * jdp + 1], pal, b1);
                    mma_bf16(acc[2 * jdp],     pah, c0);
                    mma_bf16(acc[2 * jdp + 1], pah, c1);
                }
            }
            ps0 += __shfl_xor_sync(0xFFFFFFFFu, ps0, 1);
            ps0 += __shfl_xor_sync(0xFFFFFFFFu, ps0, 2);
            ps1 += __shfl_xor_sync(0xFFFFFFFFu, ps1, 1);
            ps1 += __shfl_xor_sync(0xFFFFFFFFu, ps1, 2);
            l0 = l0 * alpha0 + ps0;
            l1 = l1 * alpha1 + ps1;
        }
        __syncthreads();
    }

    float inv0 = 1.f / l0, inv1 = 1.f / l1;
#pragma unroll
    for (int jd = 0; jd < 8; jd++) {
        int c = jd * 8 + t * 2;
        size_t i0 = qoff + (size_t)(rb + g) * EMB + c;
        size_t i1 = qoff + (size_t)(rb + g + 8) * EMB + c;
        float o00 = acc[jd][0] * inv0, o01 = acc[jd][1] * inv0;
        float o10 = acc[jd][2] * inv1, o11 = acc[jd][3] * inv1;
        if (OUT == 0) {
            *reinterpret_cast<float2*>(Op + i0) = make_float2(o00, o01);
            *reinterpret_cast<float2*>(Op + i1) = make_float2(o10, o11);
            *reinterpret_cast<uint32_t*>(Ohp + i0) = pack_bf16(o00, o01);
            *reinterpret_cast<uint32_t*>(Olp + i0) =
                pack_bf16(o00 - bf16_hi_f(o00), o01 - bf16_hi_f(o01));
            *reinterpret_cast<uint32_t*>(Ohp + i1) = pack_bf16(o10, o11);
            *reinterpret_cast<uint32_t*>(Olp + i1) =
                pack_bf16(o10 - bf16_hi_f(o10), o11 - bf16_hi_f(o11));
        } else {
            float2 e0 = *reinterpret_cast<float2*>(Op + i0);
            float2 e1 = *reinterpret_cast<float2*>(Op + i1);
            *reinterpret_cast<float2*>(Op + i0) =
                make_float2(e0.x + fmaxf(o00, 0.f), e0.y + fmaxf(o01, 0.f));
            *reinterpret_cast<float2*>(Op + i1) =
                make_float2(e1.x + fmaxf(o10, 0.f), e1.y + fmaxf(o11, 0.f));
        }
    }
}

// ---------------------------------------------------------------------------
__global__ __launch_bounds__(256) void out_proj_kernel(
    const float* __restrict__ out, const float* __restrict__ Wout,
    const float* __restrict__ bout, float* __restrict__ y)
{
    int g = blockIdx.x * 8 + (threadIdx.x >> 5);
    int lane = threadIdx.x & 31;
    const float4* o4 = reinterpret_cast<const float4*>(out + (size_t)g * EMB);
    const float4* w4 = reinterpret_cast<const float4*>(Wout);
    float s = 0.f;
#pragma unroll
    for (int i = 0; i < 4; i++) {
        float4 a = o4[lane + 32 * i];
        float4 b = w4[lane + 32 * i];
        s += a.x * b.x + a.y * b.y + a.z * b.z + a.w * b.w;
    }
#pragma unroll
    for (int off = 16; off > 0; off >>= 1)
        s += __shfl_xor_sync(0xFFFFFFFFu, s, off);
    if (lane == 0) y[g] = s + bout[0];
}

// ---------------------------------------------------------------------------
extern "C" void kernel_launch(void* const* d_in, const int* in_sizes, int n_in,
                              void* d_out, int out_size)
{
    const int*   item_inputs  = (const int*)d_in[0];
    const int*   skill_inputs = (const int*)d_in[1];
    const int*   label_inputs = (const int*)d_in[2];
    const int*   item_ids     = (const int*)d_in[3];
    const int*   skill_ids    = (const int*)d_in[4];
    const float* item_emb     = (const float*)d_in[5];
    const float* skill_emb    = (const float*)d_in[6];
    const float* W_in         = (const float*)d_in[7];
    const float* b_in         = (const float*)d_in[8];
    const float* Wq           = (const float*)d_in[9];
    const float* bq           = (const float*)d_in[10];
    const float* Wk           = (const float*)d_in[11];
    const float* bk           = (const float*)d_in[12];
    const float* Wv           = (const float*)d_in[13];
    const float* bv           = (const float*)d_in[14];
    const float* W_out        = (const float*)d_in[22];
    const float* b_out        = (const float*)d_in[23];
    float* y = (float*)d_out;

    float* outb;
    __nv_bfloat16 *w, *ih, *il, *qrh, *qrl, *xh, *xl, *oh, *ol;
    __nv_bfloat16 *q1h, *q1l, *q2h, *q2l, *kh, *kl, *vh, *vl;
    cudaGetSymbolAddress((void**)&outb, g_outb);
    cudaGetSymbolAddress((void**)&w,    g_W);
    cudaGetSymbolAddress((void**)&ih,   g_Ih);
    cudaGetSymbolAddress((void**)&il,   g_Il);
    cudaGetSymbolAddress((void**)&qrh,  g_QRh);
    cudaGetSymbolAddress((void**)&qrl,  g_QRl);
    cudaGetSymbolAddress((void**)&xh,   g_Xh);
    cudaGetSymbolAddress((void**)&xl,   g_Xl);
    cudaGetSymbolAddress((void**)&oh,   g_Oh);
    cudaGetSymbolAddress((void**)&ol,   g_Ol);
    cudaGetSymbolAddress((void**)&q1h,  g_Q1h);
    cudaGetSymbolAddress((void**)&q1l,  g_Q1l);
    cudaGetSymbolAddress((void**)&q2h,  g_Q2h);
    cudaGetSymbolAddress((void**)&q2l,  g_Q2l);
    cudaGetSymbolAddress((void**)&kh,   g_Kh);
    cudaGetSymbolAddress((void**)&kl,   g_Kl);
    cudaGetSymbolAddress((void**)&vh,   g_Vh);
    cudaGetSymbolAddress((void**)&vl,   g_Vl);

    cudaFuncSetAttribute(flash_bf16_kernel<0>,
                         cudaFuncAttributeMaxDynamicSharedMemorySize, FL_SMEM);
    cudaFuncSetAttribute(flash_bf16_kernel<1>,
                         cudaFuncAttributeMaxDynamicSharedMemorySize, FL_SMEM);
    cudaFuncSetAttribute(gemm_mlp_kernel,
                         cudaFuncAttributeMaxDynamicSharedMemorySize, GEMM_SMEM);
    cudaFuncSetAttribute(gemm_qkv_kernel,
                         cudaFuncAttributeMaxDynamicSharedMemorySize, GEMM_SMEM);

    __nv_bfloat16* win_hi = w;
    __nv_bfloat16* win_lo = w + 512 * 1024;
    __nv_bfloat16* qkv_hi[2][3];
    __nv_bfloat16* qkv_lo[2][3];
    {
        __nv_bfloat16* p = w + 2 * 512 * 1024;
        for (int l = 0; l < 2; l++)
            for (int m = 0; m < 3; m++) {
                qkv_hi[l][m] = p; p += 512 * 512;
                qkv_lo[l][m] = p; p += 512 * 512;
            }
    }

    gather_kernel<<<TOT, 128>>>(item_inputs, skill_inputs, label_inputs,
                                item_ids, skill_ids, item_emb, skill_emb,
                                ih, il, qrh, qrl);
    transpose_cvt_kernel<<<dim3(16, 32), 256>>>(W_in, win_hi, win_lo, 1024, 512);
    {
        TrArgs ta;
        const float* srcs[3] = { Wq, Wk, Wv };
        for (int l = 0; l < 2; l++)
            for (int m = 0; m < 3; m++) {
                ta.src[l * 3 + m] = srcs[m] + (size_t)l * 512 * 512;
                ta.dhi[l * 3 + m] = qkv_hi[l][m];
                ta.dlo[l * 3 + m] = qkv_lo[l][m];
            }
        transpose_qkv_kernel<<<dim3(16, 16, 6), 256>>>(ta);
    }
    gemm_mlp_kernel<<<dim3(4, 128), 256, GEMM_SMEM>>>(
        ih, il, win_hi, win_lo, b_in, xh, xl, 1024);

    // fused Q1,K1,V1,Q2
    {
        QKVArgs qa;
        qa.Ah[0] = qrh; qa.Al[0] = qrl;
        qa.Ah[1] = xh;  qa.Al[1] = xl;
        qa.Ah[2] = xh;  qa.Al[2] = xl;
        qa.Ah[3] = qrh; qa.Al[3] = qrl;
        qa.Bh[0] = qkv_hi[0][0]; qa.Bl[0] = qkv_lo[0][0];
        qa.Bh[1] = qkv_hi[0][1]; qa.Bl[1] = qkv_lo[0][1];
        qa.Bh[2] = qkv_hi[0][2]; qa.Bl[2] = qkv_lo[0][2];
        qa.Bh[3] = qkv_hi[1][0]; qa.Bl[3] = qkv_lo[1][0];
        qa.bias[0] = bq; qa.bias[1] = bk; qa.bias[2] = bv; qa.bias[3] = bq + EMB;
        qa.Ch[0] = q1h; qa.Cl[0] = q1l;
        qa.Ch[1] = kh;  qa.Cl[1] = kl;
        qa.Ch[2] = vh;  qa.Cl[2] = vl;
        qa.Ch[3] = q2h; qa.Cl[3] = q2l;
        gemm_qkv_kernel<<<dim3(4, 128, 4), 256, GEMM_SMEM>>>(qa);
    }
    flash_bf16_kernel<0><<<dim3(SEQ / 128, NH, Bsz), 256, FL_SMEM>>>(
        q1h, q1l, kh, kl, vh, vl, outb, oh, ol);
    // fused K2,V2
    {
        QKVArgs qa;
        qa.Ah[0] = oh; qa.Al[0] = ol;
        qa.Ah[1] = oh; qa.Al[1] = ol;
        qa.Ah[2] = oh; qa.Al[2] = ol;
        qa.Ah[3] = oh; qa.Al[3] = ol;
        qa.Bh[0] = qkv_hi[1][1]; qa.Bl[0] = qkv_lo[1][1];
        qa.Bh[1] = qkv_hi[1][2]; qa.Bl[1] = qkv_lo[1][2];
        qa.Bh[2] = qkv_hi[1][1]; qa.Bl[2] = qkv_lo[1][1];
        qa.Bh[3] = qkv_hi[1][2]; qa.Bl[3] = qkv_lo[1][2];
        qa.bias[0] = bk + EMB; qa.bias[1] = bv + EMB;
        qa.bias[2] = bk + EMB; qa.bias[3] = bv + EMB;
        qa.Ch[0] = kh; qa.Cl[0] = kl;
        qa.Ch[1] = vh; qa.Cl[1] = vl;
        qa.Ch[2] = kh; qa.Cl[2] = kl;
        qa.Ch[3] = vh; qa.Cl[3] = vl;
        gemm_qkv_kernel<<<dim3(4, 128, 2), 256, GEMM_SMEM>>>(qa);
    }
    flash_bf16_kernel<1><<<dim3(SEQ / 128, NH, Bsz), 256, FL_SMEM>>>(
        q2h, q2l, kh, kl, vh, vl, outb, nullptr, nullptr);

    out_proj_kernel<<<TOT / 8, 256>>>(outb, W_out, b_out, y);
}

// round 10
// speedup vs baseline: 3.2752x; 1.0562x over previous
#include <cuda_runtime.h>
#include <cuda_bf16.h>
#include <cstdint>

// ---------------------------------------------------------------------------
// TSAKT: gather -> ReLU MLP -> 2x causal MHA -> output proj.
// glo/ts biases are key-constant pre-mask => softmax-shift-invariant => dropped.
// R10: GEMM fragment-level software pipeline: B frags hoisted per chunk,
//      A frags double-buffered one step ahead, barrier overlapped with the
//      tail MMA group. Same arithmetic as R9 (rel_err bit-identical).
// ---------------------------------------------------------------------------

#define Bsz 32
#define SEQ 512
#define EMB 512
#define NH  8
#define DHD 64
#define TOT (Bsz * SEQ)
#define ATTN_SCALE 0.125f

// ---- device scratch ---------------------------------------------------------
__device__ float g_outb [(size_t)TOT * EMB];
__device__ __nv_bfloat16 g_W[2 * 512 * 1024 + 12 * 512 * 512];
__device__ __nv_bfloat16 g_Ih[(size_t)TOT * 1024], g_Il[(size_t)TOT * 1024];
__device__ __nv_bfloat16 g_QRh[(size_t)TOT * EMB], g_QRl[(size_t)TOT * EMB];
__device__ __nv_bfloat16 g_Xh[(size_t)TOT * EMB],  g_Xl[(size_t)TOT * EMB];
__device__ __nv_bfloat16 g_Oh[(size_t)TOT * EMB],  g_Ol[(size_t)TOT * EMB];
__device__ __nv_bfloat16 g_Q1h[(size_t)TOT * EMB], g_Q1l[(size_t)TOT * EMB];
__device__ __nv_bfloat16 g_Q2h[(size_t)TOT * EMB], g_Q2l[(size_t)TOT * EMB];
__device__ __nv_bfloat16 g_Kh[(size_t)TOT * EMB],  g_Kl[(size_t)TOT * EMB];
__device__ __nv_bfloat16 g_Vh[(size_t)TOT * EMB],  g_Vl[(size_t)TOT * EMB];

// ---------------------------------------------------------------------------
__device__ __forceinline__ uint32_t pack_bf16(float x, float y) {
    __nv_bfloat162 h = __floats2bfloat162_rn(x, y);
    return *reinterpret_cast<uint32_t*>(&h);
}
__device__ __forceinline__ float bf16_hi_f(float x) {
    return __bfloat162float(__float2bfloat16_rn(x));
}
__device__ __forceinline__ void mma_bf16(float* c, const uint32_t* a, const uint32_t* b) {
    asm volatile(
        "mma.sync.aligned.m16n8k16.row.col.f32.bf16.bf16.f32 "
        "{%0,%1,%2,%3}, {%4,%5,%6,%7}, {%8,%9}, {%0,%1,%2,%3};"
        : "+f"(c[0]), "+f"(c[1]), "+f"(c[2]), "+f"(c[3])
        : "r"(a[0]), "r"(a[1]), "r"(a[2]), "r"(a[3]), "r"(b[0]), "r"(b[1]));
}
__device__ __forceinline__ void ldm_x4(uint32_t* r, uint32_t a) {
    asm volatile("ldmatrix.sync.aligned.m8n8.x4.shared.b16 {%0,%1,%2,%3}, [%4];"
        : "=r"(r[0]), "=r"(r[1]), "=r"(r[2]), "=r"(r[3]) : "r"(a));
}
__device__ __forceinline__ void ldm_x4t(uint32_t* r, uint32_t a) {
    asm volatile("ldmatrix.sync.aligned.m8n8.x4.trans.shared.b16 {%0,%1,%2,%3}, [%4];"
        : "=r"(r[0]), "=r"(r[1]), "=r"(r[2]), "=r"(r[3]) : "r"(a));
}
__device__ __forceinline__ uint32_t smaddr(const void* p) {
    return (uint32_t)__cvta_generic_to_shared(p);
}
#define CPA16(dst, src) \
    asm volatile("cp.async.cg.shared.global [%0], [%1], 16;" :: "r"(dst), "l"(src))
#define CPA_COMMIT() asm volatile("cp.async.commit_group;")
#define CPA_WAIT(n)  asm volatile("cp.async.wait_group %0;" :: "n"(n))

__device__ __forceinline__ void cvt_store4(float4 v, __nv_bfloat16* hi, __nv_bfloat16* lo) {
    float hx = bf16_hi_f(v.x), hy = bf16_hi_f(v.y);
    float hz = bf16_hi_f(v.z), hw = bf16_hi_f(v.w);
    *reinterpret_cast<uint2*>(hi) = make_uint2(pack_bf16(v.x, v.y), pack_bf16(v.z, v.w));
    *reinterpret_cast<uint2*>(lo) = make_uint2(pack_bf16(v.x - hx, v.y - hy),
                                               pack_bf16(v.z - hz, v.w - hw));
}

// ---------------------------------------------------------------------------
// Gather: emits inputs planes [g,1024] and query planes [g,512]
// ---------------------------------------------------------------------------
__global__ __launch_bounds__(128) void gather_kernel(
    const int* __restrict__ item_inputs, const int* __restrict__ skill_inputs,
    const int* __restrict__ label_inputs,
    const int* __restrict__ item_ids, const int* __restrict__ skill_ids,
    const float* __restrict__ item_emb, const float* __restrict__ skill_emb,
    __nv_bfloat16* __restrict__ Ih, __nv_bfloat16* __restrict__ Il,
    __nv_bfloat16* __restrict__ QRh, __nv_bfloat16* __restrict__ QRl)
{
    int g = blockIdx.x;
    int t = threadIdx.x;
    float lab = (float)label_inputs[g];
    float nlab = 1.0f - lab;
    size_t ib = (size_t)g * 1024, qb = (size_t)g * 512;
    if (t < 64) {
        const float4* ie = reinterpret_cast<const float4*>(item_emb + (size_t)item_inputs[g] * 256);
        float4 v = ie[t];
        float4 a = make_float4(v.x * lab, v.y * lab, v.z * lab, v.w * lab);
        float4 c = make_float4(v.x * nlab, v.y * nlab, v.z * nlab, v.w * nlab);
        cvt_store4(a, Ih + ib + t * 4, Il + ib + t * 4);
        cvt_store4(c, Ih + ib + 512 + t * 4, Il + ib + 512 + t * 4);
        const float4* qe = reinterpret_cast<const float4*>(item_emb + (size_t)item_ids[g] * 256);
        cvt_store4(qe[t], QRh + qb + t * 4, QRl + qb + t * 4);
    } else {
        int u = t - 64;
        const float4* se = reinterpret_cast<const float4*>(skill_emb + (size_t)skill_inputs[g] * 256);
        float4 v = se[u];
        float4 a = make_float4(v.x * lab, v.y * lab, v.z * lab, v.w * lab);
        float4 c = make_float4(v.x * nlab, v.y * nlab, v.z * nlab, v.w * nlab);
        cvt_store4(a, Ih + ib + 256 + u * 4, Il + ib + 256 + u * 4);
        cvt_store4(c, Ih + ib + 512 + 256 + u * 4, Il + ib + 512 + 256 + u * 4);
        const float4* qs = reinterpret_cast<const float4*>(skill_emb + (size_t)skill_ids[g] * 256);
        cvt_store4(qs[u], QRh + qb + 256 + u * 4, QRl + qb + 256 + u * 4);
    }
}

// ---------------------------------------------------------------------------
// Weight transposes (+ bf16 hi/lo split)
// ---------------------------------------------------------------------------
__global__ __launch_bounds__(256) void transpose_cvt_kernel(
    const float* __restrict__ src, __nv_bfloat16* __restrict__ dhi,
    __nv_bfloat16* __restrict__ dlo, int K, int N)
{
    __shared__ float t[32][33];
    int bx = blockIdx.x * 32, by = blockIdx.y * 32;
    int x = threadIdx.x & 31, y0 = threadIdx.x >> 5;
#pragma unroll
    for (int j = 0; j < 32; j += 8)
        t[y0 + j][x] = src[(size_t)(by + y0 + j) * N + bx + x];
    __syncthreads();
#pragma unroll
    for (int j = 0; j < 32; j += 8) {
        float v = t[x][y0 + j];
        float h = bf16_hi_f(v);
        size_t idx = (size_t)(bx + y0 + j) * K + by + x;
        dhi[idx] = __float2bfloat16_rn(v);
        dlo[idx] = __float2bfloat16_rn(v - h);
    }
}

struct TrArgs {
    const float* src[6];
    __nv_bfloat16* dhi[6];
    __nv_bfloat16* dlo[6];
};
__global__ __launch_bounds__(256) void transpose_qkv_kernel(TrArgs a)
{
    __shared__ float t[32][33];
    int z = blockIdx.z;
    const float* src = a.src[z];
    __nv_bfloat16* dhi = a.dhi[z];
    __nv_bfloat16* dlo = a.dlo[z];
    int bx = blockIdx.x * 32, by = blockIdx.y * 32;
    int x = threadIdx.x & 31, y0 = threadIdx.x >> 5;
#pragma unroll
    for (int j = 0; j < 32; j += 8)
        t[y0 + j][x] = src[(size_t)(by + y0 + j) * 512 + bx + x];
    __syncthreads();
#pragma unroll
    for (int j = 0; j < 32; j += 8) {
        float v = t[x][y0 + j];
        float h = bf16_hi_f(v);
        size_t idx = (size_t)(bx + y0 + j) * 512 + by + x;
        dhi[idx] = __float2bfloat16_rn(v);
        dlo[idx] = __float2bfloat16_rn(v - h);
    }
}

// ---------------------------------------------------------------------------
// GEMM: all operands bf16 hi/lo planes, 100% cp.async loads.
// 128x128 tile, 8 warps, K-chunk 32, double buffer.
// R10: B frags hoisted per chunk (regs), A frags double-buffered one (s,i)
//      step ahead, CPA_WAIT+barrier placed before the final 12 tail MMAs.
// ---------------------------------------------------------------------------
#define RSTR 40
#define PLANE_B (128 * RSTR * 2)
#define STAGE_B (4 * PLANE_B)
#define GEMM_SMEM (2 * STAGE_B)

__device__ __forceinline__ void gemm_load_stage(
    uint32_t st, const __nv_bfloat16* Ah, const __nv_bfloat16* Al,
    const __nv_bfloat16* Bh, const __nv_bfloat16* Bl,
    int bm, int bn, int k0, int K, const int* fr, const int* fc)
{
#pragma unroll
    for (int i = 0; i < 2; i++) {
        uint32_t doff = (uint32_t)(fr[i] * RSTR + fc[i]) * 2;
        size_t ga = (size_t)(bm + fr[i]) * K + k0 + fc[i];
        size_t gb = (size_t)(bn + fr[i]) * K + k0 + fc[i];
        CPA16(st + doff, Ah + ga);
        CPA16(st + PLANE_B + doff, Al + ga);
        CPA16(st + 2 * PLANE_B + doff, Bh + gb);
        CPA16(st + 3 * PLANE_B + doff, Bl + gb);
    }
    CPA_COMMIT();
}

// Software-pipelined chunk. If tail_sync, the cp.async wait + __syncthreads
// are issued after the LAST ldmatrix and before the final 12 MMAs, hiding
// barrier convergence behind tail compute. All ldmatrix reads of `cur` retire
// before the barrier, so the stage may be safely overwritten afterwards.
__device__ __forceinline__ void gemm_chunk_pipe(
    uint32_t cur, float (&acc)[4][4][4], int wm, int wn,
    int lm, int kq, int nb, int kb2, bool tail_sync)
{
    uint32_t a_u = cur;
    uint32_t b_u = cur + 2 * PLANE_B;

    // hoist all B fragments for both k16 steps (8 ldm, 32 regs)
    uint32_t bfh[2][4][2], bfl[2][4][2];
#pragma unroll
    for (int s = 0; s < 2; s++)
#pragma unroll
        for (int jp = 0; jp < 2; jp++) {
            uint32_t off = (uint32_t)((wn + jp * 16 + nb) * RSTR + s * 16 + kb2) * 2;
            uint32_t r[4];
            ldm_x4(r, b_u + off);
            bfh[s][jp * 2][0] = r[0]; bfh[s][jp * 2][1] = r[1];
            bfh[s][jp * 2 + 1][0] = r[2]; bfh[s][jp * 2 + 1][1] = r[3];
            ldm_x4(r, b_u + PLANE_B + off);
            bfl[s][jp * 2][0] = r[0]; bfl[s][jp * 2][1] = r[1];
            bfl[s][jp * 2 + 1][0] = r[2]; bfl[s][jp * 2 + 1][1] = r[3];
        }

    // A fragment double buffer
    uint32_t ah[2][4], al[2][4];
    {
        uint32_t off0 = (uint32_t)((wm + lm) * RSTR + kq) * 2;
        ldm_x4(ah[0], a_u + off0);
        ldm_x4(al[0], a_u + PLANE_B + off0);
    }
#pragma unroll
    for (int t = 0; t < 8; t++) {
        const int s = t >> 2, i = t & 3;
        const int cb = t & 1;
        if (t < 7) {
            const int tn = t + 1, sn = tn >> 2, in = tn & 3;
            uint32_t offn = (uint32_t)((wm + in * 16 + lm) * RSTR + sn * 16 + kq) * 2;
            ldm_x4(ah[cb ^ 1], a_u + offn);
            ldm_x4(al[cb ^ 1], a_u + PLANE_B + offn);
        } else if (tail_sync) {
            CPA_WAIT(0);
            __syncthreads();
        }
#pragma unroll
        for (int j = 0; j < 4; j++) mma_bf16(acc[i][j], ah[cb], bfh[s][j]);
#pragma unroll
        for (int j = 0; j < 4; j++) mma_bf16(acc[i][j], al[cb], bfh[s][j]);
#pragma unroll
        for (int j = 0; j < 4; j++) mma_bf16(acc[i][j], ah[cb], bfl[s][j]);
    }
}

// MLP (K variable, relu, plane output)
__global__ __launch_bounds__(256, 2)
void gemm_mlp_kernel(const __nv_bfloat16* __restrict__ Ah,
                     const __nv_bfloat16* __restrict__ Al,
                     const __nv_bfloat16* __restrict__ Bthi,
                     const __nv_bfloat16* __restrict__ Btlo,
                     const float* __restrict__ bias,
                     __nv_bfloat16* __restrict__ Xh,
                     __nv_bfloat16* __restrict__ Xl, int K)
{
    extern __shared__ __align__(16) char dsm[];
    int tid = threadIdx.x;
    int wid = tid >> 5, lane = tid & 31;
    int g = lane >> 2, t = lane & 3;
    int bm = blockIdx.y * 128, bn = blockIdx.x * 128;
    int wm = (wid & 1) * 64, wn = (wid >> 1) * 32;
    int NC = K >> 5;
    int lm = lane & 15, kq = (lane >> 4) << 3;
    int nb = (lane & 7) + ((lane >> 4) << 3);
    int kb2 = ((lane >> 3) & 1) * 8;

    int fr[2], fc[2];
#pragma unroll
    for (int i = 0; i < 2; i++) { int f = tid + i * 256; fr[i] = f >> 2; fc[i] = (f & 3) * 8; }

    float acc[4][4][4];
#pragma unroll
    for (int i = 0; i < 4; i++)
#pragma unroll
        for (int j = 0; j < 4; j++)
#pragma unroll
            for (int r = 0; r < 4; r++) acc[i][j][r] = 0.f;

    gemm_load_stage(smaddr(dsm), Ah, Al, Bthi, Btlo, bm, bn, 0, K, fr, fc);
    CPA_WAIT(0);
    __syncthreads();

    for (int chunk = 0; chunk < NC; chunk++) {
        uint32_t cur = smaddr(dsm) + (chunk & 1) * STAGE_B;
        bool more = (chunk + 1 < NC);
        if (more)
            gemm_load_stage(smaddr(dsm) + ((chunk + 1) & 1) * STAGE_B,
                            Ah, Al, Bthi, Btlo, bm, bn, (chunk + 1) << 5, K, fr, fc);
        gemm_chunk_pipe(cur, acc, wm, wn, lm, kq, nb, kb2, more);
    }

#pragma unroll
    for (int i = 0; i < 4; i++) {
        int row0 = bm + wm + i * 16 + g;
#pragma unroll
        for (int j = 0; j < 4; j++) {
            int col = bn + wn + j * 8 + t * 2;
            float2 bv = *reinterpret_cast<const float2*>(bias + col);
            float v0 = fmaxf(acc[i][j][0] + bv.x, 0.f);
            float v1 = fmaxf(acc[i][j][1] + bv.y, 0.f);
            float v2 = fmaxf(acc[i][j][2] + bv.x, 0.f);
            float v3 = fmaxf(acc[i][j][3] + bv.y, 0.f);
            size_t i0 = (size_t)row0 * 512 + col;
            size_t i1 = (size_t)(row0 + 8) * 512 + col;
            *reinterpret_cast<uint32_t*>(Xh + i0) = pack_bf16(v0, v1);
            *reinterpret_cast<uint32_t*>(Xl + i0) =
                pack_bf16(v0 - bf16_hi_f(v0), v1 - bf16_hi_f(v1));
            *reinterpret_cast<uint32_t*>(Xh + i1) = pack_bf16(v2, v3);
            *reinterpret_cast<uint32_t*>(Xl + i1) =
                pack_bf16(v2 - bf16_hi_f(v2), v3 - bf16_hi_f(v3));
        }
    }
}

// Fused projections: z selects problem (K=512), plane output.
struct QKVArgs {
    const __nv_bfloat16* Ah[4];
    const __nv_bfloat16* Al[4];
    const __nv_bfloat16* Bh[4];
    const __nv_bfloat16* Bl[4];
    const float* bias[4];
    __nv_bfloat16* Ch[4];
    __nv_bfloat16* Cl[4];
};
__global__ __launch_bounds__(256, 2)
void gemm_qkv_kernel(QKVArgs args)
{
    extern __shared__ __align__(16) char dsm[];
    const int K = 512;
    int z = blockIdx.z;
    const __nv_bfloat16* Ah = args.Ah[z];
    const __nv_bfloat16* Al = args.Al[z];
    const __nv_bfloat16* Bthi = args.Bh[z];
    const __nv_bfloat16* Btlo = args.Bl[z];
    const float* bias = args.bias[z];
    __nv_bfloat16* Chi = args.Ch[z];
    __nv_bfloat16* Clo = args.Cl[z];

    int tid = threadIdx.x;
    int wid = tid >> 5, lane = tid & 31;
    int g = lane >> 2, t = lane & 3;
    int bm = blockIdx.y * 128, bn = blockIdx.x * 128;
    int wm = (wid & 1) * 64, wn = (wid >> 1) * 32;
    const int NC = 16;
    int lm = lane & 15, kq = (lane >> 4) << 3;
    int nb = (lane & 7) + ((lane >> 4) << 3);
    int kb2 = ((lane >> 3) & 1) * 8;

    int fr[2], fc[2];
#pragma unroll
    for (int i = 0; i < 2; i++) { int f = tid + i * 256; fr[i] = f >> 2; fc[i] = (f & 3) * 8; }

    float acc[4][4][4];
#pragma unroll
    for (int i = 0; i < 4; i++)
#pragma unroll
        for (int j = 0; j < 4; j++)
#pragma unroll
            for (int r = 0; r < 4; r++) acc[i][j][r] = 0.f;

    gemm_load_stage(smaddr(dsm), Ah, Al, Bthi, Btlo, bm, bn, 0, K, fr, fc);
    CPA_WAIT(0);
    __syncthreads();

    for (int chunk = 0; chunk < NC; chunk++) {
        uint32_t cur = smaddr(dsm) + (chunk & 1) * STAGE_B;
        bool more = (chunk + 1 < NC);
        if (more)
            gemm_load_stage(smaddr(dsm) + ((chunk + 1) & 1) * STAGE_B,
                            Ah, Al, Bthi, Btlo, bm, bn, (chunk + 1) << 5, K, fr, fc);
        gemm_chunk_pipe(cur, acc, wm, wn, lm, kq, nb, kb2, more);
    }

#pragma unroll
    for (int i = 0; i < 4; i++) {
        int row0 = bm + wm + i * 16 + g;
#pragma unroll
        for (int j = 0; j < 4; j++) {
            int col = bn + wn + j * 8 + t * 2;
            float2 bv = *reinterpret_cast<const float2*>(bias + col);
            float v0 = acc[i][j][0] + bv.x, v1 = acc[i][j][1] + bv.y;
            float v2 = acc[i][j][2] + bv.x, v3 = acc[i][j][3] + bv.y;
            size_t i0 = (size_t)row0 * 512 + col;
            size_t i1 = (size_t)(row0 + 8) * 512 + col;
            *reinterpret_cast<uint32_t*>(Chi + i0) = pack_bf16(v0, v1);
            *reinterpret_cast<uint32_t*>(Clo + i0) =
                pack_bf16(v0 - bf16_hi_f(v0), v1 - bf16_hi_f(v1));
            *reinterpret_cast<uint32_t*>(Chi + i1) = pack_bf16(v2, v3);
            *reinterpret_cast<uint32_t*>(Clo + i1) =
                pack_bf16(v2 - bf16_hi_f(v2), v3 - bf16_hi_f(v3));
        }
    }
}

// ---------------------------------------------------------------------------
// Flash attention: cp.async double-buffered K/V, Q frags in registers.
// OUT=0: write f32 Op + planes. OUT=1: Op += relu(result).
// ---------------------------------------------------------------------------
#define QS 72
#define FPL (64 * QS)
#define FSTG_B (4 * FPL * 2)
#define FL_SMEM (2 * FSTG_B)

template<int OUT>
__global__ __launch_bounds__(256, 2) void flash_bf16_kernel(
    const __nv_bfloat16* __restrict__ Qh, const __nv_bfloat16* __restrict__ Ql,
    const __nv_bfloat16* __restrict__ Kh, const __nv_bfloat16* __restrict__ Kl,
    const __nv_bfloat16* __restrict__ Vh, const __nv_bfloat16* __restrict__ Vl,
    float* __restrict__ Op,
    __nv_bfloat16* __restrict__ Ohp, __nv_bfloat16* __restrict__ Olp)
{
    extern __shared__ __align__(16) char fsm[];

    int tid = threadIdx.x;
    int wid = tid >> 5, lane = tid & 31;
    int g = lane >> 2, t = lane & 3;
    int qt = (SEQ / 128 - 1) - blockIdx.x;
    int h = blockIdx.y, b = blockIdx.z;
    size_t qoff = ((size_t)(b * SEQ + qt * 128)) * EMB + h * DHD;
    size_t kvoff = ((size_t)b * SEQ) * EMB + h * DHD;

    int rb = wid * 16;
    int lm = lane & 15, kq = (lane >> 4) << 3;
    int nbk = (lane & 7) + ((lane >> 4) << 3);
    int kb2 = ((lane >> 3) & 1) * 8;
    int kv = (lane & 7) + ((lane >> 3) & 1) * 8;
    int nv = (lane >> 4) << 3;

    uint32_t qah[4][4], qal[4][4];
    {
        __nv_bfloat16* sQh = reinterpret_cast<__nv_bfloat16*>(fsm);
        __nv_bfloat16* sQl = sQh + 128 * QS;
#pragma unroll
        for (int i = 0; i < 4; i++) {
            int f = tid + i * 256;
            int r = f >> 3, c = (f & 7) * 8;
            *reinterpret_cast<uint4*>(sQh + r * QS + c) =
                *reinterpret_cast<const uint4*>(Qh + qoff + (size_t)r * EMB + c);
            *reinterpret_cast<uint4*>(sQl + r * QS + c) =
                *reinterpret_cast<const uint4*>(Ql + qoff + (size_t)r * EMB + c);
        }
        __syncthreads();
        uint32_t uQh = smaddr(sQh), uQl = smaddr(sQl);
#pragma unroll
        for (int kk = 0; kk < 4; kk++) {
            uint32_t qo = (uint32_t)((rb + lm) * QS + kk * 16 + kq) * 2;
            ldm_x4(qah[kk], uQh + qo);
            ldm_x4(qal[kk], uQl + qo);
        }
        __syncthreads();
    }

    int ktmax = qt * 2 + 1;
    int wmaxrow = qt * 128 + rb + 15;
    int row0g = qt * 128 + rb + g, row1g = row0g + 8;

    int fr[2], fc[2];
#pragma unroll
    for (int i = 0; i < 2; i++) {
        int f = tid + i * 256;
        fr[i] = f >> 3; fc[i] = (f & 7) * 8;
    }

    {
        uint32_t st = smaddr(fsm);
#pragma unroll
        for (int i = 0; i < 2; i++) {
            uint32_t doff = (uint32_t)(fr[i] * QS + fc[i]) * 2;
            size_t go = kvoff + (size_t)fr[i] * EMB + fc[i];
            CPA16(st + doff, Kh + go);
            CPA16(st + FPL * 2 + doff, Kl + go);
            CPA16(st + 2 * FPL * 2 + doff, Vh + go);
            CPA16(st + 3 * FPL * 2 + doff, Vl + go);
        }
        CPA_COMMIT();
    }

    float m0 = -INFINITY, m1 = -INFINITY, l0 = 0.f, l1 = 0.f;
    float acc[8][4];
#pragma unroll
    for (int j = 0; j < 8; j++)
#pragma unroll
        for (int r = 0; r < 4; r++) acc[j][r] = 0.f;

    for (int kt = 0; kt <= ktmax; kt++) {
        uint32_t cur = smaddr(fsm) + (kt & 1) * FSTG_B;
        bool more = (kt < ktmax);
        if (more) {
            uint32_t nxt = smaddr(fsm) + ((kt + 1) & 1) * FSTG_B;
            size_t ko = kvoff + (size_t)(kt + 1) * 64 * EMB;
#pragma unroll
            for (int i = 0; i < 2; i++) {
                uint32_t doff = (uint32_t)(fr[i] * QS + fc[i]) * 2;
                size_t go = ko + (size_t)fr[i] * EMB + fc[i];
                CPA16(nxt + doff, Kh + go);
                CPA16(nxt + FPL * 2 + doff, Kl + go);
                CPA16(nxt + 2 * FPL * 2 + doff, Vh + go);
                CPA16(nxt + 3 * FPL * 2 + doff, Vl + go);
            }
            CPA_COMMIT();
            CPA_WAIT(1);
        } else {
            CPA_WAIT(0);
        }
        __syncthreads();

        if (kt * 64 <= wmaxrow) {
            uint32_t uKh = cur, uKl = cur + FPL * 2;
            uint32_t uVh = cur + 2 * FPL * 2, uVl = cur + 3 * FPL * 2;

            float s[8][4];
#pragma unroll
            for (int j = 0; j < 8; j++)
#pragma unroll
                for (int r = 0; r < 4; r++) s[j][r] = 0.f;
#pragma unroll
            for (int kk = 0; kk < 4; kk++) {
#pragma unroll
                for (int jp = 0; jp < 4; jp++) {
                    uint32_t koff = (uint32_t)((jp * 16 + nbk) * QS + kk * 16 + kb2) * 2;
                    uint32_t rh[4], rl[4];
                    ldm_x4(rh, uKh + koff);
                    ldm_x4(rl, uKl + koff);
                    uint32_t b0[2] = { rh[0], rh[1] }, b1[2] = { rh[2], rh[3] };
                    uint32_t c0[2] = { rl[0], rl[1] }, c1[2] = { rl[2], rl[3] };
                    mma_bf16(s[2 * jp],     qah[kk], b0);
                    mma_bf16(s[2 * jp + 1], qah[kk], b1);
                    mma_bf16(s[2 * jp],     qal[kk], b0);
                    mma_bf16(s[2 * jp + 1], qal[kk], b1);
                    mma_bf16(s[2 * jp],     qah[kk], c0);
                    mma_bf16(s[2 * jp + 1], qah[kk], c1);
                }
            }

            int colb = kt * 64 + t * 2;
#pragma unroll
            for (int j = 0; j < 8; j++) {
                int c0 = colb + j * 8, c1 = c0 + 1;
                s[j][0] = (c0 > row0g) ? -INFINITY : s[j][0] * ATTN_SCALE;
                s[j][1] = (c1 > row0g) ? -INFINITY : s[j][1] * ATTN_SCALE;
                s[j][2] = (c0 > row1g) ? -INFINITY : s[j][2] * ATTN_SCALE;
                s[j][3] = (c1 > row1g) ? -INFINITY : s[j][3] * ATTN_SCALE;
            }

            float tm0 = -INFINITY, tm1 = -INFINITY;
#pragma unroll
            for (int j = 0; j < 8; j++) {
                tm0 = fmaxf(tm0, fmaxf(s[j][0], s[j][1]));
                tm1 = fmaxf(tm1, fmaxf(s[j][2], s[j][3]));
            }
            tm0 = fmaxf(tm0, __shfl_xor_sync(0xFFFFFFFFu, tm0, 1));
            tm0 = fmaxf(tm0, __shfl_xor_sync(0xFFFFFFFFu, tm0, 2));
            tm1 = fmaxf(tm1, __shfl_xor_sync(0xFFFFFFFFu, tm1, 1));
            tm1 = fmaxf(tm1, __shfl_xor_sync(0xFFFFFFFFu, tm1, 2));
            float m0n = fmaxf(m0, tm0), m1n = fmaxf(m1, tm1);
            float ms0 = fmaxf(m0n, -1e30f), ms1 = fmaxf(m1n, -1e30f);
            float alpha0 = __expf(m0 - ms0), alpha1 = __expf(m1 - ms1);
            m0 = m0n; m1 = m1n;
#pragma unroll
            for (int j = 0; j < 8; j++) {
                acc[j][0] *= alpha0; acc[j][1] *= alpha0;
                acc[j][2] *= alpha1; acc[j][3] *= alpha1;
            }

            float ps0 = 0.f, ps1 = 0.f;
#pragma unroll
            for (int kk = 0; kk < 4; kk++) {
                int j0 = 2 * kk, j1 = 2 * kk + 1;
                float p00 = __expf(s[j0][0] - ms0), p01 = __expf(s[j0][1] - ms0);
                float p02 = __expf(s[j0][2] - ms1), p03 = __expf(s[j0][3] - ms1);
                float p10 = __expf(s[j1][0] - ms0), p11 = __expf(s[j1][1] - ms0);
                float p12 = __expf(s[j1][2] - ms1), p13 = __expf(s[j1][3] - ms1);
                ps0 += p00 + p01 + p10 + p11;
                ps1 += p02 + p03 + p12 + p13;
                uint32_t pah[4], pal[4];
                pah[0] = pack_bf16(p00, p01);
                pah[1] = pack_bf16(p02, p03);
                pah[2] = pack_bf16(p10, p11);
                pah[3] = pack_bf16(p12, p13);
                pal[0] = pack_bf16(p00 - bf16_hi_f(p00), p01 - bf16_hi_f(p01));
                pal[1] = pack_bf16(p02 - bf16_hi_f(p02), p03 - bf16_hi_f(p03));
                pal[2] = pack_bf16(p10 - bf16_hi_f(p10), p11 - bf16_hi_f(p11));
                pal[3] = pack_bf16(p12 - bf16_hi_f(p12), p13 - bf16_hi_f(p13));
#pragma unroll
                for (int jdp = 0; jdp < 4; jdp++) {
                    uint32_t voff = (uint32_t)((kk * 16 + kv) * QS + jdp * 16 + nv) * 2;
                    uint32_t rh[4], rl[4];
                    ldm_x4t(rh, uVh + voff);
                    ldm_x4t(rl, uVl + voff);
                    uint32_t b0[2] = { rh[0], rh[1] }, b1[2] = { rh[2], rh[3] };
                    uint32_t c0[2] = { rl[0], rl[1] }, c1[2] = { rl[2], rl[3] };
                    mma_bf16(acc[2 * jdp],     pah, b0);
                    mma_bf16(acc[2 * jdp + 1], pah, b1);
                    mma_bf16(acc[2 * jdp],     pal, b0);
                    mma_bf16(acc[2 * jdp + 1], pal, b1);
                    mma_bf16(acc[2 * jdp],     pah, c0);
                    mma_bf16(acc[2 * jdp + 1], pah, c1);
                }
            }
            ps0 += __shfl_xor_sync(0xFFFFFFFFu, ps0, 1);
            ps0 += __shfl_xor_sync(0xFFFFFFFFu, ps0, 2);
            ps1 += __shfl_xor_sync(0xFFFFFFFFu, ps1, 1);
            ps1 += __shfl_xor_sync(0xFFFFFFFFu, ps1, 2);
            l0 = l0 * alpha0 + ps0;
            l1 = l1 * alpha1 + ps1;
        }
        __syncthreads();
    }

    float inv0 = 1.f / l0, inv1 = 1.f / l1;
#pragma unroll
    for (int jd = 0; jd < 8; jd++) {
        int c = jd * 8 + t * 2;
        size_t i0 = qoff + (size_t)(rb + g) * EMB + c;
        size_t i1 = qoff + (size_t)(rb + g + 8) * EMB + c;
        float o00 = acc[jd][0] * inv0, o01 = acc[jd][1] * inv0;
        float o10 = acc[jd][2] * inv1, o11 = acc[jd][3] * inv1;
        if (OUT == 0) {
            *reinterpret_cast<float2*>(Op + i0) = make_float2(o00, o01);
            *reinterpret_cast<float2*>(Op + i1) = make_float2(o10, o11);
            *reinterpret_cast<uint32_t*>(Ohp + i0) = pack_bf16(o00, o01);
            *reinterpret_cast<uint32_t*>(Olp + i0) =
                pack_bf16(o00 - bf16_hi_f(o00), o01 - bf16_hi_f(o01));
            *reinterpret_cast<uint32_t*>(Ohp + i1) = pack_bf16(o10, o11);
            *reinterpret_cast<uint32_t*>(Olp + i1) =
                pack_bf16(o10 - bf16_hi_f(o10), o11 - bf16_hi_f(o11));
        } else {
            float2 e0 = *reinterpret_cast<float2*>(Op + i0);
            float2 e1 = *reinterpret_cast<float2*>(Op + i1);
            *reinterpret_cast<float2*>(Op + i0) =
                make_float2(e0.x + fmaxf(o00, 0.f), e0.y + fmaxf(o01, 0.f));
            *reinterpret_cast<float2*>(Op + i1) =
                make_float2(e1.x + fmaxf(o10, 0.f), e1.y + fmaxf(o11, 0.f));
        }
    }
}

// ---------------------------------------------------------------------------
__global__ __launch_bounds__(256) void out_proj_kernel(
    const float* __restrict__ out, const float* __restrict__ Wout,
    const float* __restrict__ bout, float* __restrict__ y)
{
    int g = blockIdx.x * 8 + (threadIdx.x >> 5);
    int lane = threadIdx.x & 31;
    const float4* o4 = reinterpret_cast<const float4*>(out + (size_t)g * EMB);
    const float4* w4 = reinterpret_cast<const float4*>(Wout);
    float s = 0.f;
#pragma unroll
    for (int i = 0; i < 4; i++) {
        float4 a = o4[lane + 32 * i];
        float4 b = w4[lane + 32 * i];
        s += a.x * b.x + a.y * b.y + a.z * b.z + a.w * b.w;
    }
#pragma unroll
    for (int off = 16; off > 0; off >>= 1)
        s += __shfl_xor_sync(0xFFFFFFFFu, s, off);
    if (lane == 0) y[g] = s + bout[0];
}

// ---------------------------------------------------------------------------
extern "C" void kernel_launch(void* const* d_in, const int* in_sizes, int n_in,
                              void* d_out, int out_size)
{
    const int*   item_inputs  = (const int*)d_in[0];
    const int*   skill_inputs = (const int*)d_in[1];
    const int*   label_inputs = (const int*)d_in[2];
    const int*   item_ids     = (const int*)d_in[3];
    const int*   skill_ids    = (const int*)d_in[4];
    const float* item_emb     = (const float*)d_in[5];
    const float* skill_emb    = (const float*)d_in[6];
    const float* W_in         = (const float*)d_in[7];
    const float* b_in         = (const float*)d_in[8];
    const float* Wq           = (const float*)d_in[9];
    const float* bq           = (const float*)d_in[10];
    const float* Wk           = (const float*)d_in[11];
    const float* bk           = (const float*)d_in[12];
    const float* Wv           = (const float*)d_in[13];
    const float* bv           = (const float*)d_in[14];
    const float* W_out        = (const float*)d_in[22];
    const float* b_out        = (const float*)d_in[23];
    float* y = (float*)d_out;

    float* outb;
    __nv_bfloat16 *w, *ih, *il, *qrh, *qrl, *xh, *xl, *oh, *ol;
    __nv_bfloat16 *q1h, *q1l, *q2h, *q2l, *kh, *kl, *vh, *vl;
    cudaGetSymbolAddress((void**)&outb, g_outb);
    cudaGetSymbolAddress((void**)&w,    g_W);
    cudaGetSymbolAddress((void**)&ih,   g_Ih);
    cudaGetSymbolAddress((void**)&il,   g_Il);
    cudaGetSymbolAddress((void**)&qrh,  g_QRh);
    cudaGetSymbolAddress((void**)&qrl,  g_QRl);
    cudaGetSymbolAddress((void**)&xh,   g_Xh);
    cudaGetSymbolAddress((void**)&xl,   g_Xl);
    cudaGetSymbolAddress((void**)&oh,   g_Oh);
    cudaGetSymbolAddress((void**)&ol,   g_Ol);
    cudaGetSymbolAddress((void**)&q1h,  g_Q1h);
    cudaGetSymbolAddress((void**)&q1l,  g_Q1l);
    cudaGetSymbolAddress((void**)&q2h,  g_Q2h);
    cudaGetSymbolAddress((void**)&q2l,  g_Q2l);
    cudaGetSymbolAddress((void**)&kh,   g_Kh);
    cudaGetSymbolAddress((void**)&kl,   g_Kl);
    cudaGetSymbolAddress((void**)&vh,   g_Vh);
    cudaGetSymbolAddress((void**)&vl,   g_Vl);

    cudaFuncSetAttribute(flash_bf16_kernel<0>,
                         cudaFuncAttributeMaxDynamicSharedMemorySize, FL_SMEM);
    cudaFuncSetAttribute(flash_bf16_kernel<1>,
                         cudaFuncAttributeMaxDynamicSharedMemorySize, FL_SMEM);
    cudaFuncSetAttribute(gemm_mlp_kernel,
                         cudaFuncAttributeMaxDynamicSharedMemorySize, GEMM_SMEM);
    cudaFuncSetAttribute(gemm_qkv_kernel,
                         cudaFuncAttributeMaxDynamicSharedMemorySize, GEMM_SMEM);

    __nv_bfloat16* win_hi = w;
    __nv_bfloat16* win_lo = w + 512 * 1024;
    __nv_bfloat16* qkv_hi[2][3];
    __nv_bfloat16* qkv_lo[2][3];
    {
        __nv_bfloat16* p = w + 2 * 512 * 1024;
        for (int l = 0; l < 2; l++)
            for (int m = 0; m < 3; m++) {
                qkv_hi[l][m] = p; p += 512 * 512;
                qkv_lo[l][m] = p; p += 512 * 512;
            }
    }

    gather_kernel<<<TOT, 128>>>(item_inputs, skill_inputs, label_inputs,
                                item_ids, skill_ids, item_emb, skill_emb,
                                ih, il, qrh, qrl);
    transpose_cvt_kernel<<<dim3(16, 32), 256>>>(W_in, win_hi, win_lo, 1024, 512);
    {
        TrArgs ta;
        const float* srcs[3] = { Wq, Wk, Wv };
        for (int l = 0; l < 2; l++)
            for (int m = 0; m < 3; m++) {
                ta.src[l * 3 + m] = srcs[m] + (size_t)l * 512 * 512;
                ta.dhi[l * 3 + m] = qkv_hi[l][m];
                ta.dlo[l * 3 + m] = qkv_lo[l][m];
            }
        transpose_qkv_kernel<<<dim3(16, 16, 6), 256>>>(ta);
    }
    gemm_mlp_kernel<<<dim3(4, 128), 256, GEMM_SMEM>>>(
        ih, il, win_hi, win_lo, b_in, xh, xl, 1024);

    // fused Q1,K1,V1,Q2
    {
        QKVArgs qa;
        qa.Ah[0] = qrh; qa.Al[0] = qrl;
        qa.Ah[1] = xh;  qa.Al[1] = xl;
        qa.Ah[2] = xh;  qa.Al[2] = xl;
        qa.Ah[3] = qrh; qa.Al[3] = qrl;
        qa.Bh[0] = qkv_hi[0][0]; qa.Bl[0] = qkv_lo[0][0];
        qa.Bh[1] = qkv_hi[0][1]; qa.Bl[1] = qkv_lo[0][1];
        qa.Bh[2] = qkv_hi[0][2]; qa.Bl[2] = qkv_lo[0][2];
        qa.Bh[3] = qkv_hi[1][0]; qa.Bl[3] = qkv_lo[1][0];
        qa.bias[0] = bq; qa.bias[1] = bk; qa.bias[2] = bv; qa.bias[3] = bq + EMB;
        qa.Ch[0] = q1h; qa.Cl[0] = q1l;
        qa.Ch[1] = kh;  qa.Cl[1] = kl;
        qa.Ch[2] = vh;  qa.Cl[2] = vl;
        qa.Ch[3] = q2h; qa.Cl[3] = q2l;
        gemm_qkv_kernel<<<dim3(4, 128, 4), 256, GEMM_SMEM>>>(qa);
    }
    flash_bf16_kernel<0><<<dim3(SEQ / 128, NH, Bsz), 256, FL_SMEM>>>(
        q1h, q1l, kh, kl, vh, vl, outb, oh, ol);
    // fused K2,V2
    {
        QKVArgs qa;
        qa.Ah[0] = oh; qa.Al[0] = ol;
        qa.Ah[1] = oh; qa.Al[1] = ol;
        qa.Ah[2] = oh; qa.Al[2] = ol;
        qa.Ah[3] = oh; qa.Al[3] = ol;
        qa.Bh[0] = qkv_hi[1][1]; qa.Bl[0] = qkv_lo[1][1];
        qa.Bh[1] = qkv_hi[1][2]; qa.Bl[1] = qkv_lo[1][2];
        qa.Bh[2] = qkv_hi[1][1]; qa.Bl[2] = qkv_lo[1][1];
        qa.Bh[3] = qkv_hi[1][2]; qa.Bl[3] = qkv_lo[1][2];
        qa.bias[0] = bk + EMB; qa.bias[1] = bv + EMB;
        qa.bias[2] = bk + EMB; qa.bias[3] = bv + EMB;
        qa.Ch[0] = kh; qa.Cl[0] = kl;
        qa.Ch[1] = vh; qa.Cl[1] = vl;
        qa.Ch[2] = kh; qa.Cl[2] = kl;
        qa.Ch[3] = vh; qa.Cl[3] = vl;
        gemm_qkv_kernel<<<dim3(4, 128, 2), 256, GEMM_SMEM>>>(qa);
    }
    flash_bf16_kernel<1><<<dim3(SEQ / 128, NH, Bsz), 256, FL_SMEM>>>(
        q2h, q2l, kh, kl, vh, vl, outb, nullptr, nullptr);

    out_proj_kernel<<<TOT / 8, 256>>>(outb, W_out, b_out, y);
}

// round 11
// speedup vs baseline: 3.5006x; 1.0688x over previous
#include <cuda_runtime.h>
#include <cuda_bf16.h>
#include <cstdint>

// ---------------------------------------------------------------------------
// TSAKT: gather -> ReLU MLP -> 2x causal MHA -> output proj.
// glo/ts biases are key-constant pre-mask => softmax-shift-invariant => dropped.
// R11: labels are binary => half the MLP K-dim is exact zeros per row.
//      Partition rows by label; MLP is K=512 with per-tile weight-half
//      selection (exact). Flash CTAs pair heavy+light q-tiles (balanced).
// ---------------------------------------------------------------------------

#define Bsz 32
#define SEQ 512
#define EMB 512
#define NH  8
#define DHD 64
#define TOT (Bsz * SEQ)
#define ATTN_SCALE 0.125f

// ---- device scratch ---------------------------------------------------------
__device__ float g_outb [(size_t)TOT * EMB];
__device__ __nv_bfloat16 g_W[2 * 512 * 1024 + 12 * 512 * 512];
__device__ __nv_bfloat16 g_Hh[(size_t)TOT * 512],  g_Hl[(size_t)TOT * 512];
__device__ __nv_bfloat16 g_QRh[(size_t)TOT * EMB], g_QRl[(size_t)TOT * EMB];
__device__ __nv_bfloat16 g_Xh[(size_t)TOT * EMB],  g_Xl[(size_t)TOT * EMB];
__device__ __nv_bfloat16 g_Oh[(size_t)TOT * EMB],  g_Ol[(size_t)TOT * EMB];
__device__ __nv_bfloat16 g_Q1h[(size_t)TOT * EMB], g_Q1l[(size_t)TOT * EMB];
__device__ __nv_bfloat16 g_Q2h[(size_t)TOT * EMB], g_Q2l[(size_t)TOT * EMB];
__device__ __nv_bfloat16 g_Kh[(size_t)TOT * EMB],  g_Kl[(size_t)TOT * EMB];
__device__ __nv_bfloat16 g_Vh[(size_t)TOT * EMB],  g_Vl[(size_t)TOT * EMB];
__device__ int g_perm[TOT];
__device__ int g_n1;
__device__ __align__(16) __nv_bfloat16 g_zero16[8];   // zero-initialized

// ---------------------------------------------------------------------------
__device__ __forceinline__ uint32_t pack_bf16(float x, float y) {
    __nv_bfloat162 h = __floats2bfloat162_rn(x, y);
    return *reinterpret_cast<uint32_t*>(&h);
}
__device__ __forceinline__ float bf16_hi_f(float x) {
    return __bfloat162float(__float2bfloat16_rn(x));
}
__device__ __forceinline__ void mma_bf16(float* c, const uint32_t* a, const uint32_t* b) {
    asm volatile(
        "mma.sync.aligned.m16n8k16.row.col.f32.bf16.bf16.f32 "
        "{%0,%1,%2,%3}, {%4,%5,%6,%7}, {%8,%9}, {%0,%1,%2,%3};"
        : "+f"(c[0]), "+f"(c[1]), "+f"(c[2]), "+f"(c[3])
        : "r"(a[0]), "r"(a[1]), "r"(a[2]), "r"(a[3]), "r"(b[0]), "r"(b[1]));
}
__device__ __forceinline__ void ldm_x4(uint32_t* r, uint32_t a) {
    asm volatile("ldmatrix.sync.aligned.m8n8.x4.shared.b16 {%0,%1,%2,%3}, [%4];"
        : "=r"(r[0]), "=r"(r[1]), "=r"(r[2]), "=r"(r[3]) : "r"(a));
}
__device__ __forceinline__ void ldm_x4t(uint32_t* r, uint32_t a) {
    asm volatile("ldmatrix.sync.aligned.m8n8.x4.trans.shared.b16 {%0,%1,%2,%3}, [%4];"
        : "=r"(r[0]), "=r"(r[1]), "=r"(r[2]), "=r"(r[3]) : "r"(a));
}
__device__ __forceinline__ uint32_t smaddr(const void* p) {
    return (uint32_t)__cvta_generic_to_shared(p);
}
#define CPA16(dst, src) \
    asm volatile("cp.async.cg.shared.global [%0], [%1], 16;" :: "r"(dst), "l"(src))
#define CPA_COMMIT() asm volatile("cp.async.commit_group;")
#define CPA_WAIT(n)  asm volatile("cp.async.wait_group %0;" :: "n"(n))

__device__ __forceinline__ void cvt_store4(float4 v, __nv_bfloat16* hi, __nv_bfloat16* lo) {
    float hx = bf16_hi_f(v.x), hy = bf16_hi_f(v.y);
    float hz = bf16_hi_f(v.z), hw = bf16_hi_f(v.w);
    *reinterpret_cast<uint2*>(hi) = make_uint2(pack_bf16(v.x, v.y), pack_bf16(v.z, v.w));
    *reinterpret_cast<uint2*>(lo) = make_uint2(pack_bf16(v.x - hx, v.y - hy),
                                               pack_bf16(v.z - hz, v.w - hw));
}

// ---------------------------------------------------------------------------
// Stable partition of rows by label (lab=1 first). One block, deterministic.
// ---------------------------------------------------------------------------
__global__ __launch_bounds__(512) void partition_kernel(
    const int* __restrict__ labels, int* __restrict__ perm, int* __restrict__ n1out)
{
    __shared__ int s[512];
    __shared__ int tot1;
    int tid = threadIdx.x;
    int base = tid * 32;
    int c = 0;
#pragma unroll
    for (int i = 0; i < 32; i++) c += labels[base + i];
    s[tid] = c;
    __syncthreads();
    for (int off = 1; off < 512; off <<= 1) {
        int v = (tid >= off) ? s[tid - off] : 0;
        __syncthreads();
        if (tid >= off) s[tid] += v;
        __syncthreads();
    }
    int incl = s[tid];
    int excl = incl - c;
    if (tid == 511) { tot1 = incl; *n1out = incl; }
    __syncthreads();
    int p1 = excl;
    int p0 = tot1 + base - excl;
    for (int i = 0; i < 32; i++) {
        int g = base + i;
        if (labels[g]) perm[p1++] = g;
        else           perm[p0++] = g;
    }
}

// ---------------------------------------------------------------------------
// Gather: emits half planes [g,512] and query planes [g,512]
// ---------------------------------------------------------------------------
__global__ __launch_bounds__(128) void gather_kernel(
    const int* __restrict__ item_inputs, const int* __restrict__ skill_inputs,
    const int* __restrict__ item_ids, const int* __restrict__ skill_ids,
    const float* __restrict__ item_emb, const float* __restrict__ skill_emb,
    __nv_bfloat16* __restrict__ Hh, __nv_bfloat16* __restrict__ Hl,
    __nv_bfloat16* __restrict__ QRh, __nv_bfloat16* __restrict__ QRl)
{
    int g = blockIdx.x;
    int t = threadIdx.x;
    size_t hb = (size_t)g * 512, qb = (size_t)g * 512;
    if (t < 64) {
        const float4* ie = reinterpret_cast<const float4*>(item_emb + (size_t)item_inputs[g] * 256);
        cvt_store4(ie[t], Hh + hb + t * 4, Hl + hb + t * 4);
        const float4* qe = reinterpret_cast<const float4*>(item_emb + (size_t)item_ids[g] * 256);
        cvt_store4(qe[t], QRh + qb + t * 4, QRl + qb + t * 4);
    } else {
        int u = t - 64;
        const float4* se = reinterpret_cast<const float4*>(skill_emb + (size_t)skill_inputs[g] * 256);
        cvt_store4(se[u], Hh + hb + 256 + u * 4, Hl + hb + 256 + u * 4);
        const float4* qs = reinterpret_cast<const float4*>(skill_emb + (size_t)skill_ids[g] * 256);
        cvt_store4(qs[u], QRh + qb + 256 + u * 4, QRl + qb + 256 + u * 4);
    }
}

// ---------------------------------------------------------------------------
// Weight transposes (+ bf16 hi/lo split)
// ---------------------------------------------------------------------------
__global__ __launch_bounds__(256) void transpose_cvt_kernel(
    const float* __restrict__ src, __nv_bfloat16* __restrict__ dhi,
    __nv_bfloat16* __restrict__ dlo, int K, int N)
{
    __shared__ float t[32][33];
    int bx = blockIdx.x * 32, by = blockIdx.y * 32;
    int x = threadIdx.x & 31, y0 = threadIdx.x >> 5;
#pragma unroll
    for (int j = 0; j < 32; j += 8)
        t[y0 + j][x] = src[(size_t)(by + y0 + j) * N + bx + x];
    __syncthreads();
#pragma unroll
    for (int j = 0; j < 32; j += 8) {
        float v = t[x][y0 + j];
        float h = bf16_hi_f(v);
        size_t idx = (size_t)(bx + y0 + j) * K + by + x;
        dhi[idx] = __float2bfloat16_rn(v);
        dlo[idx] = __float2bfloat16_rn(v - h);
    }
}

struct TrArgs {
    const float* src[6];
    __nv_bfloat16* dhi[6];
    __nv_bfloat16* dlo[6];
};
__global__ __launch_bounds__(256) void transpose_qkv_kernel(TrArgs a)
{
    __shared__ float t[32][33];
    int z = blockIdx.z;
    const float* src = a.src[z];
    __nv_bfloat16* dhi = a.dhi[z];
    __nv_bfloat16* dlo = a.dlo[z];
    int bx = blockIdx.x * 32, by = blockIdx.y * 32;
    int x = threadIdx.x & 31, y0 = threadIdx.x >> 5;
#pragma unroll
    for (int j = 0; j < 32; j += 8)
        t[y0 + j][x] = src[(size_t)(by + y0 + j) * 512 + bx + x];
    __syncthreads();
#pragma unroll
    for (int j = 0; j < 32; j += 8) {
        float v = t[x][y0 + j];
        float h = bf16_hi_f(v);
        size_t idx = (size_t)(bx + y0 + j) * 512 + by + x;
        dhi[idx] = __float2bfloat16_rn(v);
        dlo[idx] = __float2bfloat16_rn(v - h);
    }
}

// ---------------------------------------------------------------------------
// GEMM shared machinery: 128x128 tile, 8 warps, K-chunk 32, double buffer.
// ---------------------------------------------------------------------------
#define RSTR 40
#define PLANE_B (128 * RSTR * 2)
#define STAGE_B (4 * PLANE_B)
#define GEMM_SMEM (2 * STAGE_B)

// Software-pipelined chunk (from R10): B frags hoisted, A double-buffered,
// optional tail sync overlapped with the final MMA group.
__device__ __forceinline__ void gemm_chunk_pipe(
    uint32_t cur, float (&acc)[4][4][4], int wm, int wn,
    int lm, int kq, int nb, int kb2, bool tail_sync)
{
    uint32_t a_u = cur;
    uint32_t b_u = cur + 2 * PLANE_B;

    uint32_t bfh[2][4][2], bfl[2][4][2];
#pragma unroll
    for (int s = 0; s < 2; s++)
#pragma unroll
        for (int jp = 0; jp < 2; jp++) {
            uint32_t off = (uint32_t)((wn + jp * 16 + nb) * RSTR + s * 16 + kb2) * 2;
            uint32_t r[4];
            ldm_x4(r, b_u + off);
            bfh[s][jp * 2][0] = r[0]; bfh[s][jp * 2][1] = r[1];
            bfh[s][jp * 2 + 1][0] = r[2]; bfh[s][jp * 2 + 1][1] = r[3];
            ldm_x4(r, b_u + PLANE_B + off);
            bfl[s][jp * 2][0] = r[0]; bfl[s][jp * 2][1] = r[1];
            bfl[s][jp * 2 + 1][0] = r[2]; bfl[s][jp * 2 + 1][1] = r[3];
        }

    uint32_t ah[2][4], al[2][4];
    {
        uint32_t off0 = (uint32_t)((wm + lm) * RSTR + kq) * 2;
        ldm_x4(ah[0], a_u + off0);
        ldm_x4(al[0], a_u + PLANE_B + off0);
    }
#pragma unroll
    for (int t = 0; t < 8; t++) {
        const int s = t >> 2, i = t & 3;
        const int cb = t & 1;
        if (t < 7) {
            const int tn = t + 1, sn = tn >> 2, in = tn & 3;
            uint32_t offn = (uint32_t)((wm + in * 16 + lm) * RSTR + sn * 16 + kq) * 2;
            ldm_x4(ah[cb ^ 1], a_u + offn);
            ldm_x4(al[cb ^ 1], a_u + PLANE_B + offn);
        } else if (tail_sync) {
            CPA_WAIT(0);
            __syncthreads();
        }
#pragma unroll
        for (int j = 0; j < 4; j++) mma_bf16(acc[i][j], ah[cb], bfh[s][j]);
#pragma unroll
        for (int j = 0; j < 4; j++) mma_bf16(acc[i][j], al[cb], bfh[s][j]);
#pragma unroll
        for (int j = 0; j < 4; j++) mma_bf16(acc[i][j], ah[cb], bfl[s][j]);
    }
}

// ---------------------------------------------------------------------------
// MLP GEMM over partitioned rows (K=512 per pass, weight-half selected).
// Wh/Wl are the [512,1024] transposed W_in planes; W1 = cols 0..511,
// W2 = cols 512..1023 (base offset, row stride 1024).
// Homogeneous tile: 16 chunks. Mixed boundary tile: 32 chunks, rows of the
// non-matching label read from a zero buffer (exact).
// ---------------------------------------------------------------------------
__global__ __launch_bounds__(256, 2)
void gemm_mlp_kernel(const __nv_bfloat16* __restrict__ Hh,
                     const __nv_bfloat16* __restrict__ Hl,
                     const __nv_bfloat16* __restrict__ Wh,
                     const __nv_bfloat16* __restrict__ Wl,
                     const float* __restrict__ bias,
                     __nv_bfloat16* __restrict__ Xh,
                     __nv_bfloat16* __restrict__ Xl,
                     const int* __restrict__ perm,
                     const int* __restrict__ n1p)
{
    extern __shared__ __align__(16) char dsm[];
    int tid = threadIdx.x;
    int wid = tid >> 5, lane = tid & 31;
    int g = lane >> 2, t = lane & 3;
    int bm = blockIdx.y * 128, bn = blockIdx.x * 128;
    int wm = (wid & 1) * 64, wn = (wid >> 1) * 32;
    int lm = lane & 15, kq = (lane >> 4) << 3;
    int nb = (lane & 7) + ((lane >> 4) << 3);
    int kb2 = ((lane >> 3) & 1) * 8;

    int n1 = *n1p;
    int mode = (bm + 128 <= n1) ? 0 : ((bm >= n1) ? 1 : 2);
    int NC = (mode == 2) ? 32 : 16;

    int fr[2], fc[2];
#pragma unroll
    for (int i = 0; i < 2; i++) { int f = tid + i * 256; fr[i] = f >> 2; fc[i] = (f & 3) * 8; }

    // A row bases (permuted), per-row label from sorted position
    const __nv_bfloat16* rAh[2];
    const __nv_bfloat16* rAl[2];
    bool is1[2];
#pragma unroll
    for (int i = 0; i < 2; i++) {
        int pos = bm + fr[i];
        int pr = perm[pos];
        rAh[i] = Hh + (size_t)pr * 512;
        rAl[i] = Hl + (size_t)pr * 512;
        is1[i] = pos < n1;
    }

    float acc[4][4][4];
#pragma unroll
    for (int i = 0; i < 4; i++)
#pragma unroll
        for (int j = 0; j < 4; j++)
#pragma unroll
            for (int r = 0; r < 4; r++) acc[i][j][r] = 0.f;

    // loader lambda (manual): chunk index selects pass/k0/B-half/A-mask
    auto load_stage = [&](uint32_t st, int ci) {
        int pass = (mode == 2) ? (ci >> 4) : mode;
        int k0 = (ci & 15) << 5;
        const __nv_bfloat16* Bh = Wh + (pass ? 512 : 0);
        const __nv_bfloat16* Bl = Wl + (pass ? 512 : 0);
#pragma unroll
        for (int i = 0; i < 2; i++) {
            uint32_t doff = (uint32_t)(fr[i] * RSTR + fc[i]) * 2;
            bool on = (mode != 2) || ((pass == 0) ? is1[i] : !is1[i]);
            const __nv_bfloat16* sah = on ? (rAh[i] + k0 + fc[i]) : g_zero16;
            const __nv_bfloat16* sal = on ? (rAl[i] + k0 + fc[i]) : g_zero16;
            CPA16(st + doff, sah);
            CPA16(st + PLANE_B + doff, sal);
            size_t gb = (size_t)(bn + fr[i]) * 1024 + k0 + fc[i];
            CPA16(st + 2 * PLANE_B + doff, Bh + gb);
            CPA16(st + 3 * PLANE_B + doff, Bl + gb);
        }
        CPA_COMMIT();
    };

    load_stage(smaddr(dsm), 0);
    CPA_WAIT(0);
    __syncthreads();

    for (int chunk = 0; chunk < NC; chunk++) {
        uint32_t cur = smaddr(dsm) + (chunk & 1) * STAGE_B;
        bool more = (chunk + 1 < NC);
        if (more)
            load_stage(smaddr(dsm) + ((chunk + 1) & 1) * STAGE_B, chunk + 1);
        gemm_chunk_pipe(cur, acc, wm, wn, lm, kq, nb, kb2, more);
    }

#pragma unroll
    for (int i = 0; i < 4; i++) {
        int pos0 = bm + wm + i * 16 + g;
        int orow0 = perm[pos0];
        int orow1 = perm[pos0 + 8];
#pragma unroll
        for (int j = 0; j < 4; j++) {
            int col = bn + wn + j * 8 + t * 2;
            float2 bv = *reinterpret_cast<const float2*>(bias + col);
            float v0 = fmaxf(acc[i][j][0] + bv.x, 0.f);
            float v1 = fmaxf(acc[i][j][1] + bv.y, 0.f);
            float v2 = fmaxf(acc[i][j][2] + bv.x, 0.f);
            float v3 = fmaxf(acc[i][j][3] + bv.y, 0.f);
            size_t i0 = (size_t)orow0 * 512 + col;
            size_t i1 = (size_t)orow1 * 512 + col;
            *reinterpret_cast<uint32_t*>(Xh + i0) = pack_bf16(v0, v1);
            *reinterpret_cast<uint32_t*>(Xl + i0) =
                pack_bf16(v0 - bf16_hi_f(v0), v1 - bf16_hi_f(v1));
            *reinterpret_cast<uint32_t*>(Xh + i1) = pack_bf16(v2, v3);
            *reinterpret_cast<uint32_t*>(Xl + i1) =
                pack_bf16(v2 - bf16_hi_f(v2), v3 - bf16_hi_f(v3));
        }
    }
}

// ---------------------------------------------------------------------------
// Fused projections: z selects problem (K=512), plane output.
// ---------------------------------------------------------------------------
struct QKVArgs {
    const __nv_bfloat16* Ah[4];
    const __nv_bfloat16* Al[4];
    const __nv_bfloat16* Bh[4];
    const __nv_bfloat16* Bl[4];
    const float* bias[4];
    __nv_bfloat16* Ch[4];
    __nv_bfloat16* Cl[4];
};
__global__ __launch_bounds__(256, 2)
void gemm_qkv_kernel(QKVArgs args)
{
    extern __shared__ __align__(16) char dsm[];
    const int K = 512;
    int z = blockIdx.z;
    const __nv_bfloat16* Ah = args.Ah[z];
    const __nv_bfloat16* Al = args.Al[z];
    const __nv_bfloat16* Bthi = args.Bh[z];
    const __nv_bfloat16* Btlo = args.Bl[z];
    const float* bias = args.bias[z];
    __nv_bfloat16* Chi = args.Ch[z];
    __nv_bfloat16* Clo = args.Cl[z];

    int tid = threadIdx.x;
    int wid = tid >> 5, lane = tid & 31;
    int g = lane >> 2, t = lane & 3;
    int bm = blockIdx.y * 128, bn = blockIdx.x * 128;
    int wm = (wid & 1) * 64, wn = (wid >> 1) * 32;
    const int NC = 16;
    int lm = lane & 15, kq = (lane >> 4) << 3;
    int nb = (lane & 7) + ((lane >> 4) << 3);
    int kb2 = ((lane >> 3) & 1) * 8;

    int fr[2], fc[2];
#pragma unroll
    for (int i = 0; i < 2; i++) { int f = tid + i * 256; fr[i] = f >> 2; fc[i] = (f & 3) * 8; }

    float acc[4][4][4];
#pragma unroll
    for (int i = 0; i < 4; i++)
#pragma unroll
        for (int j = 0; j < 4; j++)
#pragma unroll
            for (int r = 0; r < 4; r++) acc[i][j][r] = 0.f;

    auto load_stage = [&](uint32_t st, int k0) {
#pragma unroll
        for (int i = 0; i < 2; i++) {
            uint32_t doff = (uint32_t)(fr[i] * RSTR + fc[i]) * 2;
            size_t ga = (size_t)(bm + fr[i]) * K + k0 + fc[i];
            size_t gb = (size_t)(bn + fr[i]) * K + k0 + fc[i];
            CPA16(st + doff, Ah + ga);
            CPA16(st + PLANE_B + doff, Al + ga);
            CPA16(st + 2 * PLANE_B + doff, Bthi + gb);
            CPA16(st + 3 * PLANE_B + doff, Btlo + gb);
        }
        CPA_COMMIT();
    };

    load_stage(smaddr(dsm), 0);
    CPA_WAIT(0);
    __syncthreads();

    for (int chunk = 0; chunk < NC; chunk++) {
        uint32_t cur = smaddr(dsm) + (chunk & 1) * STAGE_B;
        bool more = (chunk + 1 < NC);
        if (more)
            load_stage(smaddr(dsm) + ((chunk + 1) & 1) * STAGE_B, (chunk + 1) << 5);
        gemm_chunk_pipe(cur, acc, wm, wn, lm, kq, nb, kb2, more);
    }

#pragma unroll
    for (int i = 0; i < 4; i++) {
        int row0 = bm + wm + i * 16 + g;
#pragma unroll
        for (int j = 0; j < 4; j++) {
            int col = bn + wn + j * 8 + t * 2;
            float2 bv = *reinterpret_cast<const float2*>(bias + col);
            float v0 = acc[i][j][0] + bv.x, v1 = acc[i][j][1] + bv.y;
            float v2 = acc[i][j][2] + bv.x, v3 = acc[i][j][3] + bv.y;
            size_t i0 = (size_t)row0 * 512 + col;
            size_t i1 = (size_t)(row0 + 8) * 512 + col;
            *reinterpret_cast<uint32_t*>(Chi + i0) = pack_bf16(v0, v1);
            *reinterpret_cast<uint32_t*>(Clo + i0) =
                pack_bf16(v0 - bf16_hi_f(v0), v1 - bf16_hi_f(v1));
            *reinterpret_cast<uint32_t*>(Chi + i1) = pack_bf16(v2, v3);
            *reinterpret_cast<uint32_t*>(Clo + i1) =
                pack_bf16(v2 - bf16_hi_f(v2), v3 - bf16_hi_f(v3));
        }
    }
}

// ---------------------------------------------------------------------------
// Flash attention: cp.async double-buffered K/V, Q frags in registers.
// Each CTA processes a balanced PAIR of q-tiles: (3,0) or (2,1) -> 10 KV
// tiles each. OUT=0: write f32 Op + planes. OUT=1: Op += relu(result).
// ---------------------------------------------------------------------------
#define QS 72
#define FPL (64 * QS)
#define FSTG_B (4 * FPL * 2)
#define FL_SMEM (2 * FSTG_B)

template<int OUT>
__global__ __launch_bounds__(256, 2) void flash_bf16_kernel(
    const __nv_bfloat16* __restrict__ Qh, const __nv_bfloat16* __restrict__ Ql,
    const __nv_bfloat16* __restrict__ Kh, const __nv_bfloat16* __restrict__ Kl,
    const __nv_bfloat16* __restrict__ Vh, const __nv_bfloat16* __restrict__ Vl,
    float* __restrict__ Op,
    __nv_bfloat16* __restrict__ Ohp, __nv_bfloat16* __restrict__ Olp)
{
    extern __shared__ __align__(16) char fsm[];

    int tid = threadIdx.x;
    int wid = tid >> 5, lane = tid & 31;
    int g = lane >> 2, t = lane & 3;
    int qtx = blockIdx.x;                  // 0 or 1
    int h = blockIdx.y, b = blockIdx.z;
    size_t kvoff = ((size_t)b * SEQ) * EMB + h * DHD;

    int rb = wid * 16;
    int lm = lane & 15, kq = (lane >> 4) << 3;
    int nbk = (lane & 7) + ((lane >> 4) << 3);
    int kb2 = ((lane >> 3) & 1) * 8;
    int kv = (lane & 7) + ((lane >> 3) & 1) * 8;
    int nv = (lane >> 4) << 3;

    int fr[2], fc[2];
#pragma unroll
    for (int i = 0; i < 2; i++) {
        int f = tid + i * 256;
        fr[i] = f >> 3; fc[i] = (f & 7) * 8;
    }

    for (int pass = 0; pass < 2; pass++) {
        int qt = (pass == 0) ? (3 - qtx) : qtx;
        size_t qoff = ((size_t)(b * SEQ + qt * 128)) * EMB + h * DHD;

        // ---- stage Q, hoist fragments ----
        uint32_t qah[4][4], qal[4][4];
        {
            __nv_bfloat16* sQh = reinterpret_cast<__nv_bfloat16*>(fsm);
            __nv_bfloat16* sQl = sQh + 128 * QS;
#pragma unroll
            for (int i = 0; i < 4; i++) {
                int f = tid + i * 256;
                int r = f >> 3, c = (f & 7) * 8;
                *reinterpret_cast<uint4*>(sQh + r * QS + c) =
                    *reinterpret_cast<const uint4*>(Qh + qoff + (size_t)r * EMB + c);
                *reinterpret_cast<uint4*>(sQl + r * QS + c) =
                    *reinterpret_cast<const uint4*>(Ql + qoff + (size_t)r * EMB + c);
            }
            __syncthreads();
            uint32_t uQh = smaddr(sQh), uQl = smaddr(sQl);
#pragma unroll
            for (int kk = 0; kk < 4; kk++) {
                uint32_t qo = (uint32_t)((rb + lm) * QS + kk * 16 + kq) * 2;
                ldm_x4(qah[kk], uQh + qo);
                ldm_x4(qal[kk], uQl + qo);
            }
            __syncthreads();
        }

        int ktmax = qt * 2 + 1;
        int wmaxrow = qt * 128 + rb + 15;
        int row0g = qt * 128 + rb + g, row1g = row0g + 8;

        // KV prologue
        {
            uint32_t st = smaddr(fsm);
#pragma unroll
            for (int i = 0; i < 2; i++) {
                uint32_t doff = (uint32_t)(fr[i] * QS + fc[i]) * 2;
                size_t go = kvoff + (size_t)fr[i] * EMB + fc[i];
                CPA16(st + doff, Kh + go);
                CPA16(st + FPL * 2 + doff, Kl + go);
                CPA16(st + 2 * FPL * 2 + doff, Vh + go);
                CPA16(st + 3 * FPL * 2 + doff, Vl + go);
            }
            CPA_COMMIT();
        }

        float m0 = -INFINITY, m1 = -INFINITY, l0 = 0.f, l1 = 0.f;
        float acc[8][4];
#pragma unroll
        for (int j = 0; j < 8; j++)
#pragma unroll
            for (int r = 0; r < 4; r++) acc[j][r] = 0.f;

        for (int kt = 0; kt <= ktmax; kt++) {
            uint32_t cur = smaddr(fsm) + (kt & 1) * FSTG_B;
            bool more = (kt < ktmax);
            if (more) {
                uint32_t nxt = smaddr(fsm) + ((kt + 1) & 1) * FSTG_B;
                size_t ko = kvoff + (size_t)(kt + 1) * 64 * EMB;
#pragma unroll
                for (int i = 0; i < 2; i++) {
                    uint32_t doff = (uint32_t)(fr[i] * QS + fc[i]) * 2;
                    size_t go = ko + (size_t)fr[i] * EMB + fc[i];
                    CPA16(nxt + doff, Kh + go);
                    CPA16(nxt + FPL * 2 + doff, Kl + go);
                    CPA16(nxt + 2 * FPL * 2 + doff, Vh + go);
                    CPA16(nxt + 3 * FPL * 2 + doff, Vl + go);
                }
                CPA_COMMIT();
                CPA_WAIT(1);
            } else {
                CPA_WAIT(0);
            }
            __syncthreads();

            if (kt * 64 <= wmaxrow) {
                uint32_t uKh = cur, uKl = cur + FPL * 2;
                uint32_t uVh = cur + 2 * FPL * 2, uVl = cur + 3 * FPL * 2;

                float s[8][4];
#pragma unroll
                for (int j = 0; j < 8; j++)
#pragma unroll
                    for (int r = 0; r < 4; r++) s[j][r] = 0.f;
#pragma unroll
                for (int kk = 0; kk < 4; kk++) {
#pragma unroll
                    for (int jp = 0; jp < 4; jp++) {
                        uint32_t koff = (uint32_t)((jp * 16 + nbk) * QS + kk * 16 + kb2) * 2;
                        uint32_t rh[4], rl[4];
                        ldm_x4(rh, uKh + koff);
                        ldm_x4(rl, uKl + koff);
                        uint32_t b0[2] = { rh[0], rh[1] }, b1[2] = { rh[2], rh[3] };
                        uint32_t c0[2] = { rl[0], rl[1] }, c1[2] = { rl[2], rl[3] };
                        mma_bf16(s[2 * jp],     qah[kk], b0);
                        mma_bf16(s[2 * jp + 1], qah[kk], b1);
                        mma_bf16(s[2 * jp],     qal[kk], b0);
                        mma_bf16(s[2 * jp + 1], qal[kk], b1);
                        mma_bf16(s[2 * jp],     qah[kk], c0);
                        mma_bf16(s[2 * jp + 1], qah[kk], c1);
                    }
                }

                int colb = kt * 64 + t * 2;
#pragma unroll
                for (int j = 0; j < 8; j++) {
                    int c0 = colb + j * 8, c1 = c0 + 1;
                    s[j][0] = (c0 > row0g) ? -INFINITY : s[j][0] * ATTN_SCALE;
                    s[j][1] = (c1 > row0g) ? -INFINITY : s[j][1] * ATTN_SCALE;
                    s[j][2] = (c0 > row1g) ? -INFINITY : s[j][2] * ATTN_SCALE;
                    s[j][3] = (c1 > row1g) ? -INFINITY : s[j][3] * ATTN_SCALE;
                }

                float tm0 = -INFINITY, tm1 = -INFINITY;
#pragma unroll
                for (int j = 0; j < 8; j++) {
                    tm0 = fmaxf(tm0, fmaxf(s[j][0], s[j][1]));
                    tm1 = fmaxf(tm1, fmaxf(s[j][2], s[j][3]));
                }
                tm0 = fmaxf(tm0, __shfl_xor_sync(0xFFFFFFFFu, tm0, 1));
                tm0 = fmaxf(tm0, __shfl_xor_sync(0xFFFFFFFFu, tm0, 2));
                tm1 = fmaxf(tm1, __shfl_xor_sync(0xFFFFFFFFu, tm1, 1));
                tm1 = fmaxf(tm1, __shfl_xor_sync(0xFFFFFFFFu, tm1, 2));
                float m0n = fmaxf(m0, tm0), m1n = fmaxf(m1, tm1);
                float ms0 = fmaxf(m0n, -1e30f), ms1 = fmaxf(m1n, -1e30f);
                float alpha0 = __expf(m0 - ms0), alpha1 = __expf(m1 - ms1);
                m0 = m0n; m1 = m1n;
#pragma unroll
                for (int j = 0; j < 8; j++) {
                    acc[j][0] *= alpha0; acc[j][1] *= alpha0;
                    acc[j][2] *= alpha1; acc[j][3] *= alpha1;
                }

                float ps0 = 0.f, ps1 = 0.f;
#pragma unroll
                for (int kk = 0; kk < 4; kk++) {
                    int j0 = 2 * kk, j1 = 2 * kk + 1;
                    float p00 = __expf(s[j0][0] - ms0), p01 = __expf(s[j0][1] - ms0);
                    float p02 = __expf(s[j0][2] - ms1), p03 = __expf(s[j0][3] - ms1);
                    float p10 = __expf(s[j1][0] - ms0), p11 = __expf(s[j1][1] - ms0);
                    float p12 = __expf(s[j1][2] - ms1), p13 = __expf(s[j1][3] - ms1);
                    ps0 += p00 + p01 + p10 + p11;
                    ps1 += p02 + p03 + p12 + p13;
                    uint32_t pah[4], pal[4];
                    pah[0] = pack_bf16(p00, p01);
                    pah[1] = pack_bf16(p02, p03);
                    pah[2] = pack_bf16(p10, p11);
                    pah[3] = pack_bf16(p12, p13);
                    pal[0] = pack_bf16(p00 - bf16_hi_f(p00), p01 - bf16_hi_f(p01));
                    pal[1] = pack_bf16(p02 - bf16_hi_f(p02), p03 - bf16_hi_f(p03));
                    pal[2] = pack_bf16(p10 - bf16_hi_f(p10), p11 - bf16_hi_f(p11));
                    pal[3] = pack_bf16(p12 - bf16_hi_f(p12), p13 - bf16_hi_f(p13));
#pragma unroll
                    for (int jdp = 0; jdp < 4; jdp++) {
                        uint32_t voff = (uint32_t)((kk * 16 + kv) * QS + jdp * 16 + nv) * 2;
                        uint32_t rh[4], rl[4];
                        ldm_x4t(rh, uVh + voff);
                        ldm_x4t(rl, uVl + voff);
                        uint32_t b0[2] = { rh[0], rh[1] }, b1[2] = { rh[2], rh[3] };
                        uint32_t c0[2] = { rl[0], rl[1] }, c1[2] = { rl[2], rl[3] };
                        mma_bf16(acc[2 * jdp],     pah, b0);
                        mma_bf16(acc[2 * jdp + 1], pah, b1);
                        mma_bf16(acc[2 * jdp],     pal, b0);
                        mma_bf16(acc[2 * jdp + 1], pal, b1);
                        mma_bf16(acc[2 * jdp],     pah, c0);
                        mma_bf16(acc[2 * jdp + 1], pah, c1);
                    }
                }
                ps0 += __shfl_xor_sync(0xFFFFFFFFu, ps0, 1);
                ps0 += __shfl_xor_sync(0xFFFFFFFFu, ps0, 2);
                ps1 += __shfl_xor_sync(0xFFFFFFFFu, ps1, 1);
                ps1 += __shfl_xor_sync(0xFFFFFFFFu, ps1, 2);
                l0 = l0 * alpha0 + ps0;
                l1 = l1 * alpha1 + ps1;
            }
            __syncthreads();
        }

        float inv0 = 1.f / l0, inv1 = 1.f / l1;
#pragma unroll
        for (int jd = 0; jd < 8; jd++) {
            int c = jd * 8 + t * 2;
            size_t i0 = qoff + (size_t)(rb + g) * EMB + c;
            size_t i1 = qoff + (size_t)(rb + g + 8) * EMB + c;
            float o00 = acc[jd][0] * inv0, o01 = acc[jd][1] * inv0;
            float o10 = acc[jd][2] * inv1, o11 = acc[jd][3] * inv1;
            if (OUT == 0) {
                *reinterpret_cast<float2*>(Op + i0) = make_float2(o00, o01);
                *reinterpret_cast<float2*>(Op + i1) = make_float2(o10, o11);
                *reinterpret_cast<uint32_t*>(Ohp + i0) = pack_bf16(o00, o01);
                *reinterpret_cast<uint32_t*>(Olp + i0) =
                    pack_bf16(o00 - bf16_hi_f(o00), o01 - bf16_hi_f(o01));
                *reinterpret_cast<uint32_t*>(Ohp + i1) = pack_bf16(o10, o11);
                *reinterpret_cast<uint32_t*>(Olp + i1) =
                    pack_bf16(o10 - bf16_hi_f(o10), o11 - bf16_hi_f(o11));
            } else {
                float2 e0 = *reinterpret_cast<float2*>(Op + i0);
                float2 e1 = *reinterpret_cast<float2*>(Op + i1);
                *reinterpret_cast<float2*>(Op + i0) =
                    make_float2(e0.x + fmaxf(o00, 0.f), e0.y + fmaxf(o01, 0.f));
                *reinterpret_cast<float2*>(Op + i1) =
                    make_float2(e1.x + fmaxf(o10, 0.f), e1.y + fmaxf(o11, 0.f));
            }
        }
    }
}

// ---------------------------------------------------------------------------
__global__ __launch_bounds__(256) void out_proj_kernel(
    const float* __restrict__ out, const float* __restrict__ Wout,
    const float* __restrict__ bout, float* __restrict__ y)
{
    int g = blockIdx.x * 8 + (threadIdx.x >> 5);
    int lane = threadIdx.x & 31;
    const float4* o4 = reinterpret_cast<const float4*>(out + (size_t)g * EMB);
    const float4* w4 = reinterpret_cast<const float4*>(Wout);
    float s = 0.f;
#pragma unroll
    for (int i = 0; i < 4; i++) {
        float4 a = o4[lane + 32 * i];
        float4 b = w4[lane + 32 * i];
        s += a.x * b.x + a.y * b.y + a.z * b.z + a.w * b.w;
    }
#pragma unroll
    for (int off = 16; off > 0; off >>= 1)
        s += __shfl_xor_sync(0xFFFFFFFFu, s, off);
    if (lane == 0) y[g] = s + bout[0];
}

// ---------------------------------------------------------------------------
extern "C" void kernel_launch(void* const* d_in, const int* in_sizes, int n_in,
                              void* d_out, int out_size)
{
    const int*   item_inputs  = (const int*)d_in[0];
    const int*   skill_inputs = (const int*)d_in[1];
    const int*   label_inputs = (const int*)d_in[2];
    const int*   item_ids     = (const int*)d_in[3];
    const int*   skill_ids    = (const int*)d_in[4];
    const float* item_emb     = (const float*)d_in[5];
    const float* skill_emb    = (const float*)d_in[6];
    const float* W_in         = (const float*)d_in[7];
    const float* b_in         = (const float*)d_in[8];
    const float* Wq           = (const float*)d_in[9];
    const float* bq           = (const float*)d_in[10];
    const float* Wk           = (const float*)d_in[11];
    const float* bk           = (const float*)d_in[12];
    const float* Wv           = (const float*)d_in[13];
    const float* bv           = (const float*)d_in[14];
    const float* W_out        = (const float*)d_in[22];
    const float* b_out        = (const float*)d_in[23];
    float* y = (float*)d_out;

    float* outb;
    __nv_bfloat16 *w, *hh, *hl, *qrh, *qrl, *xh, *xl, *oh, *ol;
    __nv_bfloat16 *q1h, *q1l, *q2h, *q2l, *kh, *kl, *vh, *vl;
    int *perm, *n1;
    cudaGetSymbolAddress((void**)&outb, g_outb);
    cudaGetSymbolAddress((void**)&w,    g_W);
    cudaGetSymbolAddress((void**)&hh,   g_Hh);
    cudaGetSymbolAddress((void**)&hl,   g_Hl);
    cudaGetSymbolAddress((void**)&qrh,  g_QRh);
    cudaGetSymbolAddress((void**)&qrl,  g_QRl);
    cudaGetSymbolAddress((void**)&xh,   g_Xh);
    cudaGetSymbolAddress((void**)&xl,   g_Xl);
    cudaGetSymbolAddress((void**)&oh,   g_Oh);
    cudaGetSymbolAddress((void**)&ol,   g_Ol);
    cudaGetSymbolAddress((void**)&q1h,  g_Q1h);
    cudaGetSymbolAddress((void**)&q1l,  g_Q1l);
    cudaGetSymbolAddress((void**)&q2h,  g_Q2h);
    cudaGetSymbolAddress((void**)&q2l,  g_Q2l);
    cudaGetSymbolAddress((void**)&kh,   g_Kh);
    cudaGetSymbolAddress((void**)&kl,   g_Kl);
    cudaGetSymbolAddress((void**)&vh,   g_Vh);
    cudaGetSymbolAddress((void**)&vl,   g_Vl);
    cudaGetSymbolAddress((void**)&perm, g_perm);
    cudaGetSymbolAddress((void**)&n1,   g_n1);

    cudaFuncSetAttribute(flash_bf16_kernel<0>,
                         cudaFuncAttributeMaxDynamicSharedMemorySize, FL_SMEM);
    cudaFuncSetAttribute(flash_bf16_kernel<1>,
                         cudaFuncAttributeMaxDynamicSharedMemorySize, FL_SMEM);
    cudaFuncSetAttribute(gemm_mlp_kernel,
                         cudaFuncAttributeMaxDynamicSharedMemorySize, GEMM_SMEM);
    cudaFuncSetAttribute(gemm_qkv_kernel,
                         cudaFuncAttributeMaxDynamicSharedMemorySize, GEMM_SMEM);

    __nv_bfloat16* win_hi = w;
    __nv_bfloat16* win_lo = w + 512 * 1024;
    __nv_bfloat16* qkv_hi[2][3];
    __nv_bfloat16* qkv_lo[2][3];
    {
        __nv_bfloat16* p = w + 2 * 512 * 1024;
        for (int l = 0; l < 2; l++)
            for (int m = 0; m < 3; m++) {
                qkv_hi[l][m] = p; p += 512 * 512;
                qkv_lo[l][m] = p; p += 512 * 512;
            }
    }

    partition_kernel<<<1, 512>>>(label_inputs, perm, n1);
    gather_kernel<<<TOT, 128>>>(item_inputs, skill_inputs,
                                item_ids, skill_ids, item_emb, skill_emb,
                                hh, hl, qrh, qrl);
    transpose_cvt_kernel<<<dim3(16, 32), 256>>>(W_in, win_hi, win_lo, 1024, 512);
    {
        TrArgs ta;
        const float* srcs[3] = { Wq, Wk, Wv };
        for (int l = 0; l < 2; l++)
            for (int m = 0; m < 3; m++) {
                ta.src[l * 3 + m] = srcs[m] + (size_t)l * 512 * 512;
                ta.dhi[l * 3 + m] = qkv_hi[l][m];
                ta.dlo[l * 3 + m] = qkv_lo[l][m];
            }
        transpose_qkv_kernel<<<dim3(16, 16, 6), 256>>>(ta);
    }
    gemm_mlp_kernel<<<dim3(4, 128), 256, GEMM_SMEM>>>(
        hh, hl, win_hi, win_lo, b_in, xh, xl, perm, n1);

    // fused Q1,K1,V1,Q2
    {
        QKVArgs qa;
        qa.Ah[0] = qrh; qa.Al[0] = qrl;
        qa.Ah[1] = xh;  qa.Al[1] = xl;
        qa.Ah[2] = xh;  qa.Al[2] = xl;
        qa.Ah[3] = qrh; qa.Al[3] = qrl;
        qa.Bh[0] = qkv_hi[0][0]; qa.Bl[0] = qkv_lo[0][0];
        qa.Bh[1] = qkv_hi[0][1]; qa.Bl[1] = qkv_lo[0][1];
        qa.Bh[2] = qkv_hi[0][2]; qa.Bl[2] = qkv_lo[0][2];
        qa.Bh[3] = qkv_hi[1][0]; qa.Bl[3] = qkv_lo[1][0];
        qa.bias[0] = bq; qa.bias[1] = bk; qa.bias[2] = bv; qa.bias[3] = bq + EMB;
        qa.Ch[0] = q1h; qa.Cl[0] = q1l;
        qa.Ch[1] = kh;  qa.Cl[1] = kl;
        qa.Ch[2] = vh;  qa.Cl[2] = vl;
        qa.Ch[3] = q2h; qa.Cl[3] = q2l;
        gemm_qkv_kernel<<<dim3(4, 128, 4), 256, GEMM_SMEM>>>(qa);
    }
    flash_bf16_kernel<0><<<dim3(2, NH, Bsz), 256, FL_SMEM>>>(
        q1h, q1l, kh, kl, vh, vl, outb, oh, ol);
    // fused K2,V2
    {
        QKVArgs qa;
        qa.Ah[0] = oh; qa.Al[0] = ol;
        qa.Ah[1] = oh; qa.Al[1] = ol;
        qa.Ah[2] = oh; qa.Al[2] = ol;
        qa.Ah[3] = oh; qa.Al[3] = ol;
        qa.Bh[0] = qkv_hi[1][1]; qa.Bl[0] = qkv_lo[1][1];
        qa.Bh[1] = qkv_hi[1][2]; qa.Bl[1] = qkv_lo[1][2];
        qa.Bh[2] = qkv_hi[1][1]; qa.Bl[2] = qkv_lo[1][1];
        qa.Bh[3] = qkv_hi[1][2]; qa.Bl[3] = qkv_lo[1][2];
        qa.bias[0] = bk + EMB; qa.bias[1] = bv + EMB;
        qa.bias[2] = bk + EMB; qa.bias[3] = bv + EMB;
        qa.Ch[0] = kh; qa.Cl[0] = kl;
        qa.Ch[1] = vh; qa.Cl[1] = vl;
        qa.Ch[2] = kh; qa.Cl[2] = kl;
        qa.Ch[3] = vh; qa.Cl[3] = vl;
        gemm_qkv_kernel<<<dim3(4, 128, 2), 256, GEMM_SMEM>>>(qa);
    }
    flash_bf16_kernel<1><<<dim3(2, NH, Bsz), 256, FL_SMEM>>>(
        q2h, q2l, kh, kl, vh, vl, outb, nullptr, nullptr);

    out_proj_kernel<<<TOT / 8, 256>>>(outb, W_out, b_out, y);
}